// round 1
// baseline (speedup 1.0000x reference)
#include <cuda_runtime.h>
#include <math.h>

#define WIN   512
#define BATCH 8
#define CIN   38
#define COUT  38
#define DM    512
#define NH    8
#define EHD   64
#define NL    3
#define ROWS  (BATCH*WIN)   /* 4096 */

// output packing offsets (floats)
#define OUT_ELEMS    (BATCH*WIN*COUT)            /* 155648 */
#define LAYER_ELEMS  ((size_t)BATCH*NH*WIN*WIN)  /* 16777216 */
#define SERIES_OFF   ((size_t)OUT_ELEMS)
#define PRIOR_OFF    (SERIES_OFF + 3*LAYER_ELEMS)
#define SIGMA_OFF    (PRIOR_OFF  + 3*LAYER_ELEMS)

// ---------------- scratch (device globals; no allocations allowed) --------
__device__ float g_h [ROWS*DM];
__device__ float g_q [ROWS*DM];
__device__ float g_k [ROWS*DM];
__device__ float g_v [ROWS*DM];
__device__ float g_t1[ROWS*DM];
__device__ float g_t2[ROWS*DM];
__device__ float g_sig[ROWS*NH];

// ---------------- embedding: wrap-pad conv1d(k=3) + sinusoidal PE ---------
__global__ void embed_kernel(const float* __restrict__ x,
                             const float* __restrict__ ck,
                             float* __restrict__ h) {
    int bt = blockIdx.x;              // b*WIN + t
    int b = bt >> 9, t = bt & (WIN-1);
    __shared__ float xs[3*CIN];
    int tid = threadIdx.x;
    if (tid < 3*CIN) {
        int w = tid / CIN, c = tid % CIN;
        int src = (t + w - 1 + WIN) & (WIN-1);   // wrap pad
        xs[tid] = x[((size_t)b*WIN + src)*CIN + c];
    }
    __syncthreads();
    int d = tid;                      // blockDim = 512
    int i2 = (d >> 1) * 2;
    float ang = (float)t * __expf(-(float)i2 * (9.210340371976184f/512.0f));
    float acc = (d & 1) ? cosf(ang) : sinf(ang);
#pragma unroll 1
    for (int wc = 0; wc < 3*CIN; wc++)
        acc += xs[wc] * ck[(size_t)wc*DM + d];
    h[(size_t)bt*DM + d] = acc;
}

// ---------------- generic 128x128 fp32 SGEMM: C = A@B + bias (opt gelu) ---
template<bool GELU>
__global__ __launch_bounds__(256)
void sgemm_kernel(const float* __restrict__ A, const float* __restrict__ B,
                  const float* __restrict__ bias, float* __restrict__ C,
                  int M, int N, int K) {
    const int BM=128, BN=128, BK=8, TM=8, TN=8;
    __shared__ float As[BK*BM];
    __shared__ float Bs[BK*BN];
    int tid  = threadIdx.x;
    int cRow = blockIdx.x, cCol = blockIdx.y;
    A += (size_t)cRow*BM*K;
    B += cCol*BN;
    C += (size_t)cRow*BM*N + cCol*BN;
    int rowA = tid >> 1,  colA = (tid & 1) * 4;
    int rowB = tid >> 5,  colB = (tid & 31) * 4;
    int tr = tid >> 4,    tc = tid & 15;
    float acc[TM][TN] = {};
    for (int bk = 0; bk < K; bk += BK) {
        float4 a4 = *reinterpret_cast<const float4*>(&A[(size_t)rowA*K + colA]);
        As[(colA+0)*BM + rowA] = a4.x;
        As[(colA+1)*BM + rowA] = a4.y;
        As[(colA+2)*BM + rowA] = a4.z;
        As[(colA+3)*BM + rowA] = a4.w;
        *reinterpret_cast<float4*>(&Bs[rowB*BN + colB]) =
            *reinterpret_cast<const float4*>(&B[(size_t)rowB*N + colB]);
        __syncthreads();
        A += BK; B += (size_t)BK*N;
        float rm[TM], rn[TN];
#pragma unroll
        for (int k = 0; k < BK; k++) {
#pragma unroll
            for (int i = 0; i < TM; i++) rm[i] = As[k*BM + tr*TM + i];
#pragma unroll
            for (int j = 0; j < TN; j++) rn[j] = Bs[k*BN + tc*TN + j];
#pragma unroll
            for (int i = 0; i < TM; i++)
#pragma unroll
                for (int j = 0; j < TN; j++) acc[i][j] += rm[i]*rn[j];
        }
        __syncthreads();
    }
#pragma unroll
    for (int i = 0; i < TM; i++) {
        int r = tr*TM + i;
#pragma unroll
        for (int j = 0; j < TN; j++) {
            int c = tc*TN + j;
            float v = acc[i][j] + bias[cCol*BN + c];
            if (GELU) v = 0.5f*v*(1.0f + erff(v*0.70710678118654752f));
            C[(size_t)r*N + c] = v;
        }
    }
}

// ---------------- sigma projection: [4096,512]x[512,8] -------------------
__global__ void sig_kernel(const float* __restrict__ h, const float* __restrict__ Ws,
                           const float* __restrict__ bs, float* __restrict__ sig) {
    int row = blockIdx.x;
    int warp = threadIdx.x >> 5, lane = threadIdx.x & 31;
    const float* hr = h + (size_t)row*DM;
    float sum = 0.f;
    for (int k2 = lane; k2 < DM; k2 += 32) sum += hr[k2] * Ws[k2*NH + warp];
#pragma unroll
    for (int o = 16; o > 0; o >>= 1) sum += __shfl_xor_sync(0xffffffff, sum, o);
    if (lane == 0) sig[row*NH + warp] = sum + bs[warp];
}

// ---------------- scores: per (b,h) QK^T (NT gemm, K=64) ------------------
__global__ __launch_bounds__(256)
void scores_kernel(const float* __restrict__ q, const float* __restrict__ k,
                   float* __restrict__ out) {
    __shared__ float Qs[64*65];
    __shared__ float Ks[64*65];
    int tid = threadIdx.x;
    int bh = blockIdx.z; int b = bh >> 3, hh = bh & 7;
    int l0 = blockIdx.x * 64, s0 = blockIdx.y * 64;
    const float* qb = q + ((size_t)b*WIN + l0)*DM + hh*EHD;
    const float* kb = k + ((size_t)b*WIN + s0)*DM + hh*EHD;
    int rbase = tid >> 4, c4 = (tid & 15) * 4;
#pragma unroll
    for (int m = 0; m < 4; m++) {
        int r = rbase + m*16;
        float4 qv = *reinterpret_cast<const float4*>(&qb[(size_t)r*DM + c4]);
        Qs[r*65+c4+0]=qv.x; Qs[r*65+c4+1]=qv.y; Qs[r*65+c4+2]=qv.z; Qs[r*65+c4+3]=qv.w;
        float4 kv = *reinterpret_cast<const float4*>(&kb[(size_t)r*DM + c4]);
        Ks[r*65+c4+0]=kv.x; Ks[r*65+c4+1]=kv.y; Ks[r*65+c4+2]=kv.z; Ks[r*65+c4+3]=kv.w;
    }
    __syncthreads();
    int tr = tid >> 4, tc = tid & 15;
    float acc[4][4] = {};
#pragma unroll
    for (int e = 0; e < 64; e++) {
        float rq[4], rk[4];
#pragma unroll
        for (int i = 0; i < 4; i++) rq[i] = Qs[(tr*4+i)*65 + e];
#pragma unroll
        for (int j = 0; j < 4; j++) rk[j] = Ks[(tc*4+j)*65 + e];
#pragma unroll
        for (int i = 0; i < 4; i++)
#pragma unroll
            for (int j = 0; j < 4; j++) acc[i][j] += rq[i]*rk[j];
    }
    float* ob = out + ((size_t)bh*WIN + l0)*WIN + s0;
#pragma unroll
    for (int i = 0; i < 4; i++)
#pragma unroll
        for (int j = 0; j < 4; j++)
            ob[(size_t)(tr*4+i)*WIN + tc*4+j] = acc[i][j];
}

// ---------------- in-place row softmax (x *= 1/8 first) -------------------
__global__ void softmax_kernel(float* __restrict__ data) {
    size_t row = blockIdx.x;
    float* p = data + row*WIN;
    int tid = threadIdx.x;
    float v0 = p[tid]       * 0.125f;
    float v1 = p[tid + 256] * 0.125f;
    __shared__ float red[256];
    red[tid] = fmaxf(v0, v1);
    __syncthreads();
    for (int s = 128; s > 0; s >>= 1) { if (tid < s) red[tid] = fmaxf(red[tid], red[tid+s]); __syncthreads(); }
    float m = red[0];
    __syncthreads();
    float e0 = __expf(v0 - m), e1 = __expf(v1 - m);
    red[tid] = e0 + e1;
    __syncthreads();
    for (int s = 128; s > 0; s >>= 1) { if (tid < s) red[tid] += red[tid+s]; __syncthreads(); }
    float inv = 1.0f / red[0];
    p[tid]       = e0 * inv;
    p[tid + 256] = e1 * inv;
}

// ---------------- prior + sigma writer ------------------------------------
__global__ void prior_kernel(const float* __restrict__ sig,
                             float* __restrict__ prior, float* __restrict__ sigma) {
    int idx = blockIdx.x;                // bh*WIN + l
    int l = idx & (WIN-1);
    int bh = idx >> 9;
    int b = bh >> 3, hh = bh & 7;
    float sv = sig[((size_t)b*WIN + l)*NH + hh];
    float sgm = 1.0f/(1.0f + __expf(-5.0f*sv)) + 1e-5f;
    float sg  = __expf(sgm * 1.0986122886681098f) - 1.0f;   // 3^sgm - 1
    float inv = 0.3989422804014327f / sg;                   // 1/sqrt(2pi)/sg
    float cc  = -1.0f/(2.0f*sg*sg);
    size_t base = ((size_t)bh*WIN + l)*WIN;
    int tid = threadIdx.x;
    for (int s = tid; s < WIN; s += 256) {
        float d = (float)(l - s);
        prior[base + s] = inv * __expf(cc*d*d);
        sigma[base + s] = sg;
    }
}

// ---------------- attn out: per (b,h) S[512,512] @ V[512,64] --------------
__global__ __launch_bounds__(256)
void attnv_kernel(const float* __restrict__ series, const float* __restrict__ v,
                  float* __restrict__ out) {
    __shared__ float Ss[64*17];
    __shared__ float Vs[16*64];
    int tid = threadIdx.x;
    int bh = blockIdx.y; int b = bh >> 3, hh = bh & 7;
    int l0 = blockIdx.x * 64;
    const float* sb = series + ((size_t)bh*WIN + l0)*WIN;
    const float* vb = v + (size_t)b*WIN*DM + hh*EHD;
    int tr = tid >> 4, tc = tid & 15;
    int rA = tid >> 2, cA = (tid & 3) * 4;
    int rB = tid >> 4, cB = (tid & 15) * 4;
    float acc[4][4] = {};
    for (int kt = 0; kt < WIN; kt += 16) {
        float4 s4 = *reinterpret_cast<const float4*>(&sb[(size_t)rA*WIN + kt + cA]);
        Ss[rA*17+cA+0]=s4.x; Ss[rA*17+cA+1]=s4.y; Ss[rA*17+cA+2]=s4.z; Ss[rA*17+cA+3]=s4.w;
        *reinterpret_cast<float4*>(&Vs[rB*64 + cB]) =
            *reinterpret_cast<const float4*>(&vb[(size_t)(kt+rB)*DM + cB]);
        __syncthreads();
#pragma unroll
        for (int k = 0; k < 16; k++) {
            float rs[4], rv[4];
#pragma unroll
            for (int i = 0; i < 4; i++) rs[i] = Ss[(tr*4+i)*17 + k];
#pragma unroll
            for (int j = 0; j < 4; j++) rv[j] = Vs[k*64 + tc*4+j];
#pragma unroll
            for (int i = 0; i < 4; i++)
#pragma unroll
                for (int j = 0; j < 4; j++) acc[i][j] += rs[i]*rv[j];
        }
        __syncthreads();
    }
    float* ob = out + ((size_t)(b*WIN + l0))*DM + hh*EHD;
#pragma unroll
    for (int i = 0; i < 4; i++)
#pragma unroll
        for (int j = 0; j < 4; j++)
            ob[(size_t)(tr*4+i)*DM + tc*4+j] = acc[i][j];
}

// ---------------- LayerNorm: out = LN(x (+res)) * g + b -------------------
__global__ void ln_kernel(const float* __restrict__ x, const float* __restrict__ res,
                          const float* __restrict__ g, const float* __restrict__ bb,
                          float* __restrict__ out) {
    size_t row = blockIdx.x;
    int tid = threadIdx.x;
    const float* xr = x + row*DM;
    float v0 = xr[tid], v1 = xr[tid+256];
    if (res) { const float* rr = res + row*DM; v0 += rr[tid]; v1 += rr[tid+256]; }
    __shared__ float red[256];
    red[tid] = v0 + v1;
    __syncthreads();
    for (int s = 128; s > 0; s >>= 1) { if (tid < s) red[tid] += red[tid+s]; __syncthreads(); }
    float mu = red[0] * (1.0f/DM);
    __syncthreads();
    float d0 = v0 - mu, d1 = v1 - mu;
    red[tid] = d0*d0 + d1*d1;
    __syncthreads();
    for (int s = 128; s > 0; s >>= 1) { if (tid < s) red[tid] += red[tid+s]; __syncthreads(); }
    float r = rsqrtf(red[0]*(1.0f/DM) + 1e-3f);
    out[row*DM + tid]       = d0*r*g[tid]       + bb[tid];
    out[row*DM + tid + 256] = d1*r*g[tid+256]   + bb[tid+256];
}

// ---------------- final projection [4096,512]x[512,38] --------------------
__global__ void proj_kernel(const float* __restrict__ hf, const float* __restrict__ Wp,
                            const float* __restrict__ bp, float* __restrict__ out) {
    int row = blockIdx.x;
    int warp = threadIdx.x >> 5, lane = threadIdx.x & 31;
    const float* hr = hf + (size_t)row*DM;
    for (int c = warp; c < COUT; c += 8) {
        float sum = 0.f;
        for (int k2 = lane; k2 < DM; k2 += 32) sum += hr[k2] * Wp[(size_t)k2*COUT + c];
#pragma unroll
        for (int o = 16; o > 0; o >>= 1) sum += __shfl_xor_sync(0xffffffff, sum, o);
        if (lane == 0) out[(size_t)row*COUT + c] = sum + bp[c];
    }
}

// ---------------- host orchestration --------------------------------------
extern "C" void kernel_launch(void* const* d_in, const int* in_sizes, int n_in,
                              void* d_out, int out_size) {
    const float* x    = (const float*)d_in[0];
    const float* ck   = (const float*)d_in[1];
    const float* Wq   = (const float*)d_in[2];
    const float* bq   = (const float*)d_in[3];
    const float* Wk   = (const float*)d_in[4];
    const float* bk   = (const float*)d_in[5];
    const float* Wv   = (const float*)d_in[6];
    const float* bv   = (const float*)d_in[7];
    const float* Ws   = (const float*)d_in[8];
    const float* bs   = (const float*)d_in[9];
    const float* Wo   = (const float*)d_in[10];
    const float* bo   = (const float*)d_in[11];
    const float* W1   = (const float*)d_in[12];
    const float* b1   = (const float*)d_in[13];
    const float* W2   = (const float*)d_in[14];
    const float* b2   = (const float*)d_in[15];
    const float* ln1g = (const float*)d_in[16];
    const float* ln1b = (const float*)d_in[17];
    const float* ln2g = (const float*)d_in[18];
    const float* ln2b = (const float*)d_in[19];
    const float* lnfg = (const float*)d_in[20];
    const float* lnfb = (const float*)d_in[21];
    const float* Wp   = (const float*)d_in[22];
    const float* bp   = (const float*)d_in[23];
    float* out = (float*)d_out;

    float *h, *q, *k, *v, *t1, *t2, *sg;
    cudaGetSymbolAddress((void**)&h,  g_h);
    cudaGetSymbolAddress((void**)&q,  g_q);
    cudaGetSymbolAddress((void**)&k,  g_k);
    cudaGetSymbolAddress((void**)&v,  g_v);
    cudaGetSymbolAddress((void**)&t1, g_t1);
    cudaGetSymbolAddress((void**)&t2, g_t2);
    cudaGetSymbolAddress((void**)&sg, g_sig);

    embed_kernel<<<ROWS, DM>>>(x, ck, h);

    dim3 gg(ROWS/128, DM/128);   // (32, 4)
    for (int i = 0; i < NL; i++) {
        const float* wq = Wq + (size_t)i*DM*DM;
        const float* wk = Wk + (size_t)i*DM*DM;
        const float* wv = Wv + (size_t)i*DM*DM;
        const float* wo = Wo + (size_t)i*DM*DM;
        const float* w1 = W1 + (size_t)i*DM*DM;
        const float* w2 = W2 + (size_t)i*DM*DM;

        sgemm_kernel<false><<<gg, 256>>>(h, wq, bq + i*DM, q, ROWS, DM, DM);
        sgemm_kernel<false><<<gg, 256>>>(h, wk, bk + i*DM, k, ROWS, DM, DM);
        sgemm_kernel<false><<<gg, 256>>>(h, wv, bv + i*DM, v, ROWS, DM, DM);
        sig_kernel<<<ROWS, 256>>>(h, Ws + (size_t)i*DM*NH, bs + i*NH, sg);

        float* ser = out + SERIES_OFF + (size_t)i*LAYER_ELEMS;
        scores_kernel<<<dim3(8, 8, BATCH*NH), 256>>>(q, k, ser);
        softmax_kernel<<<BATCH*NH*WIN, 256>>>(ser);
        prior_kernel<<<BATCH*NH*WIN, 256>>>(sg,
                out + PRIOR_OFF + (size_t)i*LAYER_ELEMS,
                out + SIGMA_OFF + (size_t)i*LAYER_ELEMS);

        attnv_kernel<<<dim3(8, BATCH*NH), 256>>>(ser, v, t1);
        sgemm_kernel<false><<<gg, 256>>>(t1, wo, bo + i*DM, t2, ROWS, DM, DM);
        ln_kernel<<<ROWS, 256>>>(h, t2, ln1g + i*DM, ln1b + i*DM, h);

        sgemm_kernel<true ><<<gg, 256>>>(h,  w1, b1 + i*DM, t1, ROWS, DM, DM);
        sgemm_kernel<false><<<gg, 256>>>(t1, w2, b2 + i*DM, t2, ROWS, DM, DM);
        ln_kernel<<<ROWS, 256>>>(h, t2, ln2g + i*DM, ln2b + i*DM, h);
    }

    ln_kernel<<<ROWS, 256>>>(h, nullptr, lnfg, lnfb, t1);
    proj_kernel<<<ROWS, 256>>>(t1, Wp, bp, out);
}

// round 2
// speedup vs baseline: 1.3864x; 1.3864x over previous
#include <cuda_runtime.h>
#include <math.h>

#define WIN   512
#define BATCH 8
#define CIN   38
#define COUT  38
#define DM    512
#define NH    8
#define EHD   64
#define NL    3
#define ROWS  (BATCH*WIN)   /* 4096 */

// output packing offsets (floats)
#define OUT_ELEMS    (BATCH*WIN*COUT)            /* 155648 */
#define LAYER_ELEMS  ((size_t)BATCH*NH*WIN*WIN)  /* 16777216 */
#define SERIES_OFF   ((size_t)OUT_ELEMS)
#define PRIOR_OFF    (SERIES_OFF + 3*LAYER_ELEMS)
#define SIGMA_OFF    (PRIOR_OFF  + 3*LAYER_ELEMS)

// ---------------- scratch (device globals; no allocations allowed) --------
__device__ float g_h [ROWS*DM];
__device__ float g_q [ROWS*DM];
__device__ float g_k [ROWS*DM];
__device__ float g_v [ROWS*DM];
__device__ float g_t1[ROWS*DM];
__device__ float g_t2[ROWS*DM];
__device__ float g_sig[ROWS*NH];

// ---------------- embedding: wrap-pad conv1d(k=3) + sinusoidal PE ---------
__global__ void embed_kernel(const float* __restrict__ x,
                             const float* __restrict__ ck,
                             float* __restrict__ h) {
    int bt = blockIdx.x;              // b*WIN + t
    int b = bt >> 9, t = bt & (WIN-1);
    __shared__ float xs[3*CIN];
    int tid = threadIdx.x;
    if (tid < 3*CIN) {
        int w = tid / CIN, c = tid % CIN;
        int src = (t + w - 1 + WIN) & (WIN-1);   // wrap pad
        xs[tid] = x[((size_t)b*WIN + src)*CIN + c];
    }
    __syncthreads();
    int d = tid;                      // blockDim = 512
    int i2 = (d >> 1) * 2;
    float ang = (float)t * __expf(-(float)i2 * (9.210340371976184f/512.0f));
    float acc = (d & 1) ? cosf(ang) : sinf(ang);
#pragma unroll 1
    for (int wc = 0; wc < 3*CIN; wc++)
        acc += xs[wc] * ck[(size_t)wc*DM + d];
    h[(size_t)bt*DM + d] = acc;
}

// ---------------- 128x128x16 double-buffered SGEMM, z-batched jobs --------
struct GemmJob { const float* W; const float* b; float* C; };

template<bool GELU>
__global__ __launch_bounds__(256)
void sgemm128(const float* __restrict__ A, GemmJob j0, GemmJob j1, GemmJob j2) {
    __shared__ float As[2][16*128];
    __shared__ float Bs[2][16*128];
    GemmJob jb = (blockIdx.z == 0) ? j0 : ((blockIdx.z == 1) ? j1 : j2);
    int tid = threadIdx.x;
    const float* Ab = A + (size_t)blockIdx.x * 128 * 512;
    const float* Bb = jb.W + blockIdx.y * 128;
    int arow = tid >> 2,  acol = (tid & 3) * 4;
    int brow = tid >> 5,  bcol = (tid & 31) * 4;
    float4 a0, a1, b0, b1;
    a0 = *(const float4*)(Ab + (size_t)arow*512 + acol);
    a1 = *(const float4*)(Ab + (size_t)(arow+64)*512 + acol);
    b0 = *(const float4*)(Bb + (size_t)brow*512 + bcol);
    b1 = *(const float4*)(Bb + (size_t)(brow+8)*512 + bcol);
    As[0][(acol+0)*128+arow]=a0.x; As[0][(acol+1)*128+arow]=a0.y;
    As[0][(acol+2)*128+arow]=a0.z; As[0][(acol+3)*128+arow]=a0.w;
    As[0][(acol+0)*128+arow+64]=a1.x; As[0][(acol+1)*128+arow+64]=a1.y;
    As[0][(acol+2)*128+arow+64]=a1.z; As[0][(acol+3)*128+arow+64]=a1.w;
    *(float4*)&Bs[0][brow*128+bcol]     = b0;
    *(float4*)&Bs[0][(brow+8)*128+bcol] = b1;
    __syncthreads();

    int tr = tid >> 4, tc = tid & 15;
    float acc[8][8] = {};
    int buf = 0;
    for (int kt = 0; kt < 32; kt++) {
        if (kt < 31) {
            const float* An = Ab + (kt+1)*16;
            const float* Bn = Bb + (size_t)(kt+1)*16*512;
            a0 = *(const float4*)(An + (size_t)arow*512 + acol);
            a1 = *(const float4*)(An + (size_t)(arow+64)*512 + acol);
            b0 = *(const float4*)(Bn + (size_t)brow*512 + bcol);
            b1 = *(const float4*)(Bn + (size_t)(brow+8)*512 + bcol);
        }
#pragma unroll
        for (int k = 0; k < 16; k++) {
            float rm[8], rn[8];
            *(float4*)&rm[0] = *(float4*)&As[buf][k*128 + tr*8];
            *(float4*)&rm[4] = *(float4*)&As[buf][k*128 + tr*8 + 4];
            *(float4*)&rn[0] = *(float4*)&Bs[buf][k*128 + tc*8];
            *(float4*)&rn[4] = *(float4*)&Bs[buf][k*128 + tc*8 + 4];
#pragma unroll
            for (int i = 0; i < 8; i++)
#pragma unroll
                for (int j = 0; j < 8; j++) acc[i][j] += rm[i]*rn[j];
        }
        if (kt < 31) {
            int nb = buf ^ 1;
            As[nb][(acol+0)*128+arow]=a0.x; As[nb][(acol+1)*128+arow]=a0.y;
            As[nb][(acol+2)*128+arow]=a0.z; As[nb][(acol+3)*128+arow]=a0.w;
            As[nb][(acol+0)*128+arow+64]=a1.x; As[nb][(acol+1)*128+arow+64]=a1.y;
            As[nb][(acol+2)*128+arow+64]=a1.z; As[nb][(acol+3)*128+arow+64]=a1.w;
            *(float4*)&Bs[nb][brow*128+bcol]     = b0;
            *(float4*)&Bs[nb][(brow+8)*128+bcol] = b1;
            __syncthreads();
            buf = nb;
        }
    }
    const float* bias = jb.b + blockIdx.y*128;
    float* C = jb.C + (size_t)blockIdx.x*128*512 + blockIdx.y*128;
#pragma unroll
    for (int i = 0; i < 8; i++) {
        int r = tr*8 + i;
#pragma unroll
        for (int jj = 0; jj < 8; jj += 4) {
            float4 o;
            o.x = acc[i][jj+0] + bias[tc*8+jj+0];
            o.y = acc[i][jj+1] + bias[tc*8+jj+1];
            o.z = acc[i][jj+2] + bias[tc*8+jj+2];
            o.w = acc[i][jj+3] + bias[tc*8+jj+3];
            if (GELU) {
                o.x = 0.5f*o.x*(1.0f + erff(o.x*0.70710678118654752f));
                o.y = 0.5f*o.y*(1.0f + erff(o.y*0.70710678118654752f));
                o.z = 0.5f*o.z*(1.0f + erff(o.z*0.70710678118654752f));
                o.w = 0.5f*o.w*(1.0f + erff(o.w*0.70710678118654752f));
            }
            *(float4*)(C + (size_t)r*512 + tc*8 + jj) = o;
        }
    }
}

// ---------------- sigma projection: [4096,512]x[512,8] -------------------
__global__ void sig_kernel(const float* __restrict__ h, const float* __restrict__ Ws,
                           const float* __restrict__ bs, float* __restrict__ sig) {
    int row = blockIdx.x;
    int warp = threadIdx.x >> 5, lane = threadIdx.x & 31;
    const float* hr = h + (size_t)row*DM;
    float sum = 0.f;
    for (int k2 = lane; k2 < DM; k2 += 32) sum += hr[k2] * Ws[k2*NH + warp];
#pragma unroll
    for (int o = 16; o > 0; o >>= 1) sum += __shfl_xor_sync(0xffffffff, sum, o);
    if (lane == 0) sig[row*NH + warp] = sum + bs[warp];
}

// ---------------- scores: per (b,h) QK^T, 128x128 tile, scale fused -------
__global__ __launch_bounds__(256)
void scores128(const float* __restrict__ q, const float* __restrict__ k,
               float* __restrict__ out) {
    extern __shared__ float sh[];
    float* Qs = sh;            // [64][128] transposed: Qs[e*128 + row]
    float* Ks = sh + 64*128;
    int tid = threadIdx.x;
    int bh = blockIdx.z, b = bh >> 3, hh = bh & 7;
    int l0 = blockIdx.x * 128, s0 = blockIdx.y * 128;
    const float* qb = q + ((size_t)(b*512 + l0))*512 + hh*64;
    const float* kb = k + ((size_t)(b*512 + s0))*512 + hh*64;
    int arow = tid >> 2, acol = (tid & 3) * 4;
#pragma unroll
    for (int cc = 0; cc < 64; cc += 16) {
#pragma unroll
        for (int rr = 0; rr < 128; rr += 64) {
            int r = arow + rr, c = acol + cc;
            float4 qv = *(const float4*)(qb + (size_t)r*512 + c);
            Qs[(c+0)*128+r]=qv.x; Qs[(c+1)*128+r]=qv.y;
            Qs[(c+2)*128+r]=qv.z; Qs[(c+3)*128+r]=qv.w;
            float4 kv = *(const float4*)(kb + (size_t)r*512 + c);
            Ks[(c+0)*128+r]=kv.x; Ks[(c+1)*128+r]=kv.y;
            Ks[(c+2)*128+r]=kv.z; Ks[(c+3)*128+r]=kv.w;
        }
    }
    __syncthreads();
    int tr = tid >> 4, tc = tid & 15;
    float acc[8][8] = {};
#pragma unroll
    for (int e = 0; e < 64; e++) {
        float rm[8], rn[8];
        *(float4*)&rm[0] = *(float4*)&Qs[e*128 + tr*8];
        *(float4*)&rm[4] = *(float4*)&Qs[e*128 + tr*8 + 4];
        *(float4*)&rn[0] = *(float4*)&Ks[e*128 + tc*8];
        *(float4*)&rn[4] = *(float4*)&Ks[e*128 + tc*8 + 4];
#pragma unroll
        for (int i = 0; i < 8; i++)
#pragma unroll
            for (int j = 0; j < 8; j++) acc[i][j] += rm[i]*rn[j];
    }
    float* ob = out + ((size_t)bh*512 + l0)*512 + s0;
#pragma unroll
    for (int i = 0; i < 8; i++) {
        int r = tr*8 + i;
#pragma unroll
        for (int jj = 0; jj < 8; jj += 4) {
            float4 o;
            o.x = acc[i][jj+0]*0.125f; o.y = acc[i][jj+1]*0.125f;
            o.z = acc[i][jj+2]*0.125f; o.w = acc[i][jj+3]*0.125f;
            *(float4*)(ob + (size_t)r*512 + tc*8 + jj) = o;
        }
    }
}

// ---------------- in-place row softmax (scale already applied) ------------
__global__ void softmax_kernel(float* __restrict__ data) {
    size_t row = blockIdx.x;
    float* p = data + row*WIN;
    int tid = threadIdx.x;
    float v0 = p[tid];
    float v1 = p[tid + 256];
    __shared__ float red[256];
    red[tid] = fmaxf(v0, v1);
    __syncthreads();
    for (int s = 128; s > 0; s >>= 1) { if (tid < s) red[tid] = fmaxf(red[tid], red[tid+s]); __syncthreads(); }
    float m = red[0];
    __syncthreads();
    float e0 = __expf(v0 - m), e1 = __expf(v1 - m);
    red[tid] = e0 + e1;
    __syncthreads();
    for (int s = 128; s > 0; s >>= 1) { if (tid < s) red[tid] += red[tid+s]; __syncthreads(); }
    float inv = 1.0f / red[0];
    p[tid]       = e0 * inv;
    p[tid + 256] = e1 * inv;
}

// ---------------- prior + sigma writer ------------------------------------
__global__ void prior_kernel(const float* __restrict__ sig,
                             float* __restrict__ prior, float* __restrict__ sigma) {
    int idx = blockIdx.x;                // bh*WIN + l
    int l = idx & (WIN-1);
    int bh = idx >> 9;
    int b = bh >> 3, hh = bh & 7;
    float sv = sig[((size_t)b*WIN + l)*NH + hh];
    float sgm = 1.0f/(1.0f + __expf(-5.0f*sv)) + 1e-5f;
    float sg  = __expf(sgm * 1.0986122886681098f) - 1.0f;   // 3^sgm - 1
    float inv = 0.3989422804014327f / sg;                   // 1/sqrt(2pi)/sg
    float cc  = -1.0f/(2.0f*sg*sg);
    size_t base = ((size_t)bh*WIN + l)*WIN;
    int tid = threadIdx.x;
    for (int s = tid; s < WIN; s += 256) {
        float d = (float)(l - s);
        prior[base + s] = inv * __expf(cc*d*d);
        sigma[base + s] = sg;
    }
}

// ---------------- attn out: per (b,h) S[512,512] @ V[512,64], 128x64 ------
__global__ __launch_bounds__(128)
void attnv128(const float* __restrict__ series, const float* __restrict__ v,
              float* __restrict__ out) {
    __shared__ float Ss[128*33];
    __shared__ float Vs[32*64];
    int tid = threadIdx.x;
    int bh = blockIdx.y, b = bh >> 3, hh = bh & 7;
    int l0 = blockIdx.x * 128;
    const float* sb = series + ((size_t)bh*512 + l0)*512;
    const float* vb = v + (size_t)b*512*512 + hh*64;
    int tr = tid >> 3, tc = tid & 7;
    int vr = tid >> 2, vc = (tid & 3) * 16;
    float acc[8][8] = {};
    for (int kt = 0; kt < 512; kt += 32) {
#pragma unroll
        for (int c = 0; c < 32; c += 4) {
            float4 s4 = *(const float4*)(sb + (size_t)tid*512 + kt + c);
            Ss[tid*33 + c+0]=s4.x; Ss[tid*33 + c+1]=s4.y;
            Ss[tid*33 + c+2]=s4.z; Ss[tid*33 + c+3]=s4.w;
        }
#pragma unroll
        for (int c = 0; c < 16; c += 4)
            *(float4*)&Vs[vr*64 + vc + c] =
                *(const float4*)(vb + (size_t)(kt+vr)*512 + vc + c);
        __syncthreads();
#pragma unroll
        for (int k2 = 0; k2 < 32; k2++) {
            float rm[8], rn[8];
#pragma unroll
            for (int i = 0; i < 8; i++) rm[i] = Ss[(tr*8+i)*33 + k2];
            *(float4*)&rn[0] = *(float4*)&Vs[k2*64 + tc*8];
            *(float4*)&rn[4] = *(float4*)&Vs[k2*64 + tc*8 + 4];
#pragma unroll
            for (int i = 0; i < 8; i++)
#pragma unroll
                for (int j = 0; j < 8; j++) acc[i][j] += rm[i]*rn[j];
        }
        __syncthreads();
    }
    float* ob = out + ((size_t)(b*512 + l0))*512 + hh*64;
#pragma unroll
    for (int i = 0; i < 8; i++) {
        int r = tr*8 + i;
#pragma unroll
        for (int jj = 0; jj < 8; jj += 4) {
            float4 o;
            o.x = acc[i][jj+0]; o.y = acc[i][jj+1];
            o.z = acc[i][jj+2]; o.w = acc[i][jj+3];
            *(float4*)(ob + (size_t)r*512 + tc*8 + jj) = o;
        }
    }
}

// ---------------- LayerNorm: out = LN(x (+res)) * g + b -------------------
__global__ void ln_kernel(const float* __restrict__ x, const float* __restrict__ res,
                          const float* __restrict__ g, const float* __restrict__ bb,
                          float* __restrict__ out) {
    size_t row = blockIdx.x;
    int tid = threadIdx.x;
    const float* xr = x + row*DM;
    float v0 = xr[tid], v1 = xr[tid+256];
    if (res) { const float* rr = res + row*DM; v0 += rr[tid]; v1 += rr[tid+256]; }
    __shared__ float red[256];
    red[tid] = v0 + v1;
    __syncthreads();
    for (int s = 128; s > 0; s >>= 1) { if (tid < s) red[tid] += red[tid+s]; __syncthreads(); }
    float mu = red[0] * (1.0f/DM);
    __syncthreads();
    float d0 = v0 - mu, d1 = v1 - mu;
    red[tid] = d0*d0 + d1*d1;
    __syncthreads();
    for (int s = 128; s > 0; s >>= 1) { if (tid < s) red[tid] += red[tid+s]; __syncthreads(); }
    float r = rsqrtf(red[0]*(1.0f/DM) + 1e-3f);
    out[row*DM + tid]       = d0*r*g[tid]       + bb[tid];
    out[row*DM + tid + 256] = d1*r*g[tid+256]   + bb[tid+256];
}

// ---------------- final projection [4096,512]x[512,38] --------------------
__global__ void proj_kernel(const float* __restrict__ hf, const float* __restrict__ Wp,
                            const float* __restrict__ bp, float* __restrict__ out) {
    int row = blockIdx.x;
    int warp = threadIdx.x >> 5, lane = threadIdx.x & 31;
    const float* hr = hf + (size_t)row*DM;
    for (int c = warp; c < COUT; c += 8) {
        float sum = 0.f;
        for (int k2 = lane; k2 < DM; k2 += 32) sum += hr[k2] * Wp[(size_t)k2*COUT + c];
#pragma unroll
        for (int o = 16; o > 0; o >>= 1) sum += __shfl_xor_sync(0xffffffff, sum, o);
        if (lane == 0) out[(size_t)row*COUT + c] = sum + bp[c];
    }
}

// ---------------- host orchestration --------------------------------------
extern "C" void kernel_launch(void* const* d_in, const int* in_sizes, int n_in,
                              void* d_out, int out_size) {
    const float* x    = (const float*)d_in[0];
    const float* ck   = (const float*)d_in[1];
    const float* Wq   = (const float*)d_in[2];
    const float* bq   = (const float*)d_in[3];
    const float* Wk   = (const float*)d_in[4];
    const float* bk   = (const float*)d_in[5];
    const float* Wv   = (const float*)d_in[6];
    const float* bv   = (const float*)d_in[7];
    const float* Ws   = (const float*)d_in[8];
    const float* bs   = (const float*)d_in[9];
    const float* Wo   = (const float*)d_in[10];
    const float* bo   = (const float*)d_in[11];
    const float* W1   = (const float*)d_in[12];
    const float* b1   = (const float*)d_in[13];
    const float* W2   = (const float*)d_in[14];
    const float* b2   = (const float*)d_in[15];
    const float* ln1g = (const float*)d_in[16];
    const float* ln1b = (const float*)d_in[17];
    const float* ln2g = (const float*)d_in[18];
    const float* ln2b = (const float*)d_in[19];
    const float* lnfg = (const float*)d_in[20];
    const float* lnfb = (const float*)d_in[21];
    const float* Wp   = (const float*)d_in[22];
    const float* bp   = (const float*)d_in[23];
    float* out = (float*)d_out;

    float *h, *q, *k, *v, *t1, *t2, *sg;
    cudaGetSymbolAddress((void**)&h,  g_h);
    cudaGetSymbolAddress((void**)&q,  g_q);
    cudaGetSymbolAddress((void**)&k,  g_k);
    cudaGetSymbolAddress((void**)&v,  g_v);
    cudaGetSymbolAddress((void**)&t1, g_t1);
    cudaGetSymbolAddress((void**)&t2, g_t2);
    cudaGetSymbolAddress((void**)&sg, g_sig);

    cudaFuncSetAttribute(scores128, cudaFuncAttributeMaxDynamicSharedMemorySize, 65536);

    embed_kernel<<<ROWS, DM>>>(x, ck, h);

    dim3 g1(32, 4, 1);   // single gemm
    dim3 g3(32, 4, 3);   // qkv fused
    for (int i = 0; i < NL; i++) {
        GemmJob jq = { Wq + (size_t)i*DM*DM, bq + i*DM, q };
        GemmJob jk = { Wk + (size_t)i*DM*DM, bk + i*DM, k };
        GemmJob jv = { Wv + (size_t)i*DM*DM, bv + i*DM, v };
        GemmJob jo = { Wo + (size_t)i*DM*DM, bo + i*DM, t2 };
        GemmJob j1 = { W1 + (size_t)i*DM*DM, b1 + i*DM, t1 };
        GemmJob j2 = { W2 + (size_t)i*DM*DM, b2 + i*DM, t2 };

        sgemm128<false><<<g3, 256>>>(h, jq, jk, jv);
        sig_kernel<<<ROWS, 256>>>(h, Ws + (size_t)i*DM*NH, bs + i*NH, sg);

        float* ser = out + SERIES_OFF + (size_t)i*LAYER_ELEMS;
        scores128<<<dim3(4, 4, BATCH*NH), 256, 65536>>>(q, k, ser);
        softmax_kernel<<<BATCH*NH*WIN, 256>>>(ser);
        prior_kernel<<<BATCH*NH*WIN, 256>>>(sg,
                out + PRIOR_OFF + (size_t)i*LAYER_ELEMS,
                out + SIGMA_OFF + (size_t)i*LAYER_ELEMS);

        attnv128<<<dim3(4, BATCH*NH), 128>>>(ser, v, t1);
        sgemm128<false><<<g1, 256>>>(t1, jo, jo, jo);
        ln_kernel<<<ROWS, 256>>>(h, t2, ln1g + i*DM, ln1b + i*DM, h);

        sgemm128<true ><<<g1, 256>>>(h,  j1, j1, j1);
        sgemm128<false><<<g1, 256>>>(t1, j2, j2, j2);
        ln_kernel<<<ROWS, 256>>>(h, t2, ln2g + i*DM, ln2b + i*DM, h);
    }

    ln_kernel<<<ROWS, 256>>>(h, nullptr, lnfg, lnfb, t1);
    proj_kernel<<<ROWS, 256>>>(t1, Wp, bp, out);
}

// round 3
// speedup vs baseline: 1.9233x; 1.3872x over previous
#include <cuda_runtime.h>
#include <cuda_bf16.h>
#include <math.h>
#include <stdint.h>

#define WIN   512
#define BATCH 8
#define CIN   38
#define COUT  38
#define DM    512
#define NH    8
#define EHD   64
#define NL    3
#define ROWS  (BATCH*WIN)   /* 4096 */

#define OUT_ELEMS    (BATCH*WIN*COUT)
#define LAYER_ELEMS  ((size_t)BATCH*NH*WIN*WIN)
#define SERIES_OFF   ((size_t)OUT_ELEMS)
#define PRIOR_OFF    (SERIES_OFF + 3*LAYER_ELEMS)
#define SIGMA_OFF    (PRIOR_OFF  + 3*LAYER_ELEMS)

// ---------------- scratch ---------------------------------------------------
__device__ float g_h [ROWS*DM];
__device__ float g_q [ROWS*DM];
__device__ float g_k [ROWS*DM];
__device__ float g_v [ROWS*DM];
__device__ float g_t1[ROWS*DM];
__device__ float g_t2[ROWS*DM];
__device__ float g_sig[ROWS*NH];

// ---------------- mma helpers ----------------------------------------------
__device__ __forceinline__ uint32_t smaddr(const void* p) {
    return (uint32_t)__cvta_generic_to_shared(p);
}
__device__ __forceinline__ void ldsm4(uint32_t a, uint32_t& r0, uint32_t& r1,
                                      uint32_t& r2, uint32_t& r3) {
    asm volatile("ldmatrix.sync.aligned.m8n8.x4.shared.b16 {%0,%1,%2,%3}, [%4];\n"
                 : "=r"(r0), "=r"(r1), "=r"(r2), "=r"(r3) : "r"(a));
}
__device__ __forceinline__ void ldsm4t(uint32_t a, uint32_t& r0, uint32_t& r1,
                                       uint32_t& r2, uint32_t& r3) {
    asm volatile("ldmatrix.sync.aligned.m8n8.x4.trans.shared.b16 {%0,%1,%2,%3}, [%4];\n"
                 : "=r"(r0), "=r"(r1), "=r"(r2), "=r"(r3) : "r"(a));
}
__device__ __forceinline__ void mmabf(float* d, const uint32_t* a, uint32_t b0, uint32_t b1) {
    asm volatile("mma.sync.aligned.m16n8k16.row.col.f32.bf16.bf16.f32 "
                 "{%0,%1,%2,%3}, {%4,%5,%6,%7}, {%8,%9}, {%0,%1,%2,%3};\n"
                 : "+f"(d[0]), "+f"(d[1]), "+f"(d[2]), "+f"(d[3])
                 : "r"(a[0]), "r"(a[1]), "r"(a[2]), "r"(a[3]), "r"(b0), "r"(b1));
}
// split fp32 pair -> (hi,hi) and (lo,lo) bf16x2 stores
__device__ __forceinline__ void cvst(float x, float y, __nv_bfloat16* ph, __nv_bfloat16* pl) {
    __nv_bfloat16 h0 = __float2bfloat16_rn(x);
    __nv_bfloat16 l0 = __float2bfloat16_rn(x - __bfloat162float(h0));
    __nv_bfloat16 h1 = __float2bfloat16_rn(y);
    __nv_bfloat16 l1 = __float2bfloat16_rn(y - __bfloat162float(h1));
    *(__nv_bfloat162*)ph = __halves2bfloat162(h0, h1);
    *(__nv_bfloat162*)pl = __halves2bfloat162(l0, l1);
}

// ---------------- embedding -------------------------------------------------
__global__ void embed_kernel(const float* __restrict__ x,
                             const float* __restrict__ ck,
                             float* __restrict__ h) {
    int bt = blockIdx.x;
    int b = bt >> 9, t = bt & (WIN-1);
    __shared__ float xs[3*CIN];
    int tid = threadIdx.x;
    if (tid < 3*CIN) {
        int w = tid / CIN, c = tid % CIN;
        int src = (t + w - 1 + WIN) & (WIN-1);
        xs[tid] = x[((size_t)b*WIN + src)*CIN + c];
    }
    __syncthreads();
    int d = tid;
    int i2 = (d >> 1) * 2;
    float ang = (float)t * __expf(-(float)i2 * (9.210340371976184f/512.0f));
    float acc = (d & 1) ? cosf(ang) : sinf(ang);
#pragma unroll 1
    for (int wc = 0; wc < 3*CIN; wc++)
        acc += xs[wc] * ck[(size_t)wc*DM + d];
    h[(size_t)bt*DM + d] = acc;
}

// ---------------- dense GEMM: bf16x3 mma, 128x128 tile, BK=32 ---------------
struct GemmJob { const float* W; const float* b; float* C; };

#define AH_OFF 0
#define AL_OFF 5120
#define BH_OFF 10240
#define BL_OFF 14592
#define BUF_SZ 18944   /* halves per buffer */

__device__ __forceinline__ void mg_store(__nv_bfloat16* sm, int buf, int tid,
                                         const float4* fa, const float4* fb) {
    __nv_bfloat16* Ah = sm + buf*BUF_SZ + AH_OFF;
    __nv_bfloat16* Al = sm + buf*BUF_SZ + AL_OFF;
    __nv_bfloat16* Bh = sm + buf*BUF_SZ + BH_OFF;
    __nv_bfloat16* Bl = sm + buf*BUF_SZ + BL_OFF;
    int ar = tid >> 1, ac = (tid & 1) * 16;
    int br = tid >> 3, bc = (tid & 7) * 16;
#pragma unroll
    for (int i = 0; i < 4; i++) {
        int ia = ar*40 + ac + i*4;
        cvst(fa[i].x, fa[i].y, &Ah[ia],   &Al[ia]);
        cvst(fa[i].z, fa[i].w, &Ah[ia+2], &Al[ia+2]);
        int ib = br*136 + bc + i*4;
        cvst(fb[i].x, fb[i].y, &Bh[ib],   &Bl[ib]);
        cvst(fb[i].z, fb[i].w, &Bh[ib+2], &Bl[ib+2]);
    }
}

__device__ __forceinline__ void mg_compute(uint32_t smb, int buf, int tid,
                                           float (*acc)[8][4]) {
    int l = tid & 31, w = tid >> 5, wm = w & 3, wn = w >> 2;
    int lr = l & 15, lc8 = (l >> 4) << 3;
    uint32_t base = smb + (uint32_t)buf * (BUF_SZ*2);
#pragma unroll
    for (int ks = 0; ks < 32; ks += 16) {
        uint32_t ah[2][4], al[2][4];
#pragma unroll
        for (int fm = 0; fm < 2; fm++) {
            uint32_t aoff = (uint32_t)((wm*32 + fm*16 + lr)*40 + ks + lc8) * 2;
            ldsm4(base + AH_OFF*2 + aoff, ah[fm][0], ah[fm][1], ah[fm][2], ah[fm][3]);
            ldsm4(base + AL_OFF*2 + aoff, al[fm][0], al[fm][1], al[fm][2], al[fm][3]);
        }
#pragma unroll
        for (int fnp = 0; fnp < 4; fnp++) {
            uint32_t boff = (uint32_t)((ks + lr)*136 + wn*64 + fnp*16 + lc8) * 2;
            uint32_t bh[4], bl[4];
            ldsm4t(base + BH_OFF*2 + boff, bh[0], bh[1], bh[2], bh[3]);
            ldsm4t(base + BL_OFF*2 + boff, bl[0], bl[1], bl[2], bl[3]);
#pragma unroll
            for (int fm = 0; fm < 2; fm++) {
                mmabf(acc[fm][fnp*2],   ah[fm], bh[0], bh[1]);
                mmabf(acc[fm][fnp*2],   ah[fm], bl[0], bl[1]);
                mmabf(acc[fm][fnp*2],   al[fm], bh[0], bh[1]);
                mmabf(acc[fm][fnp*2+1], ah[fm], bh[2], bh[3]);
                mmabf(acc[fm][fnp*2+1], ah[fm], bl[2], bl[3]);
                mmabf(acc[fm][fnp*2+1], al[fm], bh[2], bh[3]);
            }
        }
    }
}

template<bool GELU>
__global__ __launch_bounds__(256)
void mgemm(const float* __restrict__ A, GemmJob j0, GemmJob j1, GemmJob j2) {
    extern __shared__ __nv_bfloat16 sm[];
    GemmJob jb = (blockIdx.z == 0) ? j0 : ((blockIdx.z == 1) ? j1 : j2);
    int tid = threadIdx.x;
    const float* Ab = A + (size_t)blockIdx.x * 128 * 512;
    const float* Bb = jb.W + blockIdx.y * 128;
    int ar = tid >> 1, ac = (tid & 1) * 16;
    int br = tid >> 3, bc = (tid & 7) * 16;
    uint32_t smb = smaddr(sm);

    float4 fa[4], fb[4];
#pragma unroll
    for (int i = 0; i < 4; i++) {
        fa[i] = *(const float4*)(Ab + (size_t)ar*512 + ac + i*4);
        fb[i] = *(const float4*)(Bb + (size_t)br*512 + bc + i*4);
    }
    mg_store(sm, 0, tid, fa, fb);
    __syncthreads();

    float acc[2][8][4] = {};
    int buf = 0;
    for (int kt = 0; kt < 16; kt++) {
        if (kt < 15) {
            const float* An = Ab + (kt+1)*32;
            const float* Bn = Bb + (size_t)(kt+1)*32*512;
#pragma unroll
            for (int i = 0; i < 4; i++) {
                fa[i] = *(const float4*)(An + (size_t)ar*512 + ac + i*4);
                fb[i] = *(const float4*)(Bn + (size_t)br*512 + bc + i*4);
            }
        }
        mg_compute(smb, buf, tid, acc);
        if (kt < 15) {
            mg_store(sm, buf ^ 1, tid, fa, fb);
            __syncthreads();
            buf ^= 1;
        }
    }

    int l = tid & 31, w = tid >> 5, wm = w & 3, wn = w >> 2;
    int g = l >> 2, t2 = (l & 3) * 2;
    int rowb = blockIdx.x*128 + wm*32;
    int colb = blockIdx.y*128 + wn*64;
#pragma unroll
    for (int fm = 0; fm < 2; fm++) {
#pragma unroll
        for (int fn = 0; fn < 8; fn++) {
            int col = colb + fn*8 + t2;
            float bx0 = jb.b[col], bx1 = jb.b[col+1];
            float o0 = acc[fm][fn][0] + bx0, o1 = acc[fm][fn][1] + bx1;
            float o2 = acc[fm][fn][2] + bx0, o3 = acc[fm][fn][3] + bx1;
            if (GELU) {
                o0 = 0.5f*o0*(1.0f + erff(o0*0.70710678118654752f));
                o1 = 0.5f*o1*(1.0f + erff(o1*0.70710678118654752f));
                o2 = 0.5f*o2*(1.0f + erff(o2*0.70710678118654752f));
                o3 = 0.5f*o3*(1.0f + erff(o3*0.70710678118654752f));
            }
            int r0 = rowb + fm*16 + g;
            float2 p0 = {o0, o1}, p1 = {o2, o3};
            *(float2*)(jb.C + (size_t)r0*512 + col)     = p0;
            *(float2*)(jb.C + (size_t)(r0+8)*512 + col) = p1;
        }
    }
}

// ---------------- scores: bf16x3 mma QK^T, 128x128 tile, K=64 ---------------
#define SQH 0
#define SQL 9216
#define SKH 18432
#define SKL 27648

__global__ __launch_bounds__(256)
void scores_mma(const float* __restrict__ q, const float* __restrict__ k,
                float* __restrict__ out) {
    extern __shared__ __nv_bfloat16 sm[];
    int tid = threadIdx.x;
    int bhz = blockIdx.z, b = bhz >> 3, hh = bhz & 7;
    int l0 = blockIdx.x * 128, s0 = blockIdx.y * 128;
    const float* qb = q + ((size_t)(b*512 + l0))*512 + hh*64;
    const float* kb = k + ((size_t)(b*512 + s0))*512 + hh*64;
    int r = tid >> 1, c0 = (tid & 1) * 32;
#pragma unroll
    for (int i = 0; i < 8; i++) {
        float4 v = *(const float4*)(qb + (size_t)r*512 + c0 + i*4);
        int idx = r*72 + c0 + i*4;
        cvst(v.x, v.y, &sm[SQH + idx],     &sm[SQL + idx]);
        cvst(v.z, v.w, &sm[SQH + idx + 2], &sm[SQL + idx + 2]);
        float4 u = *(const float4*)(kb + (size_t)r*512 + c0 + i*4);
        cvst(u.x, u.y, &sm[SKH + idx],     &sm[SKL + idx]);
        cvst(u.z, u.w, &sm[SKH + idx + 2], &sm[SKL + idx + 2]);
    }
    __syncthreads();

    uint32_t smb = smaddr(sm);
    int l = tid & 31, w = tid >> 5, wm = w & 3, wn = w >> 2;
    int lr = l & 15, lc8 = (l >> 4) << 3;
    float acc[2][8][4] = {};
#pragma unroll
    for (int ks = 0; ks < 64; ks += 16) {
        uint32_t ah[2][4], al[2][4];
#pragma unroll
        for (int fm = 0; fm < 2; fm++) {
            uint32_t aoff = (uint32_t)((wm*32 + fm*16 + lr)*72 + ks + lc8) * 2;
            ldsm4(smb + SQH*2 + aoff, ah[fm][0], ah[fm][1], ah[fm][2], ah[fm][3]);
            ldsm4(smb + SQL*2 + aoff, al[fm][0], al[fm][1], al[fm][2], al[fm][3]);
        }
#pragma unroll
        for (int fnp = 0; fnp < 4; fnp++) {
            uint32_t boff = (uint32_t)((wn*64 + fnp*16 + lr)*72 + ks + lc8) * 2;
            uint32_t kh[4], kl[4];
            // non-trans: r0=b0(fn), r1=b0(fn+1), r2=b1(fn), r3=b1(fn+1)
            ldsm4(smb + SKH*2 + boff, kh[0], kh[1], kh[2], kh[3]);
            ldsm4(smb + SKL*2 + boff, kl[0], kl[1], kl[2], kl[3]);
#pragma unroll
            for (int fm = 0; fm < 2; fm++) {
                mmabf(acc[fm][fnp*2],   ah[fm], kh[0], kh[2]);
                mmabf(acc[fm][fnp*2],   ah[fm], kl[0], kl[2]);
                mmabf(acc[fm][fnp*2],   al[fm], kh[0], kh[2]);
                mmabf(acc[fm][fnp*2+1], ah[fm], kh[1], kh[3]);
                mmabf(acc[fm][fnp*2+1], ah[fm], kl[1], kl[3]);
                mmabf(acc[fm][fnp*2+1], al[fm], kh[1], kh[3]);
            }
        }
    }

    int g = l >> 2, t2 = (l & 3) * 2;
    float* ob = out + ((size_t)bhz*512 + l0)*512 + s0;
#pragma unroll
    for (int fm = 0; fm < 2; fm++) {
#pragma unroll
        for (int fn = 0; fn < 8; fn++) {
            int row = wm*32 + fm*16 + g;
            int col = wn*64 + fn*8 + t2;
            float2 p0 = {acc[fm][fn][0]*0.125f, acc[fm][fn][1]*0.125f};
            float2 p1 = {acc[fm][fn][2]*0.125f, acc[fm][fn][3]*0.125f};
            *(float2*)(ob + (size_t)row*512 + col)     = p0;
            *(float2*)(ob + (size_t)(row+8)*512 + col) = p1;
        }
    }
}

// ---------------- sigma projection -----------------------------------------
__global__ void sig_kernel(const float* __restrict__ h, const float* __restrict__ Ws,
                           const float* __restrict__ bs, float* __restrict__ sig) {
    int row = blockIdx.x;
    int warp = threadIdx.x >> 5, lane = threadIdx.x & 31;
    const float* hr = h + (size_t)row*DM;
    float sum = 0.f;
    for (int k2 = lane; k2 < DM; k2 += 32) sum += hr[k2] * Ws[k2*NH + warp];
#pragma unroll
    for (int o = 16; o > 0; o >>= 1) sum += __shfl_xor_sync(0xffffffff, sum, o);
    if (lane == 0) sig[row*NH + warp] = sum + bs[warp];
}

// ---------------- softmax ---------------------------------------------------
__global__ void softmax_kernel(float* __restrict__ data) {
    size_t row = blockIdx.x;
    float* p = data + row*WIN;
    int tid = threadIdx.x;
    float v0 = p[tid];
    float v1 = p[tid + 256];
    __shared__ float red[256];
    red[tid] = fmaxf(v0, v1);
    __syncthreads();
    for (int s = 128; s > 0; s >>= 1) { if (tid < s) red[tid] = fmaxf(red[tid], red[tid+s]); __syncthreads(); }
    float m = red[0];
    __syncthreads();
    float e0 = __expf(v0 - m), e1 = __expf(v1 - m);
    red[tid] = e0 + e1;
    __syncthreads();
    for (int s = 128; s > 0; s >>= 1) { if (tid < s) red[tid] += red[tid+s]; __syncthreads(); }
    float inv = 1.0f / red[0];
    p[tid]       = e0 * inv;
    p[tid + 256] = e1 * inv;
}

// ---------------- prior + sigma ---------------------------------------------
__global__ void prior_kernel(const float* __restrict__ sig,
                             float* __restrict__ prior, float* __restrict__ sigma) {
    int idx = blockIdx.x;
    int l = idx & (WIN-1);
    int bh = idx >> 9;
    int b = bh >> 3, hh = bh & 7;
    float sv = sig[((size_t)b*WIN + l)*NH + hh];
    float sgm = 1.0f/(1.0f + __expf(-5.0f*sv)) + 1e-5f;
    float sg  = __expf(sgm * 1.0986122886681098f) - 1.0f;
    float inv = 0.3989422804014327f / sg;
    float cc  = -1.0f/(2.0f*sg*sg);
    size_t base = ((size_t)bh*WIN + l)*WIN;
    int tid = threadIdx.x;
    for (int s = tid; s < WIN; s += 256) {
        float d = (float)(l - s);
        prior[base + s] = inv * __expf(cc*d*d);
        sigma[base + s] = sg;
    }
}

// ---------------- attn out --------------------------------------------------
__global__ __launch_bounds__(128)
void attnv128(const float* __restrict__ series, const float* __restrict__ v,
              float* __restrict__ out) {
    __shared__ float Ss[128*33];
    __shared__ float Vs[32*64];
    int tid = threadIdx.x;
    int bh = blockIdx.y, b = bh >> 3, hh = bh & 7;
    int l0 = blockIdx.x * 128;
    const float* sb = series + ((size_t)bh*512 + l0)*512;
    const float* vb = v + (size_t)b*512*512 + hh*64;
    int tr = tid >> 3, tc = tid & 7;
    int vr = tid >> 2, vc = (tid & 3) * 16;
    float acc[8][8] = {};
    for (int kt = 0; kt < 512; kt += 32) {
#pragma unroll
        for (int c = 0; c < 32; c += 4) {
            float4 s4 = *(const float4*)(sb + (size_t)tid*512 + kt + c);
            Ss[tid*33 + c+0]=s4.x; Ss[tid*33 + c+1]=s4.y;
            Ss[tid*33 + c+2]=s4.z; Ss[tid*33 + c+3]=s4.w;
        }
#pragma unroll
        for (int c = 0; c < 16; c += 4)
            *(float4*)&Vs[vr*64 + vc + c] =
                *(const float4*)(vb + (size_t)(kt+vr)*512 + vc + c);
        __syncthreads();
#pragma unroll
        for (int k2 = 0; k2 < 32; k2++) {
            float rm[8], rn[8];
#pragma unroll
            for (int i = 0; i < 8; i++) rm[i] = Ss[(tr*8+i)*33 + k2];
            *(float4*)&rn[0] = *(float4*)&Vs[k2*64 + tc*8];
            *(float4*)&rn[4] = *(float4*)&Vs[k2*64 + tc*8 + 4];
#pragma unroll
            for (int i = 0; i < 8; i++)
#pragma unroll
                for (int j = 0; j < 8; j++) acc[i][j] += rm[i]*rn[j];
        }
        __syncthreads();
    }
    float* ob = out + ((size_t)(b*512 + l0))*512 + hh*64;
#pragma unroll
    for (int i = 0; i < 8; i++) {
        int r = tr*8 + i;
#pragma unroll
        for (int jj = 0; jj < 8; jj += 4) {
            float4 o;
            o.x = acc[i][jj+0]; o.y = acc[i][jj+1];
            o.z = acc[i][jj+2]; o.w = acc[i][jj+3];
            *(float4*)(ob + (size_t)r*512 + tc*8 + jj) = o;
        }
    }
}

// ---------------- LayerNorm -------------------------------------------------
__global__ void ln_kernel(const float* __restrict__ x, const float* __restrict__ res,
                          const float* __restrict__ g, const float* __restrict__ bb,
                          float* __restrict__ out) {
    size_t row = blockIdx.x;
    int tid = threadIdx.x;
    const float* xr = x + row*DM;
    float v0 = xr[tid], v1 = xr[tid+256];
    if (res) { const float* rr = res + row*DM; v0 += rr[tid]; v1 += rr[tid+256]; }
    __shared__ float red[256];
    red[tid] = v0 + v1;
    __syncthreads();
    for (int s = 128; s > 0; s >>= 1) { if (tid < s) red[tid] += red[tid+s]; __syncthreads(); }
    float mu = red[0] * (1.0f/DM);
    __syncthreads();
    float d0 = v0 - mu, d1 = v1 - mu;
    red[tid] = d0*d0 + d1*d1;
    __syncthreads();
    for (int s = 128; s > 0; s >>= 1) { if (tid < s) red[tid] += red[tid+s]; __syncthreads(); }
    float r = rsqrtf(red[0]*(1.0f/DM) + 1e-3f);
    out[row*DM + tid]       = d0*r*g[tid]       + bb[tid];
    out[row*DM + tid + 256] = d1*r*g[tid+256]   + bb[tid+256];
}

// ---------------- final projection ------------------------------------------
__global__ void proj_kernel(const float* __restrict__ hf, const float* __restrict__ Wp,
                            const float* __restrict__ bp, float* __restrict__ out) {
    int row = blockIdx.x;
    int warp = threadIdx.x >> 5, lane = threadIdx.x & 31;
    const float* hr = hf + (size_t)row*DM;
    for (int c = warp; c < COUT; c += 8) {
        float sum = 0.f;
        for (int k2 = lane; k2 < DM; k2 += 32) sum += hr[k2] * Wp[(size_t)k2*COUT + c];
#pragma unroll
        for (int o = 16; o > 0; o >>= 1) sum += __shfl_xor_sync(0xffffffff, sum, o);
        if (lane == 0) out[(size_t)row*COUT + c] = sum + bp[c];
    }
}

// ---------------- host orchestration ----------------------------------------
extern "C" void kernel_launch(void* const* d_in, const int* in_sizes, int n_in,
                              void* d_out, int out_size) {
    const float* x    = (const float*)d_in[0];
    const float* ck   = (const float*)d_in[1];
    const float* Wq   = (const float*)d_in[2];
    const float* bq   = (const float*)d_in[3];
    const float* Wk   = (const float*)d_in[4];
    const float* bk   = (const float*)d_in[5];
    const float* Wv   = (const float*)d_in[6];
    const float* bv   = (const float*)d_in[7];
    const float* Ws   = (const float*)d_in[8];
    const float* bs   = (const float*)d_in[9];
    const float* Wo   = (const float*)d_in[10];
    const float* bo   = (const float*)d_in[11];
    const float* W1   = (const float*)d_in[12];
    const float* b1   = (const float*)d_in[13];
    const float* W2   = (const float*)d_in[14];
    const float* b2   = (const float*)d_in[15];
    const float* ln1g = (const float*)d_in[16];
    const float* ln1b = (const float*)d_in[17];
    const float* ln2g = (const float*)d_in[18];
    const float* ln2b = (const float*)d_in[19];
    const float* lnfg = (const float*)d_in[20];
    const float* lnfb = (const float*)d_in[21];
    const float* Wp   = (const float*)d_in[22];
    const float* bp   = (const float*)d_in[23];
    float* out = (float*)d_out;

    float *h, *q, *k, *v, *t1, *t2, *sg;
    cudaGetSymbolAddress((void**)&h,  g_h);
    cudaGetSymbolAddress((void**)&q,  g_q);
    cudaGetSymbolAddress((void**)&k,  g_k);
    cudaGetSymbolAddress((void**)&v,  g_v);
    cudaGetSymbolAddress((void**)&t1, g_t1);
    cudaGetSymbolAddress((void**)&t2, g_t2);
    cudaGetSymbolAddress((void**)&sg, g_sig);

    cudaFuncSetAttribute(mgemm<false>, cudaFuncAttributeMaxDynamicSharedMemorySize, 75776);
    cudaFuncSetAttribute(mgemm<true>,  cudaFuncAttributeMaxDynamicSharedMemorySize, 75776);
    cudaFuncSetAttribute(scores_mma,   cudaFuncAttributeMaxDynamicSharedMemorySize, 73728);

    embed_kernel<<<ROWS, DM>>>(x, ck, h);

    dim3 g1(32, 4, 1);
    dim3 g3(32, 4, 3);
    for (int i = 0; i < NL; i++) {
        GemmJob jq = { Wq + (size_t)i*DM*DM, bq + i*DM, q };
        GemmJob jk = { Wk + (size_t)i*DM*DM, bk + i*DM, k };
        GemmJob jv = { Wv + (size_t)i*DM*DM, bv + i*DM, v };
        GemmJob jo = { Wo + (size_t)i*DM*DM, bo + i*DM, t2 };
        GemmJob j1 = { W1 + (size_t)i*DM*DM, b1 + i*DM, t1 };
        GemmJob j2 = { W2 + (size_t)i*DM*DM, b2 + i*DM, t2 };

        mgemm<false><<<g3, 256, 75776>>>(h, jq, jk, jv);
        sig_kernel<<<ROWS, 256>>>(h, Ws + (size_t)i*DM*NH, bs + i*NH, sg);

        float* ser = out + SERIES_OFF + (size_t)i*LAYER_ELEMS;
        scores_mma<<<dim3(4, 4, BATCH*NH), 256, 73728>>>(q, k, ser);
        softmax_kernel<<<BATCH*NH*WIN, 256>>>(ser);
        prior_kernel<<<BATCH*NH*WIN, 256>>>(sg,
                out + PRIOR_OFF + (size_t)i*LAYER_ELEMS,
                out + SIGMA_OFF + (size_t)i*LAYER_ELEMS);

        attnv128<<<dim3(4, BATCH*NH), 128>>>(ser, v, t1);
        mgemm<false><<<g1, 256, 75776>>>(t1, jo, jo, jo);
        ln_kernel<<<ROWS, 256>>>(h, t2, ln1g + i*DM, ln1b + i*DM, h);

        mgemm<true ><<<g1, 256, 75776>>>(h,  j1, j1, j1);
        mgemm<false><<<g1, 256, 75776>>>(t1, j2, j2, j2);
        ln_kernel<<<ROWS, 256>>>(h, t2, ln2g + i*DM, ln2b + i*DM, h);
    }

    ln_kernel<<<ROWS, 256>>>(h, nullptr, lnfg, lnfb, t1);
    proj_kernel<<<ROWS, 256>>>(t1, Wp, bp, out);
}

// round 4
// speedup vs baseline: 2.0248x; 1.0528x over previous
#include <cuda_runtime.h>
#include <cuda_bf16.h>
#include <math.h>
#include <stdint.h>

#define WIN   512
#define BATCH 8
#define CIN   38
#define COUT  38
#define DM    512
#define NH    8
#define EHD   64
#define NL    3
#define ROWS  (BATCH*WIN)   /* 4096 */

#define OUT_ELEMS    (BATCH*WIN*COUT)
#define LAYER_ELEMS  ((size_t)BATCH*NH*WIN*WIN)
#define SERIES_OFF   ((size_t)OUT_ELEMS)
#define PRIOR_OFF    (SERIES_OFF + 3*LAYER_ELEMS)
#define SIGMA_OFF    (PRIOR_OFF  + 3*LAYER_ELEMS)

// ---------------- scratch ---------------------------------------------------
__device__ float g_h [ROWS*DM];
__device__ float g_v [ROWS*DM];
__device__ float g_t1[ROWS*DM];
__device__ float g_t2[ROWS*DM];
__device__ float g_sig[ROWS*NH];
__device__ __nv_bfloat16 g_hh [ROWS*DM];
__device__ __nv_bfloat16 g_hl [ROWS*DM];
__device__ __nv_bfloat16 g_qh [ROWS*DM];
__device__ __nv_bfloat16 g_ql [ROWS*DM];
__device__ __nv_bfloat16 g_kh [ROWS*DM];
__device__ __nv_bfloat16 g_kl [ROWS*DM];
__device__ __nv_bfloat16 g_t1h[ROWS*DM];
__device__ __nv_bfloat16 g_t1l[ROWS*DM];
__device__ __nv_bfloat16 g_wh [18*262144];
__device__ __nv_bfloat16 g_wl [18*262144];

// ---------------- helpers ---------------------------------------------------
__device__ __forceinline__ uint32_t smaddr(const void* p) {
    return (uint32_t)__cvta_generic_to_shared(p);
}
__device__ __forceinline__ void ldsm4(uint32_t a, uint32_t& r0, uint32_t& r1,
                                      uint32_t& r2, uint32_t& r3) {
    asm volatile("ldmatrix.sync.aligned.m8n8.x4.shared.b16 {%0,%1,%2,%3}, [%4];\n"
                 : "=r"(r0), "=r"(r1), "=r"(r2), "=r"(r3) : "r"(a));
}
__device__ __forceinline__ void ldsm4t(uint32_t a, uint32_t& r0, uint32_t& r1,
                                       uint32_t& r2, uint32_t& r3) {
    asm volatile("ldmatrix.sync.aligned.m8n8.x4.trans.shared.b16 {%0,%1,%2,%3}, [%4];\n"
                 : "=r"(r0), "=r"(r1), "=r"(r2), "=r"(r3) : "r"(a));
}
__device__ __forceinline__ void mmabf(float* d, const uint32_t* a, uint32_t b0, uint32_t b1) {
    asm volatile("mma.sync.aligned.m16n8k16.row.col.f32.bf16.bf16.f32 "
                 "{%0,%1,%2,%3}, {%4,%5,%6,%7}, {%8,%9}, {%0,%1,%2,%3};\n"
                 : "+f"(d[0]), "+f"(d[1]), "+f"(d[2]), "+f"(d[3])
                 : "r"(a[0]), "r"(a[1]), "r"(a[2]), "r"(a[3]), "r"(b0), "r"(b1));
}
__device__ __forceinline__ void cvst(float x, float y, __nv_bfloat16* ph, __nv_bfloat16* pl) {
    __nv_bfloat16 h0 = __float2bfloat16_rn(x);
    __nv_bfloat16 l0 = __float2bfloat16_rn(x - __bfloat162float(h0));
    __nv_bfloat16 h1 = __float2bfloat16_rn(y);
    __nv_bfloat16 l1 = __float2bfloat16_rn(y - __bfloat162float(h1));
    *(__nv_bfloat162*)ph = __halves2bfloat162(h0, h1);
    *(__nv_bfloat162*)pl = __halves2bfloat162(l0, l1);
}
__device__ __forceinline__ void cvst1(float x, __nv_bfloat16* ph, __nv_bfloat16* pl) {
    __nv_bfloat16 h0 = __float2bfloat16_rn(x);
    *ph = h0;
    *pl = __float2bfloat16_rn(x - __bfloat162float(h0));
}
__device__ __forceinline__ void cpa16(uint32_t s, const void* g) {
    asm volatile("cp.async.ca.shared.global [%0], [%1], 16;\n" :: "r"(s), "l"(g));
}

// ---------------- weight pre-conversion -------------------------------------
__global__ void wconv_kernel(const float* __restrict__ Wq, const float* __restrict__ Wk,
                             const float* __restrict__ Wv, const float* __restrict__ Wo,
                             const float* __restrict__ W1, const float* __restrict__ W2,
                             __nv_bfloat16* __restrict__ wh, __nv_bfloat16* __restrict__ wl) {
    size_t j4 = ((size_t)blockIdx.x*256 + threadIdx.x) * 4;
    if (j4 >= 18ull*262144) return;
    size_t uu = j4 >> 18;
    int u = (int)(uu % 6), i = (int)(uu / 6);
    size_t off = j4 & 262143;
    const float* src;
    switch (u) { case 0: src=Wq; break; case 1: src=Wk; break; case 2: src=Wv; break;
                 case 3: src=Wo; break; case 4: src=W1; break; default: src=W2; }
    float4 f = *(const float4*)(src + (size_t)i*262144 + off);
    cvst(f.x, f.y, wh+j4,   wl+j4);
    cvst(f.z, f.w, wh+j4+2, wl+j4+2);
}

// ---------------- embedding -------------------------------------------------
__global__ void embed_kernel(const float* __restrict__ x,
                             const float* __restrict__ ck,
                             float* __restrict__ h,
                             __nv_bfloat16* __restrict__ hh,
                             __nv_bfloat16* __restrict__ hl) {
    int bt = blockIdx.x;
    int b = bt >> 9, t = bt & (WIN-1);
    __shared__ float xs[3*CIN];
    int tid = threadIdx.x;
    if (tid < 3*CIN) {
        int w = tid / CIN, c = tid % CIN;
        int src = (t + w - 1 + WIN) & (WIN-1);
        xs[tid] = x[((size_t)b*WIN + src)*CIN + c];
    }
    __syncthreads();
    int d = tid;
    int i2 = (d >> 1) * 2;
    float ang = (float)t * __expf(-(float)i2 * (9.210340371976184f/512.0f));
    float acc = (d & 1) ? cosf(ang) : sinf(ang);
#pragma unroll 1
    for (int wc = 0; wc < 3*CIN; wc++)
        acc += xs[wc] * ck[(size_t)wc*DM + d];
    size_t idx = (size_t)bt*DM + d;
    h[idx] = acc;
    cvst1(acc, hh + idx, hl + idx);
}

// ---------------- dense GEMM: pure-bf16 in, cp.async pipeline ---------------
struct GemmJob {
    const __nv_bfloat16* Wh; const __nv_bfloat16* Wl;
    const float* bias;
    float* Cf; __nv_bfloat16* Ch; __nv_bfloat16* Cl;
};

#define AH_OFF 0
#define AL_OFF 5120
#define BH_OFF 10240
#define BL_OFF 14592
#define BUF_SZ 18944   /* halves per buffer */

__device__ __forceinline__ void mg_issue(uint32_t smb, int buf, int tid,
        const __nv_bfloat16* Ah, const __nv_bfloat16* Al,
        const __nv_bfloat16* Wh, const __nv_bfloat16* Wl, int kt) {
    int ar = tid >> 1, ac = (tid & 1) * 16;
    int br = tid >> 3, bc = (tid & 7) * 16;
    uint32_t base = smb + (uint32_t)buf * (BUF_SZ*2);
    const __nv_bfloat16* ga  = Ah + (size_t)ar*512 + kt*32 + ac;
    const __nv_bfloat16* gal = Al + (size_t)ar*512 + kt*32 + ac;
    uint32_t sa  = base + (uint32_t)(AH_OFF + ar*40 + ac)*2;
    uint32_t sal = base + (uint32_t)(AL_OFF + ar*40 + ac)*2;
    cpa16(sa, ga);        cpa16(sa+16, ga+8);
    cpa16(sal, gal);      cpa16(sal+16, gal+8);
    const __nv_bfloat16* gb  = Wh + (size_t)(kt*32 + br)*512 + bc;
    const __nv_bfloat16* gbl = Wl + (size_t)(kt*32 + br)*512 + bc;
    uint32_t sb  = base + (uint32_t)(BH_OFF + br*136 + bc)*2;
    uint32_t sbl = base + (uint32_t)(BL_OFF + br*136 + bc)*2;
    cpa16(sb, gb);        cpa16(sb+16, gb+8);
    cpa16(sbl, gbl);      cpa16(sbl+16, gbl+8);
    asm volatile("cp.async.commit_group;\n");
}

__device__ __forceinline__ void mg_compute(uint32_t smb, int buf, int tid,
                                           float (*acc)[8][4]) {
    int l = tid & 31, w = tid >> 5, wm = w & 3, wn = w >> 2;
    int lr = l & 15, lc8 = (l >> 4) << 3;
    uint32_t base = smb + (uint32_t)buf * (BUF_SZ*2);
#pragma unroll
    for (int ks = 0; ks < 32; ks += 16) {
        uint32_t ah[2][4], al[2][4];
#pragma unroll
        for (int fm = 0; fm < 2; fm++) {
            uint32_t aoff = (uint32_t)((wm*32 + fm*16 + lr)*40 + ks + lc8) * 2;
            ldsm4(base + AH_OFF*2 + aoff, ah[fm][0], ah[fm][1], ah[fm][2], ah[fm][3]);
            ldsm4(base + AL_OFF*2 + aoff, al[fm][0], al[fm][1], al[fm][2], al[fm][3]);
        }
#pragma unroll
        for (int fnp = 0; fnp < 4; fnp++) {
            uint32_t boff = (uint32_t)((ks + lr)*136 + wn*64 + fnp*16 + lc8) * 2;
            uint32_t bh[4], bl[4];
            ldsm4t(base + BH_OFF*2 + boff, bh[0], bh[1], bh[2], bh[3]);
            ldsm4t(base + BL_OFF*2 + boff, bl[0], bl[1], bl[2], bl[3]);
#pragma unroll
            for (int fm = 0; fm < 2; fm++) {
                mmabf(acc[fm][fnp*2],   ah[fm], bh[0], bh[1]);
                mmabf(acc[fm][fnp*2],   ah[fm], bl[0], bl[1]);
                mmabf(acc[fm][fnp*2],   al[fm], bh[0], bh[1]);
                mmabf(acc[fm][fnp*2+1], ah[fm], bh[2], bh[3]);
                mmabf(acc[fm][fnp*2+1], ah[fm], bl[2], bl[3]);
                mmabf(acc[fm][fnp*2+1], al[fm], bh[2], bh[3]);
            }
        }
    }
}

template<bool GELU>
__global__ __launch_bounds__(256, 2)
void mgemm(const __nv_bfloat16* __restrict__ Ah, const __nv_bfloat16* __restrict__ Al,
           GemmJob j0, GemmJob j1, GemmJob j2) {
    extern __shared__ __nv_bfloat16 sm[];
    GemmJob jb = (blockIdx.z == 0) ? j0 : ((blockIdx.z == 1) ? j1 : j2);
    int tid = threadIdx.x;
    const __nv_bfloat16* Abh = Ah + (size_t)blockIdx.x * 128 * 512;
    const __nv_bfloat16* Abl = Al + (size_t)blockIdx.x * 128 * 512;
    const __nv_bfloat16* Wbh = jb.Wh + blockIdx.y * 128;
    const __nv_bfloat16* Wbl = jb.Wl + blockIdx.y * 128;
    uint32_t smb = smaddr(sm);

    mg_issue(smb, 0, tid, Abh, Abl, Wbh, Wbl, 0);
    mg_issue(smb, 1, tid, Abh, Abl, Wbh, Wbl, 1);

    float acc[2][8][4] = {};
    for (int kt = 0; kt < 16; kt++) {
        int buf = kt & 1;
        if (kt < 15) asm volatile("cp.async.wait_group 1;\n");
        else         asm volatile("cp.async.wait_group 0;\n");
        __syncthreads();
        mg_compute(smb, buf, tid, acc);
        if (kt < 14) {
            __syncthreads();
            mg_issue(smb, buf, tid, Abh, Abl, Wbh, Wbl, kt+2);
        }
    }

    int l = tid & 31, w = tid >> 5, wm = w & 3, wn = w >> 2;
    int g = l >> 2, t2 = (l & 3) * 2;
    int rowb = blockIdx.x*128 + wm*32;
    int colb = blockIdx.y*128 + wn*64;
#pragma unroll
    for (int fm = 0; fm < 2; fm++) {
#pragma unroll
        for (int fn = 0; fn < 8; fn++) {
            int col = colb + fn*8 + t2;
            float bx0 = jb.bias[col], bx1 = jb.bias[col+1];
            float o0 = acc[fm][fn][0] + bx0, o1 = acc[fm][fn][1] + bx1;
            float o2 = acc[fm][fn][2] + bx0, o3 = acc[fm][fn][3] + bx1;
            if (GELU) {
                o0 = 0.5f*o0*(1.0f + erff(o0*0.70710678118654752f));
                o1 = 0.5f*o1*(1.0f + erff(o1*0.70710678118654752f));
                o2 = 0.5f*o2*(1.0f + erff(o2*0.70710678118654752f));
                o3 = 0.5f*o3*(1.0f + erff(o3*0.70710678118654752f));
            }
            int r0 = rowb + fm*16 + g;
            if (jb.Cf) {
                float2 p0 = {o0, o1}, p1 = {o2, o3};
                *(float2*)(jb.Cf + (size_t)r0*512 + col)     = p0;
                *(float2*)(jb.Cf + (size_t)(r0+8)*512 + col) = p1;
            }
            if (jb.Ch) {
                cvst(o0, o1, jb.Ch + (size_t)r0*512 + col,     jb.Cl + (size_t)r0*512 + col);
                cvst(o2, o3, jb.Ch + (size_t)(r0+8)*512 + col, jb.Cl + (size_t)(r0+8)*512 + col);
            }
        }
    }
}

// ---------------- scores: bf16 planes in, mma QK^T, scale fused -------------
#define SQH 0
#define SQL 9216
#define SKH 18432
#define SKL 27648

__global__ __launch_bounds__(256)
void scores_mma(const __nv_bfloat16* __restrict__ qh, const __nv_bfloat16* __restrict__ ql,
                const __nv_bfloat16* __restrict__ kh, const __nv_bfloat16* __restrict__ kl,
                float* __restrict__ out) {
    extern __shared__ __nv_bfloat16 sm[];
    int tid = threadIdx.x;
    int bhz = blockIdx.z, b = bhz >> 3, hh = bhz & 7;
    int l0 = blockIdx.x * 128, s0 = blockIdx.y * 128;
    int r = tid >> 1, c0 = (tid & 1) * 32;
    {
        size_t qoff = ((size_t)(b*512 + l0 + r))*512 + hh*64 + c0;
        size_t koff = ((size_t)(b*512 + s0 + r))*512 + hh*64 + c0;
        int idx = r*72 + c0;
#pragma unroll
        for (int i = 0; i < 4; i++) {
            *(uint4*)&sm[SQH + idx + i*8] = *(const uint4*)(qh + qoff + i*8);
            *(uint4*)&sm[SQL + idx + i*8] = *(const uint4*)(ql + qoff + i*8);
            *(uint4*)&sm[SKH + idx + i*8] = *(const uint4*)(kh + koff + i*8);
            *(uint4*)&sm[SKL + idx + i*8] = *(const uint4*)(kl + koff + i*8);
        }
    }
    __syncthreads();

    uint32_t smb = smaddr(sm);
    int l = tid & 31, w = tid >> 5, wm = w & 3, wn = w >> 2;
    int lr = l & 15, lc8 = (l >> 4) << 3;
    float acc[2][8][4] = {};
#pragma unroll
    for (int ks = 0; ks < 64; ks += 16) {
        uint32_t ah[2][4], al[2][4];
#pragma unroll
        for (int fm = 0; fm < 2; fm++) {
            uint32_t aoff = (uint32_t)((wm*32 + fm*16 + lr)*72 + ks + lc8) * 2;
            ldsm4(smb + SQH*2 + aoff, ah[fm][0], ah[fm][1], ah[fm][2], ah[fm][3]);
            ldsm4(smb + SQL*2 + aoff, al[fm][0], al[fm][1], al[fm][2], al[fm][3]);
        }
#pragma unroll
        for (int fnp = 0; fnp < 4; fnp++) {
            uint32_t boff = (uint32_t)((wn*64 + fnp*16 + lr)*72 + ks + lc8) * 2;
            uint32_t khr[4], klr[4];
            ldsm4(smb + SKH*2 + boff, khr[0], khr[1], khr[2], khr[3]);
            ldsm4(smb + SKL*2 + boff, klr[0], klr[1], klr[2], klr[3]);
#pragma unroll
            for (int fm = 0; fm < 2; fm++) {
                mmabf(acc[fm][fnp*2],   ah[fm], khr[0], khr[2]);
                mmabf(acc[fm][fnp*2],   ah[fm], klr[0], klr[2]);
                mmabf(acc[fm][fnp*2],   al[fm], khr[0], khr[2]);
                mmabf(acc[fm][fnp*2+1], ah[fm], khr[1], khr[3]);
                mmabf(acc[fm][fnp*2+1], ah[fm], klr[1], klr[3]);
                mmabf(acc[fm][fnp*2+1], al[fm], khr[1], khr[3]);
            }
        }
    }

    int g = l >> 2, t2 = (l & 3) * 2;
    float* ob = out + ((size_t)bhz*512 + l0)*512 + s0;
#pragma unroll
    for (int fm = 0; fm < 2; fm++) {
#pragma unroll
        for (int fn = 0; fn < 8; fn++) {
            int row = wm*32 + fm*16 + g;
            int col = wn*64 + fn*8 + t2;
            float2 p0 = {acc[fm][fn][0]*0.125f, acc[fm][fn][1]*0.125f};
            float2 p1 = {acc[fm][fn][2]*0.125f, acc[fm][fn][3]*0.125f};
            *(float2*)(ob + (size_t)row*512 + col)     = p0;
            *(float2*)(ob + (size_t)(row+8)*512 + col) = p1;
        }
    }
}

// ---------------- sigma projection -----------------------------------------
__global__ void sig_kernel(const float* __restrict__ h, const float* __restrict__ Ws,
                           const float* __restrict__ bs, float* __restrict__ sig) {
    int row = blockIdx.x;
    int warp = threadIdx.x >> 5, lane = threadIdx.x & 31;
    const float* hr = h + (size_t)row*DM;
    float sum = 0.f;
    for (int k2 = lane; k2 < DM; k2 += 32) sum += hr[k2] * Ws[k2*NH + warp];
#pragma unroll
    for (int o = 16; o > 0; o >>= 1) sum += __shfl_xor_sync(0xffffffff, sum, o);
    if (lane == 0) sig[row*NH + warp] = sum + bs[warp];
}

// ---------------- softmax ---------------------------------------------------
__global__ void softmax_kernel(float* __restrict__ data) {
    size_t row = blockIdx.x;
    float* p = data + row*WIN;
    int tid = threadIdx.x;
    float v0 = p[tid];
    float v1 = p[tid + 256];
    __shared__ float red[256];
    red[tid] = fmaxf(v0, v1);
    __syncthreads();
    for (int s = 128; s > 0; s >>= 1) { if (tid < s) red[tid] = fmaxf(red[tid], red[tid+s]); __syncthreads(); }
    float m = red[0];
    __syncthreads();
    float e0 = __expf(v0 - m), e1 = __expf(v1 - m);
    red[tid] = e0 + e1;
    __syncthreads();
    for (int s = 128; s > 0; s >>= 1) { if (tid < s) red[tid] += red[tid+s]; __syncthreads(); }
    float inv = 1.0f / red[0];
    p[tid]       = e0 * inv;
    p[tid + 256] = e1 * inv;
}

// ---------------- prior + sigma ---------------------------------------------
__global__ void prior_kernel(const float* __restrict__ sig,
                             float* __restrict__ prior, float* __restrict__ sigma) {
    int idx = blockIdx.x;
    int l = idx & (WIN-1);
    int bh = idx >> 9;
    int b = bh >> 3, hh = bh & 7;
    float sv = sig[((size_t)b*WIN + l)*NH + hh];
    float sgm = 1.0f/(1.0f + __expf(-5.0f*sv)) + 1e-5f;
    float sg  = __expf(sgm * 1.0986122886681098f) - 1.0f;
    float inv = 0.3989422804014327f / sg;
    float cc  = -1.0f/(2.0f*sg*sg);
    size_t base = ((size_t)bh*WIN + l)*WIN;
    int tid = threadIdx.x;
    for (int s = tid; s < WIN; s += 256) {
        float d = (float)(l - s);
        prior[base + s] = inv * __expf(cc*d*d);
        sigma[base + s] = sg;
    }
}

// ---------------- attn out: S @ V, emits bf16 hi/lo planes ------------------
__global__ __launch_bounds__(128)
void attnv128(const float* __restrict__ series, const float* __restrict__ v,
              __nv_bfloat16* __restrict__ t1h, __nv_bfloat16* __restrict__ t1l) {
    __shared__ float Ss[128*33];
    __shared__ float Vs[32*64];
    int tid = threadIdx.x;
    int bh = blockIdx.y, b = bh >> 3, hh = bh & 7;
    int l0 = blockIdx.x * 128;
    const float* sb = series + ((size_t)bh*512 + l0)*512;
    const float* vb = v + (size_t)b*512*512 + hh*64;
    int tr = tid >> 3, tc = tid & 7;
    int vr = tid >> 2, vc = (tid & 3) * 16;
    float acc[8][8] = {};
    for (int kt = 0; kt < 512; kt += 32) {
#pragma unroll
        for (int c = 0; c < 32; c += 4) {
            float4 s4 = *(const float4*)(sb + (size_t)tid*512 + kt + c);
            Ss[tid*33 + c+0]=s4.x; Ss[tid*33 + c+1]=s4.y;
            Ss[tid*33 + c+2]=s4.z; Ss[tid*33 + c+3]=s4.w;
        }
#pragma unroll
        for (int c = 0; c < 16; c += 4)
            *(float4*)&Vs[vr*64 + vc + c] =
                *(const float4*)(vb + (size_t)(kt+vr)*512 + vc + c);
        __syncthreads();
#pragma unroll
        for (int k2 = 0; k2 < 32; k2++) {
            float rm[8], rn[8];
#pragma unroll
            for (int i = 0; i < 8; i++) rm[i] = Ss[(tr*8+i)*33 + k2];
            *(float4*)&rn[0] = *(float4*)&Vs[k2*64 + tc*8];
            *(float4*)&rn[4] = *(float4*)&Vs[k2*64 + tc*8 + 4];
#pragma unroll
            for (int i = 0; i < 8; i++)
#pragma unroll
                for (int j = 0; j < 8; j++) acc[i][j] += rm[i]*rn[j];
        }
        __syncthreads();
    }
    size_t ob = ((size_t)(b*512 + l0))*512 + hh*64;
#pragma unroll
    for (int i = 0; i < 8; i++) {
        int r = tr*8 + i;
#pragma unroll
        for (int jj = 0; jj < 8; jj += 2) {
            size_t p = ob + (size_t)r*512 + tc*8 + jj;
            cvst(acc[i][jj], acc[i][jj+1], t1h + p, t1l + p);
        }
    }
}

// ---------------- LayerNorm: f32 out + optional bf16 planes -----------------
__global__ void ln_kernel(const float* __restrict__ x, const float* __restrict__ res,
                          const float* __restrict__ g, const float* __restrict__ bb,
                          float* __restrict__ outf,
                          __nv_bfloat16* __restrict__ outh, __nv_bfloat16* __restrict__ outl) {
    size_t row = blockIdx.x;
    int tid = threadIdx.x;
    const float* xr = x + row*DM;
    float v0 = xr[tid], v1 = xr[tid+256];
    if (res) { const float* rr = res + row*DM; v0 += rr[tid]; v1 += rr[tid+256]; }
    __shared__ float red[256];
    red[tid] = v0 + v1;
    __syncthreads();
    for (int s = 128; s > 0; s >>= 1) { if (tid < s) red[tid] += red[tid+s]; __syncthreads(); }
    float mu = red[0] * (1.0f/DM);
    __syncthreads();
    float d0 = v0 - mu, d1 = v1 - mu;
    red[tid] = d0*d0 + d1*d1;
    __syncthreads();
    for (int s = 128; s > 0; s >>= 1) { if (tid < s) red[tid] += red[tid+s]; __syncthreads(); }
    float r = rsqrtf(red[0]*(1.0f/DM) + 1e-3f);
    float y0 = d0*r*g[tid]     + bb[tid];
    float y1 = d1*r*g[tid+256] + bb[tid+256];
    size_t i0 = row*DM + tid, i1 = i0 + 256;
    outf[i0] = y0;
    outf[i1] = y1;
    if (outh) {
        cvst1(y0, outh + i0, outl + i0);
        cvst1(y1, outh + i1, outl + i1);
    }
}

// ---------------- final projection ------------------------------------------
__global__ void proj_kernel(const float* __restrict__ hf, const float* __restrict__ Wp,
                            const float* __restrict__ bp, float* __restrict__ out) {
    int row = blockIdx.x;
    int warp = threadIdx.x >> 5, lane = threadIdx.x & 31;
    const float* hr = hf + (size_t)row*DM;
    for (int c = warp; c < COUT; c += 8) {
        float sum = 0.f;
        for (int k2 = lane; k2 < DM; k2 += 32) sum += hr[k2] * Wp[(size_t)k2*COUT + c];
#pragma unroll
        for (int o = 16; o > 0; o >>= 1) sum += __shfl_xor_sync(0xffffffff, sum, o);
        if (lane == 0) out[(size_t)row*COUT + c] = sum + bp[c];
    }
}

// ---------------- host orchestration ----------------------------------------
extern "C" void kernel_launch(void* const* d_in, const int* in_sizes, int n_in,
                              void* d_out, int out_size) {
    const float* x    = (const float*)d_in[0];
    const float* ck   = (const float*)d_in[1];
    const float* Wq   = (const float*)d_in[2];
    const float* bq   = (const float*)d_in[3];
    const float* Wk   = (const float*)d_in[4];
    const float* bk   = (const float*)d_in[5];
    const float* Wv   = (const float*)d_in[6];
    const float* bv   = (const float*)d_in[7];
    const float* Ws   = (const float*)d_in[8];
    const float* bs   = (const float*)d_in[9];
    const float* Wo   = (const float*)d_in[10];
    const float* bo   = (const float*)d_in[11];
    const float* W1   = (const float*)d_in[12];
    const float* b1   = (const float*)d_in[13];
    const float* W2   = (const float*)d_in[14];
    const float* b2   = (const float*)d_in[15];
    const float* ln1g = (const float*)d_in[16];
    const float* ln1b = (const float*)d_in[17];
    const float* ln2g = (const float*)d_in[18];
    const float* ln2b = (const float*)d_in[19];
    const float* lnfg = (const float*)d_in[20];
    const float* lnfb = (const float*)d_in[21];
    const float* Wp   = (const float*)d_in[22];
    const float* bp   = (const float*)d_in[23];
    float* out = (float*)d_out;

    float *h, *v, *t1, *t2, *sg;
    __nv_bfloat16 *hh, *hl, *qh, *ql, *kh, *kl, *t1h, *t1l, *wh, *wl;
    cudaGetSymbolAddress((void**)&h,   g_h);
    cudaGetSymbolAddress((void**)&v,   g_v);
    cudaGetSymbolAddress((void**)&t1,  g_t1);
    cudaGetSymbolAddress((void**)&t2,  g_t2);
    cudaGetSymbolAddress((void**)&sg,  g_sig);
    cudaGetSymbolAddress((void**)&hh,  g_hh);
    cudaGetSymbolAddress((void**)&hl,  g_hl);
    cudaGetSymbolAddress((void**)&qh,  g_qh);
    cudaGetSymbolAddress((void**)&ql,  g_ql);
    cudaGetSymbolAddress((void**)&kh,  g_kh);
    cudaGetSymbolAddress((void**)&kl,  g_kl);
    cudaGetSymbolAddress((void**)&t1h, g_t1h);
    cudaGetSymbolAddress((void**)&t1l, g_t1l);
    cudaGetSymbolAddress((void**)&wh,  g_wh);
    cudaGetSymbolAddress((void**)&wl,  g_wl);

    cudaFuncSetAttribute(mgemm<false>, cudaFuncAttributeMaxDynamicSharedMemorySize, 75776);
    cudaFuncSetAttribute(mgemm<true>,  cudaFuncAttributeMaxDynamicSharedMemorySize, 75776);
    cudaFuncSetAttribute(scores_mma,   cudaFuncAttributeMaxDynamicSharedMemorySize, 73728);

    wconv_kernel<<<4608, 256>>>(Wq, Wk, Wv, Wo, W1, W2, wh, wl);
    embed_kernel<<<ROWS, DM>>>(x, ck, h, hh, hl);

    dim3 g1(32, 4, 1);
    dim3 g3(32, 4, 3);
    for (int i = 0; i < NL; i++) {
        size_t wbase = (size_t)i*6*262144;
        GemmJob jq = { wh + wbase + 0*262144, wl + wbase + 0*262144, bq + i*DM, nullptr, qh, ql };
        GemmJob jk = { wh + wbase + 1*262144, wl + wbase + 1*262144, bk + i*DM, nullptr, kh, kl };
        GemmJob jv = { wh + wbase + 2*262144, wl + wbase + 2*262144, bv + i*DM, v, nullptr, nullptr };
        GemmJob jo = { wh + wbase + 3*262144, wl + wbase + 3*262144, bo + i*DM, t2, nullptr, nullptr };
        GemmJob jf1 = { wh + wbase + 4*262144, wl + wbase + 4*262144, b1 + i*DM, nullptr, t1h, t1l };
        GemmJob jf2 = { wh + wbase + 5*262144, wl + wbase + 5*262144, b2 + i*DM, t2, nullptr, nullptr };

        mgemm<false><<<g3, 256, 75776>>>(hh, hl, jq, jk, jv);
        sig_kernel<<<ROWS, 256>>>(h, Ws + (size_t)i*DM*NH, bs + i*NH, sg);

        float* ser = out + SERIES_OFF + (size_t)i*LAYER_ELEMS;
        scores_mma<<<dim3(4, 4, BATCH*NH), 256, 73728>>>(qh, ql, kh, kl, ser);
        softmax_kernel<<<BATCH*NH*WIN, 256>>>(ser);
        prior_kernel<<<BATCH*NH*WIN, 256>>>(sg,
                out + PRIOR_OFF + (size_t)i*LAYER_ELEMS,
                out + SIGMA_OFF + (size_t)i*LAYER_ELEMS);

        attnv128<<<dim3(4, BATCH*NH), 128>>>(ser, v, t1h, t1l);
        mgemm<false><<<g1, 256, 75776>>>(t1h, t1l, jo, jo, jo);
        ln_kernel<<<ROWS, 256>>>(h, t2, ln1g + i*DM, ln1b + i*DM, h, hh, hl);

        mgemm<true ><<<g1, 256, 75776>>>(hh, hl, jf1, jf1, jf1);
        mgemm<false><<<g1, 256, 75776>>>(t1h, t1l, jf2, jf2, jf2);
        ln_kernel<<<ROWS, 256>>>(h, t2, ln2g + i*DM, ln2b + i*DM, h, hh, hl);
    }

    ln_kernel<<<ROWS, 256>>>(h, nullptr, lnfg, lnfb, t1, nullptr, nullptr);
    proj_kernel<<<ROWS, 256>>>(t1, Wp, bp, out);
}

// round 5
// speedup vs baseline: 2.3910x; 1.1808x over previous
#include <cuda_runtime.h>
#include <cuda_bf16.h>
#include <math.h>
#include <stdint.h>

#define WIN   512
#define BATCH 8
#define CIN   38
#define COUT  38
#define DM    512
#define NH    8
#define EHD   64
#define NL    3
#define ROWS  (BATCH*WIN)   /* 4096 */

#define OUT_ELEMS    (BATCH*WIN*COUT)
#define LAYER_ELEMS  ((size_t)BATCH*NH*WIN*WIN)
#define SERIES_OFF   ((size_t)OUT_ELEMS)
#define PRIOR_OFF    (SERIES_OFF + 3*LAYER_ELEMS)
#define SIGMA_OFF    (PRIOR_OFF  + 3*LAYER_ELEMS)

// ---------------- scratch ---------------------------------------------------
__device__ float g_h [ROWS*DM];
__device__ float g_v [ROWS*DM];
__device__ float g_t1[ROWS*DM];
__device__ float g_t2[ROWS*DM];
__device__ float g_sig[ROWS*NH];
__device__ __nv_bfloat16 g_hh [ROWS*DM];
__device__ __nv_bfloat16 g_hl [ROWS*DM];
__device__ __nv_bfloat16 g_qh [ROWS*DM];
__device__ __nv_bfloat16 g_ql [ROWS*DM];
__device__ __nv_bfloat16 g_kh [ROWS*DM];
__device__ __nv_bfloat16 g_kl [ROWS*DM];
__device__ __nv_bfloat16 g_t1h[ROWS*DM];
__device__ __nv_bfloat16 g_t1l[ROWS*DM];
__device__ __nv_bfloat16 g_wh [18*262144];
__device__ __nv_bfloat16 g_wl [18*262144];

// ---------------- helpers ---------------------------------------------------
__device__ __forceinline__ uint32_t smaddr(const void* p) {
    return (uint32_t)__cvta_generic_to_shared(p);
}
__device__ __forceinline__ void ldsm4(uint32_t a, uint32_t& r0, uint32_t& r1,
                                      uint32_t& r2, uint32_t& r3) {
    asm volatile("ldmatrix.sync.aligned.m8n8.x4.shared.b16 {%0,%1,%2,%3}, [%4];\n"
                 : "=r"(r0), "=r"(r1), "=r"(r2), "=r"(r3) : "r"(a));
}
__device__ __forceinline__ void ldsm4t(uint32_t a, uint32_t& r0, uint32_t& r1,
                                       uint32_t& r2, uint32_t& r3) {
    asm volatile("ldmatrix.sync.aligned.m8n8.x4.trans.shared.b16 {%0,%1,%2,%3}, [%4];\n"
                 : "=r"(r0), "=r"(r1), "=r"(r2), "=r"(r3) : "r"(a));
}
__device__ __forceinline__ void mmabf(float* d, const uint32_t* a, uint32_t b0, uint32_t b1) {
    asm volatile("mma.sync.aligned.m16n8k16.row.col.f32.bf16.bf16.f32 "
                 "{%0,%1,%2,%3}, {%4,%5,%6,%7}, {%8,%9}, {%0,%1,%2,%3};\n"
                 : "+f"(d[0]), "+f"(d[1]), "+f"(d[2]), "+f"(d[3])
                 : "r"(a[0]), "r"(a[1]), "r"(a[2]), "r"(a[3]), "r"(b0), "r"(b1));
}
__device__ __forceinline__ void cvst(float x, float y, __nv_bfloat16* ph, __nv_bfloat16* pl) {
    __nv_bfloat16 h0 = __float2bfloat16_rn(x);
    __nv_bfloat16 l0 = __float2bfloat16_rn(x - __bfloat162float(h0));
    __nv_bfloat16 h1 = __float2bfloat16_rn(y);
    __nv_bfloat16 l1 = __float2bfloat16_rn(y - __bfloat162float(h1));
    *(__nv_bfloat162*)ph = __halves2bfloat162(h0, h1);
    *(__nv_bfloat162*)pl = __halves2bfloat162(l0, l1);
}
__device__ __forceinline__ void cvst1(float x, __nv_bfloat16* ph, __nv_bfloat16* pl) {
    __nv_bfloat16 h0 = __float2bfloat16_rn(x);
    *ph = h0;
    *pl = __float2bfloat16_rn(x - __bfloat162float(h0));
}
__device__ __forceinline__ void cpa16(uint32_t s, const void* g) {
    asm volatile("cp.async.ca.shared.global [%0], [%1], 16;\n" :: "r"(s), "l"(g));
}

// ---------------- weight pre-conversion -------------------------------------
__global__ void wconv_kernel(const float* __restrict__ Wq, const float* __restrict__ Wk,
                             const float* __restrict__ Wv, const float* __restrict__ Wo,
                             const float* __restrict__ W1, const float* __restrict__ W2,
                             __nv_bfloat16* __restrict__ wh, __nv_bfloat16* __restrict__ wl) {
    size_t j4 = ((size_t)blockIdx.x*256 + threadIdx.x) * 4;
    if (j4 >= 18ull*262144) return;
    size_t uu = j4 >> 18;
    int u = (int)(uu % 6), i = (int)(uu / 6);
    size_t off = j4 & 262143;
    const float* src;
    switch (u) { case 0: src=Wq; break; case 1: src=Wk; break; case 2: src=Wv; break;
                 case 3: src=Wo; break; case 4: src=W1; break; default: src=W2; }
    float4 f = *(const float4*)(src + (size_t)i*262144 + off);
    cvst(f.x, f.y, wh+j4,   wl+j4);
    cvst(f.z, f.w, wh+j4+2, wl+j4+2);
}

// ---------------- embedding -------------------------------------------------
__global__ void embed_kernel(const float* __restrict__ x,
                             const float* __restrict__ ck,
                             float* __restrict__ h,
                             __nv_bfloat16* __restrict__ hh,
                             __nv_bfloat16* __restrict__ hl) {
    int bt = blockIdx.x;
    int b = bt >> 9, t = bt & (WIN-1);
    __shared__ float xs[3*CIN];
    int tid = threadIdx.x;
    if (tid < 3*CIN) {
        int w = tid / CIN, c = tid % CIN;
        int src = (t + w - 1 + WIN) & (WIN-1);
        xs[tid] = x[((size_t)b*WIN + src)*CIN + c];
    }
    __syncthreads();
    int d = tid;
    int i2 = (d >> 1) * 2;
    float ang = (float)t * __expf(-(float)i2 * (9.210340371976184f/512.0f));
    float acc = (d & 1) ? cosf(ang) : sinf(ang);
#pragma unroll 1
    for (int wc = 0; wc < 3*CIN; wc++)
        acc += xs[wc] * ck[(size_t)wc*DM + d];
    size_t idx = (size_t)bt*DM + d;
    h[idx] = acc;
    cvst1(acc, hh + idx, hl + idx);
}

// ---------------- dense GEMM: pure-bf16 in, cp.async pipeline ---------------
struct GemmJob {
    const __nv_bfloat16* Wh; const __nv_bfloat16* Wl;
    const float* bias;
    float* Cf; __nv_bfloat16* Ch; __nv_bfloat16* Cl;
};

#define AH_OFF 0
#define AL_OFF 5120
#define BH_OFF 10240
#define BL_OFF 14592
#define BUF_SZ 18944   /* halves per buffer */

__device__ __forceinline__ void mg_issue(uint32_t smb, int buf, int tid,
        const __nv_bfloat16* Ah, const __nv_bfloat16* Al,
        const __nv_bfloat16* Wh, const __nv_bfloat16* Wl, int kt) {
    int ar = tid >> 1, ac = (tid & 1) * 16;
    int br = tid >> 3, bc = (tid & 7) * 16;
    uint32_t base = smb + (uint32_t)buf * (BUF_SZ*2);
    const __nv_bfloat16* ga  = Ah + (size_t)ar*512 + kt*32 + ac;
    const __nv_bfloat16* gal = Al + (size_t)ar*512 + kt*32 + ac;
    uint32_t sa  = base + (uint32_t)(AH_OFF + ar*40 + ac)*2;
    uint32_t sal = base + (uint32_t)(AL_OFF + ar*40 + ac)*2;
    cpa16(sa, ga);        cpa16(sa+16, ga+8);
    cpa16(sal, gal);      cpa16(sal+16, gal+8);
    const __nv_bfloat16* gb  = Wh + (size_t)(kt*32 + br)*512 + bc;
    const __nv_bfloat16* gbl = Wl + (size_t)(kt*32 + br)*512 + bc;
    uint32_t sb  = base + (uint32_t)(BH_OFF + br*136 + bc)*2;
    uint32_t sbl = base + (uint32_t)(BL_OFF + br*136 + bc)*2;
    cpa16(sb, gb);        cpa16(sb+16, gb+8);
    cpa16(sbl, gbl);      cpa16(sbl+16, gbl+8);
    asm volatile("cp.async.commit_group;\n");
}

__device__ __forceinline__ void mg_compute(uint32_t smb, int buf, int tid,
                                           float (*acc)[8][4]) {
    int l = tid & 31, w = tid >> 5, wm = w & 3, wn = w >> 2;
    int lr = l & 15, lc8 = (l >> 4) << 3;
    uint32_t base = smb + (uint32_t)buf * (BUF_SZ*2);
#pragma unroll
    for (int ks = 0; ks < 32; ks += 16) {
        uint32_t ah[2][4], al[2][4];
#pragma unroll
        for (int fm = 0; fm < 2; fm++) {
            uint32_t aoff = (uint32_t)((wm*32 + fm*16 + lr)*40 + ks + lc8) * 2;
            ldsm4(base + AH_OFF*2 + aoff, ah[fm][0], ah[fm][1], ah[fm][2], ah[fm][3]);
            ldsm4(base + AL_OFF*2 + aoff, al[fm][0], al[fm][1], al[fm][2], al[fm][3]);
        }
#pragma unroll
        for (int fnp = 0; fnp < 4; fnp++) {
            uint32_t boff = (uint32_t)((ks + lr)*136 + wn*64 + fnp*16 + lc8) * 2;
            uint32_t bh[4], bl[4];
            ldsm4t(base + BH_OFF*2 + boff, bh[0], bh[1], bh[2], bh[3]);
            ldsm4t(base + BL_OFF*2 + boff, bl[0], bl[1], bl[2], bl[3]);
#pragma unroll
            for (int fm = 0; fm < 2; fm++) {
                mmabf(acc[fm][fnp*2],   ah[fm], bh[0], bh[1]);
                mmabf(acc[fm][fnp*2],   ah[fm], bl[0], bl[1]);
                mmabf(acc[fm][fnp*2],   al[fm], bh[0], bh[1]);
                mmabf(acc[fm][fnp*2+1], ah[fm], bh[2], bh[3]);
                mmabf(acc[fm][fnp*2+1], ah[fm], bl[2], bl[3]);
                mmabf(acc[fm][fnp*2+1], al[fm], bh[2], bh[3]);
            }
        }
    }
}

template<bool GELU>
__global__ __launch_bounds__(256, 2)
void mgemm(const __nv_bfloat16* __restrict__ Ah, const __nv_bfloat16* __restrict__ Al,
           GemmJob j0, GemmJob j1, GemmJob j2) {
    extern __shared__ __nv_bfloat16 sm[];
    GemmJob jb = (blockIdx.z == 0) ? j0 : ((blockIdx.z == 1) ? j1 : j2);
    int tid = threadIdx.x;
    const __nv_bfloat16* Abh = Ah + (size_t)blockIdx.x * 128 * 512;
    const __nv_bfloat16* Abl = Al + (size_t)blockIdx.x * 128 * 512;
    const __nv_bfloat16* Wbh = jb.Wh + blockIdx.y * 128;
    const __nv_bfloat16* Wbl = jb.Wl + blockIdx.y * 128;
    uint32_t smb = smaddr(sm);

    mg_issue(smb, 0, tid, Abh, Abl, Wbh, Wbl, 0);
    mg_issue(smb, 1, tid, Abh, Abl, Wbh, Wbl, 1);

    float acc[2][8][4] = {};
    for (int kt = 0; kt < 16; kt++) {
        int buf = kt & 1;
        if (kt < 15) asm volatile("cp.async.wait_group 1;\n");
        else         asm volatile("cp.async.wait_group 0;\n");
        __syncthreads();
        mg_compute(smb, buf, tid, acc);
        if (kt < 14) {
            __syncthreads();
            mg_issue(smb, buf, tid, Abh, Abl, Wbh, Wbl, kt+2);
        }
    }

    int l = tid & 31, w = tid >> 5, wm = w & 3, wn = w >> 2;
    int g = l >> 2, t2 = (l & 3) * 2;
    int rowb = blockIdx.x*128 + wm*32;
    int colb = blockIdx.y*128 + wn*64;
#pragma unroll
    for (int fm = 0; fm < 2; fm++) {
#pragma unroll
        for (int fn = 0; fn < 8; fn++) {
            int col = colb + fn*8 + t2;
            float bx0 = jb.bias[col], bx1 = jb.bias[col+1];
            float o0 = acc[fm][fn][0] + bx0, o1 = acc[fm][fn][1] + bx1;
            float o2 = acc[fm][fn][2] + bx0, o3 = acc[fm][fn][3] + bx1;
            if (GELU) {
                o0 = 0.5f*o0*(1.0f + erff(o0*0.70710678118654752f));
                o1 = 0.5f*o1*(1.0f + erff(o1*0.70710678118654752f));
                o2 = 0.5f*o2*(1.0f + erff(o2*0.70710678118654752f));
                o3 = 0.5f*o3*(1.0f + erff(o3*0.70710678118654752f));
            }
            int r0 = rowb + fm*16 + g;
            if (jb.Cf) {
                float2 p0 = {o0, o1}, p1 = {o2, o3};
                *(float2*)(jb.Cf + (size_t)r0*512 + col)     = p0;
                *(float2*)(jb.Cf + (size_t)(r0+8)*512 + col) = p1;
            }
            if (jb.Ch) {
                cvst(o0, o1, jb.Ch + (size_t)r0*512 + col,     jb.Cl + (size_t)r0*512 + col);
                cvst(o2, o3, jb.Ch + (size_t)(r0+8)*512 + col, jb.Cl + (size_t)(r0+8)*512 + col);
            }
        }
    }
}

// ---------------- fused scores + softmax ------------------------------------
// block: 64 q-rows x 512 s-cols, 512 threads (16 warps: 2 m-groups x 8 n-slices)
// smem planes (halves): QH=0, QL=4608, KH=9216, KL=46080, total 82944 (165888 B)
#define FQH 0
#define FQL 4608
#define FKH 9216
#define FKL 46080
#define FS_SMEM 165888

__global__ __launch_bounds__(512)
void fscores(const __nv_bfloat16* __restrict__ qh, const __nv_bfloat16* __restrict__ ql,
             const __nv_bfloat16* __restrict__ kh, const __nv_bfloat16* __restrict__ kl,
             float* __restrict__ out) {
    extern __shared__ __nv_bfloat16 sm[];
    __shared__ float red[64][8];
    int tid = threadIdx.x;
    int bh = blockIdx.y, b = bh >> 3, hhd = bh & 7;
    int l0 = blockIdx.x * 64;

    // load Q strip (64x64) and full K (512x64), hi/lo planes
    {
        int r = tid >> 3, c = (tid & 7) * 8;
        size_t qoff = ((size_t)(b*512 + l0 + r))*512 + hhd*64 + c;
        int qi = r*72 + c;
        *(uint4*)&sm[FQH + qi] = *(const uint4*)(qh + qoff);
        *(uint4*)&sm[FQL + qi] = *(const uint4*)(ql + qoff);
#pragma unroll
        for (int i = 0; i < 8; i++) {
            int kr = r + i*64;
            size_t koff = ((size_t)(b*512 + kr))*512 + hhd*64 + c;
            int ki = kr*72 + c;
            *(uint4*)&sm[FKH + ki] = *(const uint4*)(kh + koff);
            *(uint4*)&sm[FKL + ki] = *(const uint4*)(kl + koff);
        }
    }
    __syncthreads();

    uint32_t smb = smaddr(sm);
    int l = tid & 31, w = tid >> 5;
    int wn = w & 7, wm = w >> 3;
    int lr = l & 15, lc8 = (l >> 4) << 3;
    float acc[2][8][4] = {};
#pragma unroll
    for (int ks = 0; ks < 64; ks += 16) {
        uint32_t ah[2][4], al[2][4];
#pragma unroll
        for (int fm = 0; fm < 2; fm++) {
            uint32_t aoff = (uint32_t)((wm*32 + fm*16 + lr)*72 + ks + lc8) * 2;
            ldsm4(smb + FQH*2 + aoff, ah[fm][0], ah[fm][1], ah[fm][2], ah[fm][3]);
            ldsm4(smb + FQL*2 + aoff, al[fm][0], al[fm][1], al[fm][2], al[fm][3]);
        }
#pragma unroll
        for (int fnp = 0; fnp < 4; fnp++) {
            uint32_t boff = (uint32_t)((wn*64 + fnp*16 + lr)*72 + ks + lc8) * 2;
            uint32_t khr[4], klr[4];
            ldsm4(smb + FKH*2 + boff, khr[0], khr[1], khr[2], khr[3]);
            ldsm4(smb + FKL*2 + boff, klr[0], klr[1], klr[2], klr[3]);
#pragma unroll
            for (int fm = 0; fm < 2; fm++) {
                mmabf(acc[fm][fnp*2],   ah[fm], khr[0], khr[2]);
                mmabf(acc[fm][fnp*2],   ah[fm], klr[0], klr[2]);
                mmabf(acc[fm][fnp*2],   al[fm], khr[0], khr[2]);
                mmabf(acc[fm][fnp*2+1], ah[fm], khr[1], khr[3]);
                mmabf(acc[fm][fnp*2+1], ah[fm], klr[1], klr[3]);
                mmabf(acc[fm][fnp*2+1], al[fm], khr[1], khr[3]);
            }
        }
    }

    // scale
#pragma unroll
    for (int fm = 0; fm < 2; fm++)
#pragma unroll
        for (int fn = 0; fn < 8; fn++)
#pragma unroll
            for (int e = 0; e < 4; e++) acc[fm][fn][e] *= 0.125f;

    int g = l >> 2, t2 = (l & 3) * 2;
    // per-thread rows: r[fm][hf] = wm*32 + fm*16 + g + hf*8
    // ---- max ----
    float tmax[2][2] = {{-1e30f,-1e30f},{-1e30f,-1e30f}};
#pragma unroll
    for (int fm = 0; fm < 2; fm++)
#pragma unroll
        for (int fn = 0; fn < 8; fn++) {
            tmax[fm][0] = fmaxf(tmax[fm][0], fmaxf(acc[fm][fn][0], acc[fm][fn][1]));
            tmax[fm][1] = fmaxf(tmax[fm][1], fmaxf(acc[fm][fn][2], acc[fm][fn][3]));
        }
#pragma unroll
    for (int o = 1; o <= 2; o <<= 1) {
#pragma unroll
        for (int fm = 0; fm < 2; fm++) {
            tmax[fm][0] = fmaxf(tmax[fm][0], __shfl_xor_sync(0xffffffff, tmax[fm][0], o));
            tmax[fm][1] = fmaxf(tmax[fm][1], __shfl_xor_sync(0xffffffff, tmax[fm][1], o));
        }
    }
    if ((l & 3) == 0) {
#pragma unroll
        for (int fm = 0; fm < 2; fm++) {
            red[wm*32 + fm*16 + g][wn]     = tmax[fm][0];
            red[wm*32 + fm*16 + g + 8][wn] = tmax[fm][1];
        }
    }
    __syncthreads();
    float rmax[2][2];
#pragma unroll
    for (int fm = 0; fm < 2; fm++)
#pragma unroll
        for (int hf = 0; hf < 2; hf++) {
            int r = wm*32 + fm*16 + g + hf*8;
            float m = red[r][0];
#pragma unroll
            for (int ww = 1; ww < 8; ww++) m = fmaxf(m, red[r][ww]);
            rmax[fm][hf] = m;
        }
    __syncthreads();

    // ---- exp + sum ----
    float tsum[2][2] = {};
#pragma unroll
    for (int fm = 0; fm < 2; fm++)
#pragma unroll
        for (int fn = 0; fn < 8; fn++) {
            acc[fm][fn][0] = __expf(acc[fm][fn][0] - rmax[fm][0]);
            acc[fm][fn][1] = __expf(acc[fm][fn][1] - rmax[fm][0]);
            acc[fm][fn][2] = __expf(acc[fm][fn][2] - rmax[fm][1]);
            acc[fm][fn][3] = __expf(acc[fm][fn][3] - rmax[fm][1]);
            tsum[fm][0] += acc[fm][fn][0] + acc[fm][fn][1];
            tsum[fm][1] += acc[fm][fn][2] + acc[fm][fn][3];
        }
#pragma unroll
    for (int o = 1; o <= 2; o <<= 1) {
#pragma unroll
        for (int fm = 0; fm < 2; fm++) {
            tsum[fm][0] += __shfl_xor_sync(0xffffffff, tsum[fm][0], o);
            tsum[fm][1] += __shfl_xor_sync(0xffffffff, tsum[fm][1], o);
        }
    }
    if ((l & 3) == 0) {
#pragma unroll
        for (int fm = 0; fm < 2; fm++) {
            red[wm*32 + fm*16 + g][wn]     = tsum[fm][0];
            red[wm*32 + fm*16 + g + 8][wn] = tsum[fm][1];
        }
    }
    __syncthreads();
    float rinv[2][2];
#pragma unroll
    for (int fm = 0; fm < 2; fm++)
#pragma unroll
        for (int hf = 0; hf < 2; hf++) {
            int r = wm*32 + fm*16 + g + hf*8;
            float s = red[r][0];
#pragma unroll
            for (int ww = 1; ww < 8; ww++) s += red[r][ww];
            rinv[fm][hf] = 1.0f / s;
        }

    // ---- write normalized series ----
    float* ob = out + ((size_t)bh*512 + l0)*512;
#pragma unroll
    for (int fm = 0; fm < 2; fm++)
#pragma unroll
        for (int fn = 0; fn < 8; fn++) {
            int row0 = wm*32 + fm*16 + g;
            int col = wn*64 + fn*8 + t2;
            float2 p0 = {acc[fm][fn][0]*rinv[fm][0], acc[fm][fn][1]*rinv[fm][0]};
            float2 p1 = {acc[fm][fn][2]*rinv[fm][1], acc[fm][fn][3]*rinv[fm][1]};
            *(float2*)(ob + (size_t)row0*512 + col)     = p0;
            *(float2*)(ob + (size_t)(row0+8)*512 + col) = p1;
        }
}

// ---------------- sigma projection v2 ---------------------------------------
__global__ __launch_bounds__(256)
void sig2_kernel(const float* __restrict__ h, const float* __restrict__ Ws,
                 const float* __restrict__ bs, float* __restrict__ sig) {
    __shared__ float ws[512*9];
    int tid = threadIdx.x;
    for (int j = tid; j < 4096; j += 256)
        ws[(j >> 3)*9 + (j & 7)] = Ws[j];
    __syncthreads();
    int warp = tid >> 5, lane = tid & 31;
    int row = blockIdx.x*8 + warp;
    const float* hr = h + (size_t)row*512;
    float s[8] = {};
#pragma unroll
    for (int i = 0; i < 16; i++) {
        int k = lane + 32*i;
        float hv = hr[k];
#pragma unroll
        for (int o = 0; o < 8; o++) s[o] += hv * ws[k*9 + o];
    }
#pragma unroll
    for (int off = 16; off > 0; off >>= 1)
#pragma unroll
        for (int o = 0; o < 8; o++) s[o] += __shfl_xor_sync(0xffffffff, s[o], off);
    if (lane < 8) sig[row*8 + lane] = s[lane] + bs[lane];
}

// ---------------- prior + sigma v2 (float4 writes) ---------------------------
__global__ __launch_bounds__(128)
void prior_kernel(const float* __restrict__ sig,
                  float* __restrict__ prior, float* __restrict__ sigma) {
    int idx = blockIdx.x;
    int l = idx & (WIN-1);
    int bh = idx >> 9;
    int b = bh >> 3, hh = bh & 7;
    float sv = sig[((size_t)b*WIN + l)*NH + hh];
    float sgm = 1.0f/(1.0f + __expf(-5.0f*sv)) + 1e-5f;
    float sg  = __expf(sgm * 1.0986122886681098f) - 1.0f;
    float inv = 0.3989422804014327f / sg;
    float cc  = -1.0f/(2.0f*sg*sg);
    size_t base = ((size_t)bh*WIN + l)*WIN;
    int s0 = threadIdx.x * 4;
    float d0 = (float)(l - s0), d1 = d0 - 1.0f, d2 = d0 - 2.0f, d3 = d0 - 3.0f;
    float4 pr;
    pr.x = inv*__expf(cc*d0*d0); pr.y = inv*__expf(cc*d1*d1);
    pr.z = inv*__expf(cc*d2*d2); pr.w = inv*__expf(cc*d3*d3);
    *(float4*)(prior + base + s0) = pr;
    float4 sgv = {sg, sg, sg, sg};
    *(float4*)(sigma + base + s0) = sgv;
}

// ---------------- attn out: S @ V, emits bf16 hi/lo planes ------------------
__global__ __launch_bounds__(128)
void attnv128(const float* __restrict__ series, const float* __restrict__ v,
              __nv_bfloat16* __restrict__ t1h, __nv_bfloat16* __restrict__ t1l) {
    __shared__ float Ss[128*33];
    __shared__ float Vs[32*64];
    int tid = threadIdx.x;
    int bh = blockIdx.y, b = bh >> 3, hh = bh & 7;
    int l0 = blockIdx.x * 128;
    const float* sb = series + ((size_t)bh*512 + l0)*512;
    const float* vb = v + (size_t)b*512*512 + hh*64;
    int tr = tid >> 3, tc = tid & 7;
    int vr = tid >> 2, vc = (tid & 3) * 16;
    float acc[8][8] = {};
    for (int kt = 0; kt < 512; kt += 32) {
#pragma unroll
        for (int c = 0; c < 32; c += 4) {
            float4 s4 = *(const float4*)(sb + (size_t)tid*512 + kt + c);
            Ss[tid*33 + c+0]=s4.x; Ss[tid*33 + c+1]=s4.y;
            Ss[tid*33 + c+2]=s4.z; Ss[tid*33 + c+3]=s4.w;
        }
#pragma unroll
        for (int c = 0; c < 16; c += 4)
            *(float4*)&Vs[vr*64 + vc + c] =
                *(const float4*)(vb + (size_t)(kt+vr)*512 + vc + c);
        __syncthreads();
#pragma unroll
        for (int k2 = 0; k2 < 32; k2++) {
            float rm[8], rn[8];
#pragma unroll
            for (int i = 0; i < 8; i++) rm[i] = Ss[(tr*8+i)*33 + k2];
            *(float4*)&rn[0] = *(float4*)&Vs[k2*64 + tc*8];
            *(float4*)&rn[4] = *(float4*)&Vs[k2*64 + tc*8 + 4];
#pragma unroll
            for (int i = 0; i < 8; i++)
#pragma unroll
                for (int j = 0; j < 8; j++) acc[i][j] += rm[i]*rn[j];
        }
        __syncthreads();
    }
    size_t ob = ((size_t)(b*512 + l0))*512 + hh*64;
#pragma unroll
    for (int i = 0; i < 8; i++) {
        int r = tr*8 + i;
#pragma unroll
        for (int jj = 0; jj < 8; jj += 2) {
            size_t p = ob + (size_t)r*512 + tc*8 + jj;
            cvst(acc[i][jj], acc[i][jj+1], t1h + p, t1l + p);
        }
    }
}

// ---------------- LayerNorm -------------------------------------------------
__global__ void ln_kernel(const float* __restrict__ x, const float* __restrict__ res,
                          const float* __restrict__ g, const float* __restrict__ bb,
                          float* __restrict__ outf,
                          __nv_bfloat16* __restrict__ outh, __nv_bfloat16* __restrict__ outl) {
    size_t row = blockIdx.x;
    int tid = threadIdx.x;
    const float* xr = x + row*DM;
    float v0 = xr[tid], v1 = xr[tid+256];
    if (res) { const float* rr = res + row*DM; v0 += rr[tid]; v1 += rr[tid+256]; }
    __shared__ float red[256];
    red[tid] = v0 + v1;
    __syncthreads();
    for (int s = 128; s > 0; s >>= 1) { if (tid < s) red[tid] += red[tid+s]; __syncthreads(); }
    float mu = red[0] * (1.0f/DM);
    __syncthreads();
    float d0 = v0 - mu, d1 = v1 - mu;
    red[tid] = d0*d0 + d1*d1;
    __syncthreads();
    for (int s = 128; s > 0; s >>= 1) { if (tid < s) red[tid] += red[tid+s]; __syncthreads(); }
    float r = rsqrtf(red[0]*(1.0f/DM) + 1e-3f);
    float y0 = d0*r*g[tid]     + bb[tid];
    float y1 = d1*r*g[tid+256] + bb[tid+256];
    size_t i0 = row*DM + tid, i1 = i0 + 256;
    outf[i0] = y0;
    outf[i1] = y1;
    if (outh) {
        cvst1(y0, outh + i0, outl + i0);
        cvst1(y1, outh + i1, outl + i1);
    }
}

// ---------------- final projection ------------------------------------------
__global__ void proj_kernel(const float* __restrict__ hf, const float* __restrict__ Wp,
                            const float* __restrict__ bp, float* __restrict__ out) {
    int row = blockIdx.x;
    int warp = threadIdx.x >> 5, lane = threadIdx.x & 31;
    const float* hr = hf + (size_t)row*DM;
    for (int c = warp; c < COUT; c += 8) {
        float sum = 0.f;
        for (int k2 = lane; k2 < DM; k2 += 32) sum += hr[k2] * Wp[(size_t)k2*COUT + c];
#pragma unroll
        for (int o = 16; o > 0; o >>= 1) sum += __shfl_xor_sync(0xffffffff, sum, o);
        if (lane == 0) out[(size_t)row*COUT + c] = sum + bp[c];
    }
}

// ---------------- host orchestration ----------------------------------------
extern "C" void kernel_launch(void* const* d_in, const int* in_sizes, int n_in,
                              void* d_out, int out_size) {
    const float* x    = (const float*)d_in[0];
    const float* ck   = (const float*)d_in[1];
    const float* Wq   = (const float*)d_in[2];
    const float* bq   = (const float*)d_in[3];
    const float* Wk   = (const float*)d_in[4];
    const float* bk   = (const float*)d_in[5];
    const float* Wv   = (const float*)d_in[6];
    const float* bv   = (const float*)d_in[7];
    const float* Ws   = (const float*)d_in[8];
    const float* bs   = (const float*)d_in[9];
    const float* Wo   = (const float*)d_in[10];
    const float* bo   = (const float*)d_in[11];
    const float* W1   = (const float*)d_in[12];
    const float* b1   = (const float*)d_in[13];
    const float* W2   = (const float*)d_in[14];
    const float* b2   = (const float*)d_in[15];
    const float* ln1g = (const float*)d_in[16];
    const float* ln1b = (const float*)d_in[17];
    const float* ln2g = (const float*)d_in[18];
    const float* ln2b = (const float*)d_in[19];
    const float* lnfg = (const float*)d_in[20];
    const float* lnfb = (const float*)d_in[21];
    const float* Wp   = (const float*)d_in[22];
    const float* bp   = (const float*)d_in[23];
    float* out = (float*)d_out;

    float *h, *v, *t1, *t2, *sg;
    __nv_bfloat16 *hh, *hl, *qh, *ql, *kh, *kl, *t1h, *t1l, *wh, *wl;
    cudaGetSymbolAddress((void**)&h,   g_h);
    cudaGetSymbolAddress((void**)&v,   g_v);
    cudaGetSymbolAddress((void**)&t1,  g_t1);
    cudaGetSymbolAddress((void**)&t2,  g_t2);
    cudaGetSymbolAddress((void**)&sg,  g_sig);
    cudaGetSymbolAddress((void**)&hh,  g_hh);
    cudaGetSymbolAddress((void**)&hl,  g_hl);
    cudaGetSymbolAddress((void**)&qh,  g_qh);
    cudaGetSymbolAddress((void**)&ql,  g_ql);
    cudaGetSymbolAddress((void**)&kh,  g_kh);
    cudaGetSymbolAddress((void**)&kl,  g_kl);
    cudaGetSymbolAddress((void**)&t1h, g_t1h);
    cudaGetSymbolAddress((void**)&t1l, g_t1l);
    cudaGetSymbolAddress((void**)&wh,  g_wh);
    cudaGetSymbolAddress((void**)&wl,  g_wl);

    cudaFuncSetAttribute(mgemm<false>, cudaFuncAttributeMaxDynamicSharedMemorySize, 75776);
    cudaFuncSetAttribute(mgemm<true>,  cudaFuncAttributeMaxDynamicSharedMemorySize, 75776);
    cudaFuncSetAttribute(fscores,      cudaFuncAttributeMaxDynamicSharedMemorySize, FS_SMEM);

    wconv_kernel<<<4608, 256>>>(Wq, Wk, Wv, Wo, W1, W2, wh, wl);
    embed_kernel<<<ROWS, DM>>>(x, ck, h, hh, hl);

    dim3 g1(32, 4, 1);
    dim3 g3(32, 4, 3);
    for (int i = 0; i < NL; i++) {
        size_t wbase = (size_t)i*6*262144;
        GemmJob jq = { wh + wbase + 0*262144, wl + wbase + 0*262144, bq + i*DM, nullptr, qh, ql };
        GemmJob jk = { wh + wbase + 1*262144, wl + wbase + 1*262144, bk + i*DM, nullptr, kh, kl };
        GemmJob jv = { wh + wbase + 2*262144, wl + wbase + 2*262144, bv + i*DM, v, nullptr, nullptr };
        GemmJob jo = { wh + wbase + 3*262144, wl + wbase + 3*262144, bo + i*DM, t2, nullptr, nullptr };
        GemmJob jf1 = { wh + wbase + 4*262144, wl + wbase + 4*262144, b1 + i*DM, nullptr, t1h, t1l };
        GemmJob jf2 = { wh + wbase + 5*262144, wl + wbase + 5*262144, b2 + i*DM, t2, nullptr, nullptr };

        mgemm<false><<<g3, 256, 75776>>>(hh, hl, jq, jk, jv);
        sig2_kernel<<<ROWS/8, 256>>>(h, Ws + (size_t)i*DM*NH, bs + i*NH, sg);

        float* ser = out + SERIES_OFF + (size_t)i*LAYER_ELEMS;
        fscores<<<dim3(8, 64), 512, FS_SMEM>>>(qh, ql, kh, kl, ser);
        prior_kernel<<<BATCH*NH*WIN, 128>>>(sg,
                out + PRIOR_OFF + (size_t)i*LAYER_ELEMS,
                out + SIGMA_OFF + (size_t)i*LAYER_ELEMS);

        attnv128<<<dim3(4, BATCH*NH), 128>>>(ser, v, t1h, t1l);
        mgemm<false><<<g1, 256, 75776>>>(t1h, t1l, jo, jo, jo);
        ln_kernel<<<ROWS, 256>>>(h, t2, ln1g + i*DM, ln1b + i*DM, h, hh, hl);

        mgemm<true ><<<g1, 256, 75776>>>(hh, hl, jf1, jf1, jf1);
        mgemm<false><<<g1, 256, 75776>>>(t1h, t1l, jf2, jf2, jf2);
        ln_kernel<<<ROWS, 256>>>(h, t2, ln2g + i*DM, ln2b + i*DM, h, hh, hl);
    }

    ln_kernel<<<ROWS, 256>>>(h, nullptr, lnfg, lnfb, t1, nullptr, nullptr);
    proj_kernel<<<ROWS, 256>>>(t1, Wp, bp, out);
}

// round 6
// speedup vs baseline: 2.5992x; 1.0871x over previous
#include <cuda_runtime.h>
#include <cuda_bf16.h>
#include <math.h>
#include <stdint.h>

#define WIN   512
#define BATCH 8
#define CIN   38
#define COUT  38
#define DM    512
#define NH    8
#define EHD   64
#define NL    3
#define ROWS  (BATCH*WIN)   /* 4096 */

#define OUT_ELEMS    (BATCH*WIN*COUT)
#define LAYER_ELEMS  ((size_t)BATCH*NH*WIN*WIN)
#define SERIES_OFF   ((size_t)OUT_ELEMS)
#define PRIOR_OFF    (SERIES_OFF + 3*LAYER_ELEMS)
#define SIGMA_OFF    (PRIOR_OFF  + 3*LAYER_ELEMS)

// ---------------- scratch ---------------------------------------------------
__device__ float g_h [ROWS*DM];
__device__ float g_t1[ROWS*DM];
__device__ float g_t2[ROWS*DM];
__device__ float g_sig[ROWS*NH];
__device__ __nv_bfloat16 g_hh [ROWS*DM];
__device__ __nv_bfloat16 g_hl [ROWS*DM];
__device__ __nv_bfloat16 g_qh [ROWS*DM];
__device__ __nv_bfloat16 g_ql [ROWS*DM];
__device__ __nv_bfloat16 g_kh [ROWS*DM];
__device__ __nv_bfloat16 g_kl [ROWS*DM];
__device__ __nv_bfloat16 g_vh [ROWS*DM];
__device__ __nv_bfloat16 g_vl [ROWS*DM];
__device__ __nv_bfloat16 g_t1h[ROWS*DM];
__device__ __nv_bfloat16 g_t1l[ROWS*DM];
__device__ __nv_bfloat16 g_wh [18*262144];
__device__ __nv_bfloat16 g_wl [18*262144];

// ---------------- helpers ---------------------------------------------------
__device__ __forceinline__ uint32_t smaddr(const void* p) {
    return (uint32_t)__cvta_generic_to_shared(p);
}
__device__ __forceinline__ void ldsm4(uint32_t a, uint32_t& r0, uint32_t& r1,
                                      uint32_t& r2, uint32_t& r3) {
    asm volatile("ldmatrix.sync.aligned.m8n8.x4.shared.b16 {%0,%1,%2,%3}, [%4];\n"
                 : "=r"(r0), "=r"(r1), "=r"(r2), "=r"(r3) : "r"(a));
}
__device__ __forceinline__ void ldsm4t(uint32_t a, uint32_t& r0, uint32_t& r1,
                                       uint32_t& r2, uint32_t& r3) {
    asm volatile("ldmatrix.sync.aligned.m8n8.x4.trans.shared.b16 {%0,%1,%2,%3}, [%4];\n"
                 : "=r"(r0), "=r"(r1), "=r"(r2), "=r"(r3) : "r"(a));
}
__device__ __forceinline__ void ldsm2t(uint32_t a, uint32_t& r0, uint32_t& r1) {
    asm volatile("ldmatrix.sync.aligned.m8n8.x2.trans.shared.b16 {%0,%1}, [%2];\n"
                 : "=r"(r0), "=r"(r1) : "r"(a));
}
__device__ __forceinline__ void mmabf(float* d, const uint32_t* a, uint32_t b0, uint32_t b1) {
    asm volatile("mma.sync.aligned.m16n8k16.row.col.f32.bf16.bf16.f32 "
                 "{%0,%1,%2,%3}, {%4,%5,%6,%7}, {%8,%9}, {%0,%1,%2,%3};\n"
                 : "+f"(d[0]), "+f"(d[1]), "+f"(d[2]), "+f"(d[3])
                 : "r"(a[0]), "r"(a[1]), "r"(a[2]), "r"(a[3]), "r"(b0), "r"(b1));
}
__device__ __forceinline__ void cvst(float x, float y, __nv_bfloat16* ph, __nv_bfloat16* pl) {
    __nv_bfloat16 h0 = __float2bfloat16_rn(x);
    __nv_bfloat16 l0 = __float2bfloat16_rn(x - __bfloat162float(h0));
    __nv_bfloat16 h1 = __float2bfloat16_rn(y);
    __nv_bfloat16 l1 = __float2bfloat16_rn(y - __bfloat162float(h1));
    *(__nv_bfloat162*)ph = __halves2bfloat162(h0, h1);
    *(__nv_bfloat162*)pl = __halves2bfloat162(l0, l1);
}
__device__ __forceinline__ void cvst1(float x, __nv_bfloat16* ph, __nv_bfloat16* pl) {
    __nv_bfloat16 h0 = __float2bfloat16_rn(x);
    *ph = h0;
    *pl = __float2bfloat16_rn(x - __bfloat162float(h0));
}
__device__ __forceinline__ void cpa16(uint32_t s, const void* g) {
    asm volatile("cp.async.ca.shared.global [%0], [%1], 16;\n" :: "r"(s), "l"(g));
}

// ---------------- weight pre-conversion -------------------------------------
__global__ void wconv_kernel(const float* __restrict__ Wq, const float* __restrict__ Wk,
                             const float* __restrict__ Wv, const float* __restrict__ Wo,
                             const float* __restrict__ W1, const float* __restrict__ W2,
                             __nv_bfloat16* __restrict__ wh, __nv_bfloat16* __restrict__ wl) {
    size_t j4 = ((size_t)blockIdx.x*256 + threadIdx.x) * 4;
    if (j4 >= 18ull*262144) return;
    size_t uu = j4 >> 18;
    int u = (int)(uu % 6), i = (int)(uu / 6);
    size_t off = j4 & 262143;
    const float* src;
    switch (u) { case 0: src=Wq; break; case 1: src=Wk; break; case 2: src=Wv; break;
                 case 3: src=Wo; break; case 4: src=W1; break; default: src=W2; }
    float4 f = *(const float4*)(src + (size_t)i*262144 + off);
    cvst(f.x, f.y, wh+j4,   wl+j4);
    cvst(f.z, f.w, wh+j4+2, wl+j4+2);
}

// ---------------- embedding -------------------------------------------------
__global__ void embed_kernel(const float* __restrict__ x,
                             const float* __restrict__ ck,
                             float* __restrict__ h,
                             __nv_bfloat16* __restrict__ hh,
                             __nv_bfloat16* __restrict__ hl) {
    int bt = blockIdx.x;
    int b = bt >> 9, t = bt & (WIN-1);
    __shared__ float xs[3*CIN];
    int tid = threadIdx.x;
    if (tid < 3*CIN) {
        int w = tid / CIN, c = tid % CIN;
        int src = (t + w - 1 + WIN) & (WIN-1);
        xs[tid] = x[((size_t)b*WIN + src)*CIN + c];
    }
    __syncthreads();
    int d = tid;
    int i2 = (d >> 1) * 2;
    float ang = (float)t * __expf(-(float)i2 * (9.210340371976184f/512.0f));
    float acc = (d & 1) ? cosf(ang) : sinf(ang);
#pragma unroll 1
    for (int wc = 0; wc < 3*CIN; wc++)
        acc += xs[wc] * ck[(size_t)wc*DM + d];
    size_t idx = (size_t)bt*DM + d;
    h[idx] = acc;
    cvst1(acc, hh + idx, hl + idx);
}

// ---------------- dense GEMM: pure-bf16 in, cp.async pipeline ---------------
struct GemmJob {
    const __nv_bfloat16* Wh; const __nv_bfloat16* Wl;
    const float* bias;
    float* Cf; __nv_bfloat16* Ch; __nv_bfloat16* Cl;
};

#define AH_OFF 0
#define AL_OFF 5120
#define BH_OFF 10240
#define BL_OFF 14592
#define BUF_SZ 18944   /* halves per buffer */

__device__ __forceinline__ void mg_issue(uint32_t smb, int buf, int tid,
        const __nv_bfloat16* Ah, const __nv_bfloat16* Al,
        const __nv_bfloat16* Wh, const __nv_bfloat16* Wl, int kt) {
    int ar = tid >> 1, ac = (tid & 1) * 16;
    int br = tid >> 3, bc = (tid & 7) * 16;
    uint32_t base = smb + (uint32_t)buf * (BUF_SZ*2);
    const __nv_bfloat16* ga  = Ah + (size_t)ar*512 + kt*32 + ac;
    const __nv_bfloat16* gal = Al + (size_t)ar*512 + kt*32 + ac;
    uint32_t sa  = base + (uint32_t)(AH_OFF + ar*40 + ac)*2;
    uint32_t sal = base + (uint32_t)(AL_OFF + ar*40 + ac)*2;
    cpa16(sa, ga);        cpa16(sa+16, ga+8);
    cpa16(sal, gal);      cpa16(sal+16, gal+8);
    const __nv_bfloat16* gb  = Wh + (size_t)(kt*32 + br)*512 + bc;
    const __nv_bfloat16* gbl = Wl + (size_t)(kt*32 + br)*512 + bc;
    uint32_t sb  = base + (uint32_t)(BH_OFF + br*136 + bc)*2;
    uint32_t sbl = base + (uint32_t)(BL_OFF + br*136 + bc)*2;
    cpa16(sb, gb);        cpa16(sb+16, gb+8);
    cpa16(sbl, gbl);      cpa16(sbl+16, gbl+8);
    asm volatile("cp.async.commit_group;\n");
}

__device__ __forceinline__ void mg_compute(uint32_t smb, int buf, int tid,
                                           float (*acc)[8][4]) {
    int l = tid & 31, w = tid >> 5, wm = w & 3, wn = w >> 2;
    int lr = l & 15, lc8 = (l >> 4) << 3;
    uint32_t base = smb + (uint32_t)buf * (BUF_SZ*2);
#pragma unroll
    for (int ks = 0; ks < 32; ks += 16) {
        uint32_t ah[2][4], al[2][4];
#pragma unroll
        for (int fm = 0; fm < 2; fm++) {
            uint32_t aoff = (uint32_t)((wm*32 + fm*16 + lr)*40 + ks + lc8) * 2;
            ldsm4(base + AH_OFF*2 + aoff, ah[fm][0], ah[fm][1], ah[fm][2], ah[fm][3]);
            ldsm4(base + AL_OFF*2 + aoff, al[fm][0], al[fm][1], al[fm][2], al[fm][3]);
        }
#pragma unroll
        for (int fnp = 0; fnp < 4; fnp++) {
            uint32_t boff = (uint32_t)((ks + lr)*136 + wn*64 + fnp*16 + lc8) * 2;
            uint32_t bh[4], bl[4];
            ldsm4t(base + BH_OFF*2 + boff, bh[0], bh[1], bh[2], bh[3]);
            ldsm4t(base + BL_OFF*2 + boff, bl[0], bl[1], bl[2], bl[3]);
#pragma unroll
            for (int fm = 0; fm < 2; fm++) {
                mmabf(acc[fm][fnp*2],   ah[fm], bh[0], bh[1]);
                mmabf(acc[fm][fnp*2],   ah[fm], bl[0], bl[1]);
                mmabf(acc[fm][fnp*2],   al[fm], bh[0], bh[1]);
                mmabf(acc[fm][fnp*2+1], ah[fm], bh[2], bh[3]);
                mmabf(acc[fm][fnp*2+1], ah[fm], bl[2], bl[3]);
                mmabf(acc[fm][fnp*2+1], al[fm], bh[2], bh[3]);
            }
        }
    }
}

template<bool GELU>
__global__ __launch_bounds__(256, 2)
void mgemm(const __nv_bfloat16* __restrict__ Ah, const __nv_bfloat16* __restrict__ Al,
           GemmJob j0, GemmJob j1, GemmJob j2) {
    extern __shared__ __nv_bfloat16 sm[];
    GemmJob jb = (blockIdx.z == 0) ? j0 : ((blockIdx.z == 1) ? j1 : j2);
    int tid = threadIdx.x;
    const __nv_bfloat16* Abh = Ah + (size_t)blockIdx.x * 128 * 512;
    const __nv_bfloat16* Abl = Al + (size_t)blockIdx.x * 128 * 512;
    const __nv_bfloat16* Wbh = jb.Wh + blockIdx.y * 128;
    const __nv_bfloat16* Wbl = jb.Wl + blockIdx.y * 128;
    uint32_t smb = smaddr(sm);

    mg_issue(smb, 0, tid, Abh, Abl, Wbh, Wbl, 0);
    mg_issue(smb, 1, tid, Abh, Abl, Wbh, Wbl, 1);

    float acc[2][8][4] = {};
    for (int kt = 0; kt < 16; kt++) {
        int buf = kt & 1;
        if (kt < 15) asm volatile("cp.async.wait_group 1;\n");
        else         asm volatile("cp.async.wait_group 0;\n");
        __syncthreads();
        mg_compute(smb, buf, tid, acc);
        if (kt < 14) {
            __syncthreads();
            mg_issue(smb, buf, tid, Abh, Abl, Wbh, Wbl, kt+2);
        }
    }

    int l = tid & 31, w = tid >> 5, wm = w & 3, wn = w >> 2;
    int g = l >> 2, t2 = (l & 3) * 2;
    int rowb = blockIdx.x*128 + wm*32;
    int colb = blockIdx.y*128 + wn*64;
#pragma unroll
    for (int fm = 0; fm < 2; fm++) {
#pragma unroll
        for (int fn = 0; fn < 8; fn++) {
            int col = colb + fn*8 + t2;
            float bx0 = jb.bias[col], bx1 = jb.bias[col+1];
            float o0 = acc[fm][fn][0] + bx0, o1 = acc[fm][fn][1] + bx1;
            float o2 = acc[fm][fn][2] + bx0, o3 = acc[fm][fn][3] + bx1;
            if (GELU) {
                o0 = 0.5f*o0*(1.0f + erff(o0*0.70710678118654752f));
                o1 = 0.5f*o1*(1.0f + erff(o1*0.70710678118654752f));
                o2 = 0.5f*o2*(1.0f + erff(o2*0.70710678118654752f));
                o3 = 0.5f*o3*(1.0f + erff(o3*0.70710678118654752f));
            }
            int r0 = rowb + fm*16 + g;
            if (jb.Cf) {
                float2 p0 = {o0, o1}, p1 = {o2, o3};
                *(float2*)(jb.Cf + (size_t)r0*512 + col)     = p0;
                *(float2*)(jb.Cf + (size_t)(r0+8)*512 + col) = p1;
            }
            if (jb.Ch) {
                cvst(o0, o1, jb.Ch + (size_t)r0*512 + col,     jb.Cl + (size_t)r0*512 + col);
                cvst(o2, o3, jb.Ch + (size_t)(r0+8)*512 + col, jb.Cl + (size_t)(r0+8)*512 + col);
            }
        }
    }
}

// ---------------- fused scores + softmax + S@V ------------------------------
// block: 64 q-rows x 512 s-cols, 512 threads (16 warps: 2 m-groups x 8 n-slices)
// phase1 planes (halves): QH=0, QL=4608, KH=9216, KL=46080
// phase2 planes reuse:    VH=0, VL=4608, SH=9216 (64x520), SL=42496
#define FQH 0
#define FQL 4608
#define FKH 9216
#define FKL 46080
#define FVH 0
#define FVL 4608
#define FSH 9216
#define FSL 42496
#define FS_SMEM 165888

__global__ __launch_bounds__(512)
void fscores(const __nv_bfloat16* __restrict__ qh, const __nv_bfloat16* __restrict__ ql,
             const __nv_bfloat16* __restrict__ kh, const __nv_bfloat16* __restrict__ kl,
             const __nv_bfloat16* __restrict__ vh, const __nv_bfloat16* __restrict__ vl,
             float* __restrict__ out,
             __nv_bfloat16* __restrict__ t1h, __nv_bfloat16* __restrict__ t1l) {
    extern __shared__ __nv_bfloat16 sm[];
    __shared__ float red[64][8];
    int tid = threadIdx.x;
    int bh = blockIdx.y, b = bh >> 3, hhd = bh & 7;
    int l0 = blockIdx.x * 64;

    // load Q strip (64x64) and full K (512x64), hi/lo planes
    {
        int r = tid >> 3, c = (tid & 7) * 8;
        size_t qoff = ((size_t)(b*512 + l0 + r))*512 + hhd*64 + c;
        int qi = r*72 + c;
        *(uint4*)&sm[FQH + qi] = *(const uint4*)(qh + qoff);
        *(uint4*)&sm[FQL + qi] = *(const uint4*)(ql + qoff);
#pragma unroll
        for (int i = 0; i < 8; i++) {
            int kr = r + i*64;
            size_t koff = ((size_t)(b*512 + kr))*512 + hhd*64 + c;
            int ki = kr*72 + c;
            *(uint4*)&sm[FKH + ki] = *(const uint4*)(kh + koff);
            *(uint4*)&sm[FKL + ki] = *(const uint4*)(kl + koff);
        }
    }
    __syncthreads();

    uint32_t smb = smaddr(sm);
    int l = tid & 31, w = tid >> 5;
    int wn = w & 7, wm = w >> 3;
    int lr = l & 15, lc8 = (l >> 4) << 3;
    float acc[2][8][4] = {};
#pragma unroll
    for (int ks = 0; ks < 64; ks += 16) {
        uint32_t ah[2][4], al[2][4];
#pragma unroll
        for (int fm = 0; fm < 2; fm++) {
            uint32_t aoff = (uint32_t)((wm*32 + fm*16 + lr)*72 + ks + lc8) * 2;
            ldsm4(smb + FQH*2 + aoff, ah[fm][0], ah[fm][1], ah[fm][2], ah[fm][3]);
            ldsm4(smb + FQL*2 + aoff, al[fm][0], al[fm][1], al[fm][2], al[fm][3]);
        }
#pragma unroll
        for (int fnp = 0; fnp < 4; fnp++) {
            uint32_t boff = (uint32_t)((wn*64 + fnp*16 + lr)*72 + ks + lc8) * 2;
            uint32_t khr[4], klr[4];
            ldsm4(smb + FKH*2 + boff, khr[0], khr[1], khr[2], khr[3]);
            ldsm4(smb + FKL*2 + boff, klr[0], klr[1], klr[2], klr[3]);
#pragma unroll
            for (int fm = 0; fm < 2; fm++) {
                mmabf(acc[fm][fnp*2],   ah[fm], khr[0], khr[2]);
                mmabf(acc[fm][fnp*2],   ah[fm], klr[0], klr[2]);
                mmabf(acc[fm][fnp*2],   al[fm], khr[0], khr[2]);
                mmabf(acc[fm][fnp*2+1], ah[fm], khr[1], khr[3]);
                mmabf(acc[fm][fnp*2+1], ah[fm], klr[1], klr[3]);
                mmabf(acc[fm][fnp*2+1], al[fm], khr[1], khr[3]);
            }
        }
    }

    // scale
#pragma unroll
    for (int fm = 0; fm < 2; fm++)
#pragma unroll
        for (int fn = 0; fn < 8; fn++)
#pragma unroll
            for (int e = 0; e < 4; e++) acc[fm][fn][e] *= 0.125f;

    int g = l >> 2, t2 = (l & 3) * 2;
    // ---- max ----
    float tmax[2][2] = {{-1e30f,-1e30f},{-1e30f,-1e30f}};
#pragma unroll
    for (int fm = 0; fm < 2; fm++)
#pragma unroll
        for (int fn = 0; fn < 8; fn++) {
            tmax[fm][0] = fmaxf(tmax[fm][0], fmaxf(acc[fm][fn][0], acc[fm][fn][1]));
            tmax[fm][1] = fmaxf(tmax[fm][1], fmaxf(acc[fm][fn][2], acc[fm][fn][3]));
        }
#pragma unroll
    for (int o = 1; o <= 2; o <<= 1) {
#pragma unroll
        for (int fm = 0; fm < 2; fm++) {
            tmax[fm][0] = fmaxf(tmax[fm][0], __shfl_xor_sync(0xffffffff, tmax[fm][0], o));
            tmax[fm][1] = fmaxf(tmax[fm][1], __shfl_xor_sync(0xffffffff, tmax[fm][1], o));
        }
    }
    if ((l & 3) == 0) {
#pragma unroll
        for (int fm = 0; fm < 2; fm++) {
            red[wm*32 + fm*16 + g][wn]     = tmax[fm][0];
            red[wm*32 + fm*16 + g + 8][wn] = tmax[fm][1];
        }
    }
    __syncthreads();
    float rmax[2][2];
#pragma unroll
    for (int fm = 0; fm < 2; fm++)
#pragma unroll
        for (int hf = 0; hf < 2; hf++) {
            int r = wm*32 + fm*16 + g + hf*8;
            float m = red[r][0];
#pragma unroll
            for (int ww = 1; ww < 8; ww++) m = fmaxf(m, red[r][ww]);
            rmax[fm][hf] = m;
        }
    __syncthreads();

    // ---- exp + sum ----
    float tsum[2][2] = {};
#pragma unroll
    for (int fm = 0; fm < 2; fm++)
#pragma unroll
        for (int fn = 0; fn < 8; fn++) {
            acc[fm][fn][0] = __expf(acc[fm][fn][0] - rmax[fm][0]);
            acc[fm][fn][1] = __expf(acc[fm][fn][1] - rmax[fm][0]);
            acc[fm][fn][2] = __expf(acc[fm][fn][2] - rmax[fm][1]);
            acc[fm][fn][3] = __expf(acc[fm][fn][3] - rmax[fm][1]);
            tsum[fm][0] += acc[fm][fn][0] + acc[fm][fn][1];
            tsum[fm][1] += acc[fm][fn][2] + acc[fm][fn][3];
        }
#pragma unroll
    for (int o = 1; o <= 2; o <<= 1) {
#pragma unroll
        for (int fm = 0; fm < 2; fm++) {
            tsum[fm][0] += __shfl_xor_sync(0xffffffff, tsum[fm][0], o);
            tsum[fm][1] += __shfl_xor_sync(0xffffffff, tsum[fm][1], o);
        }
    }
    if ((l & 3) == 0) {
#pragma unroll
        for (int fm = 0; fm < 2; fm++) {
            red[wm*32 + fm*16 + g][wn]     = tsum[fm][0];
            red[wm*32 + fm*16 + g + 8][wn] = tsum[fm][1];
        }
    }
    __syncthreads();
    float rinv[2][2];
#pragma unroll
    for (int fm = 0; fm < 2; fm++)
#pragma unroll
        for (int hf = 0; hf < 2; hf++) {
            int r = wm*32 + fm*16 + g + hf*8;
            float s = red[r][0];
#pragma unroll
            for (int ww = 1; ww < 8; ww++) s += red[r][ww];
            rinv[fm][hf] = 1.0f / s;
        }

    // ---- normalize: write series to gmem AND bf16 hi/lo planes to smem ----
    float* ob = out + ((size_t)bh*512 + l0)*512;
#pragma unroll
    for (int fm = 0; fm < 2; fm++)
#pragma unroll
        for (int fn = 0; fn < 8; fn++) {
            int row0 = wm*32 + fm*16 + g;
            int col = wn*64 + fn*8 + t2;
            float s0 = acc[fm][fn][0]*rinv[fm][0], s1 = acc[fm][fn][1]*rinv[fm][0];
            float s2 = acc[fm][fn][2]*rinv[fm][1], s3 = acc[fm][fn][3]*rinv[fm][1];
            float2 p0 = {s0, s1}, p1 = {s2, s3};
            *(float2*)(ob + (size_t)row0*512 + col)     = p0;
            *(float2*)(ob + (size_t)(row0+8)*512 + col) = p1;
            cvst(s0, s1, &sm[FSH + row0*520 + col],     &sm[FSL + row0*520 + col]);
            cvst(s2, s3, &sm[FSH + (row0+8)*520 + col], &sm[FSL + (row0+8)*520 + col]);
        }
    __syncthreads();

    // ---- AV: S[64,512] @ V[512,64] via mma, V streamed in 64-row chunks ----
    float acc2[2][4] = {};
    for (int kc = 0; kc < 8; kc++) {
        {
            int r = tid >> 3, c = (tid & 7) * 8;
            size_t voff = ((size_t)(b*512 + kc*64 + r))*512 + hhd*64 + c;
            *(uint4*)&sm[FVH + r*72 + c] = *(const uint4*)(vh + voff);
            *(uint4*)&sm[FVL + r*72 + c] = *(const uint4*)(vl + voff);
        }
        __syncthreads();
#pragma unroll
        for (int ks = 0; ks < 64; ks += 16) {
            uint32_t sa[2][4], sl2[2][4];
#pragma unroll
            for (int fm = 0; fm < 2; fm++) {
                uint32_t aoff = (uint32_t)((wm*32 + fm*16 + lr)*520 + kc*64 + ks + lc8) * 2;
                ldsm4(smb + FSH*2 + aoff, sa[fm][0], sa[fm][1], sa[fm][2], sa[fm][3]);
                ldsm4(smb + FSL*2 + aoff, sl2[fm][0], sl2[fm][1], sl2[fm][2], sl2[fm][3]);
            }
            uint32_t boff = (uint32_t)((ks + lr)*72 + wn*8) * 2;
            uint32_t bh2[2], bl2[2];
            ldsm2t(smb + FVH*2 + boff, bh2[0], bh2[1]);
            ldsm2t(smb + FVL*2 + boff, bl2[0], bl2[1]);
#pragma unroll
            for (int fm = 0; fm < 2; fm++) {
                mmabf(acc2[fm], sa[fm],  bh2[0], bh2[1]);
                mmabf(acc2[fm], sa[fm],  bl2[0], bl2[1]);
                mmabf(acc2[fm], sl2[fm], bh2[0], bh2[1]);
            }
        }
        if (kc < 7) __syncthreads();
    }

    // write attn-out tile as bf16 hi/lo planes
#pragma unroll
    for (int fm = 0; fm < 2; fm++) {
        int row0 = wm*32 + fm*16 + g;
        int col = wn*8 + t2;
        size_t p0 = ((size_t)(b*512 + l0 + row0))*512 + hhd*64 + col;
        size_t p1 = ((size_t)(b*512 + l0 + row0 + 8))*512 + hhd*64 + col;
        cvst(acc2[fm][0], acc2[fm][1], t1h + p0, t1l + p0);
        cvst(acc2[fm][2], acc2[fm][3], t1h + p1, t1l + p1);
    }
}

// ---------------- sigma projection v3: 64 rows/block, Ws loaded once --------
__global__ __launch_bounds__(512)
void sig3_kernel(const float* __restrict__ h, const float* __restrict__ Ws,
                 const float* __restrict__ bs, float* __restrict__ sig) {
    __shared__ float ws[512*9];
    int tid = threadIdx.x;
    for (int j = tid; j < 4096; j += 512)
        ws[(j >> 3)*9 + (j & 7)] = Ws[j];
    __syncthreads();
    int warp = tid >> 5, lane = tid & 31;
#pragma unroll
    for (int rr = 0; rr < 4; rr++) {
        int row = blockIdx.x*64 + warp*4 + rr;
        const float* hr = h + (size_t)row*512;
        float s[8] = {};
#pragma unroll
        for (int i = 0; i < 16; i++) {
            int k = lane + 32*i;
            float hv = hr[k];
#pragma unroll
            for (int o = 0; o < 8; o++) s[o] += hv * ws[k*9 + o];
        }
#pragma unroll
        for (int off = 16; off > 0; off >>= 1)
#pragma unroll
            for (int o = 0; o < 8; o++) s[o] += __shfl_xor_sync(0xffffffff, s[o], off);
        if (lane < 8) sig[row*8 + lane] = s[lane] + bs[lane];
    }
}

// ---------------- prior + sigma (float4 writes) ------------------------------
__global__ __launch_bounds__(128)
void prior_kernel(const float* __restrict__ sig,
                  float* __restrict__ prior, float* __restrict__ sigma) {
    int idx = blockIdx.x;
    int l = idx & (WIN-1);
    int bh = idx >> 9;
    int b = bh >> 3, hh = bh & 7;
    float sv = sig[((size_t)b*WIN + l)*NH + hh];
    float sgm = 1.0f/(1.0f + __expf(-5.0f*sv)) + 1e-5f;
    float sg  = __expf(sgm * 1.0986122886681098f) - 1.0f;
    float inv = 0.3989422804014327f / sg;
    float cc  = -1.0f/(2.0f*sg*sg);
    size_t base = ((size_t)bh*WIN + l)*WIN;
    int s0 = threadIdx.x * 4;
    float d0 = (float)(l - s0), d1 = d0 - 1.0f, d2 = d0 - 2.0f, d3 = d0 - 3.0f;
    float4 pr;
    pr.x = inv*__expf(cc*d0*d0); pr.y = inv*__expf(cc*d1*d1);
    pr.z = inv*__expf(cc*d2*d2); pr.w = inv*__expf(cc*d3*d3);
    *(float4*)(prior + base + s0) = pr;
    float4 sgv = {sg, sg, sg, sg};
    *(float4*)(sigma + base + s0) = sgv;
}

// ---------------- LayerNorm -------------------------------------------------
__global__ void ln_kernel(const float* __restrict__ x, const float* __restrict__ res,
                          const float* __restrict__ g, const float* __restrict__ bb,
                          float* __restrict__ outf,
                          __nv_bfloat16* __restrict__ outh, __nv_bfloat16* __restrict__ outl) {
    size_t row = blockIdx.x;
    int tid = threadIdx.x;
    const float* xr = x + row*DM;
    float v0 = xr[tid], v1 = xr[tid+256];
    if (res) { const float* rr = res + row*DM; v0 += rr[tid]; v1 += rr[tid+256]; }
    __shared__ float red[256];
    red[tid] = v0 + v1;
    __syncthreads();
    for (int s = 128; s > 0; s >>= 1) { if (tid < s) red[tid] += red[tid+s]; __syncthreads(); }
    float mu = red[0] * (1.0f/DM);
    __syncthreads();
    float d0 = v0 - mu, d1 = v1 - mu;
    red[tid] = d0*d0 + d1*d1;
    __syncthreads();
    for (int s = 128; s > 0; s >>= 1) { if (tid < s) red[tid] += red[tid+s]; __syncthreads(); }
    float r = rsqrtf(red[0]*(1.0f/DM) + 1e-3f);
    float y0 = d0*r*g[tid]     + bb[tid];
    float y1 = d1*r*g[tid+256] + bb[tid+256];
    size_t i0 = row*DM + tid, i1 = i0 + 256;
    outf[i0] = y0;
    outf[i1] = y1;
    if (outh) {
        cvst1(y0, outh + i0, outl + i0);
        cvst1(y1, outh + i1, outl + i1);
    }
}

// ---------------- final projection ------------------------------------------
__global__ void proj_kernel(const float* __restrict__ hf, const float* __restrict__ Wp,
                            const float* __restrict__ bp, float* __restrict__ out) {
    int row = blockIdx.x;
    int warp = threadIdx.x >> 5, lane = threadIdx.x & 31;
    const float* hr = hf + (size_t)row*DM;
    for (int c = warp; c < COUT; c += 8) {
        float sum = 0.f;
        for (int k2 = lane; k2 < DM; k2 += 32) sum += hr[k2] * Wp[(size_t)k2*COUT + c];
#pragma unroll
        for (int o = 16; o > 0; o >>= 1) sum += __shfl_xor_sync(0xffffffff, sum, o);
        if (lane == 0) out[(size_t)row*COUT + c] = sum + bp[c];
    }
}

// ---------------- host orchestration ----------------------------------------
extern "C" void kernel_launch(void* const* d_in, const int* in_sizes, int n_in,
                              void* d_out, int out_size) {
    const float* x    = (const float*)d_in[0];
    const float* ck   = (const float*)d_in[1];
    const float* Wq   = (const float*)d_in[2];
    const float* bq   = (const float*)d_in[3];
    const float* Wk   = (const float*)d_in[4];
    const float* bk   = (const float*)d_in[5];
    const float* Wv   = (const float*)d_in[6];
    const float* bv   = (const float*)d_in[7];
    const float* Ws   = (const float*)d_in[8];
    const float* bs   = (const float*)d_in[9];
    const float* Wo   = (const float*)d_in[10];
    const float* bo   = (const float*)d_in[11];
    const float* W1   = (const float*)d_in[12];
    const float* b1   = (const float*)d_in[13];
    const float* W2   = (const float*)d_in[14];
    const float* b2   = (const float*)d_in[15];
    const float* ln1g = (const float*)d_in[16];
    const float* ln1b = (const float*)d_in[17];
    const float* ln2g = (const float*)d_in[18];
    const float* ln2b = (const float*)d_in[19];
    const float* lnfg = (const float*)d_in[20];
    const float* lnfb = (const float*)d_in[21];
    const float* Wp   = (const float*)d_in[22];
    const float* bp   = (const float*)d_in[23];
    float* out = (float*)d_out;

    float *h, *t1, *t2, *sg;
    __nv_bfloat16 *hh, *hl, *qh, *ql, *kh, *kl, *vh, *vl, *t1h, *t1l, *wh, *wl;
    cudaGetSymbolAddress((void**)&h,   g_h);
    cudaGetSymbolAddress((void**)&t1,  g_t1);
    cudaGetSymbolAddress((void**)&t2,  g_t2);
    cudaGetSymbolAddress((void**)&sg,  g_sig);
    cudaGetSymbolAddress((void**)&hh,  g_hh);
    cudaGetSymbolAddress((void**)&hl,  g_hl);
    cudaGetSymbolAddress((void**)&qh,  g_qh);
    cudaGetSymbolAddress((void**)&ql,  g_ql);
    cudaGetSymbolAddress((void**)&kh,  g_kh);
    cudaGetSymbolAddress((void**)&kl,  g_kl);
    cudaGetSymbolAddress((void**)&vh,  g_vh);
    cudaGetSymbolAddress((void**)&vl,  g_vl);
    cudaGetSymbolAddress((void**)&t1h, g_t1h);
    cudaGetSymbolAddress((void**)&t1l, g_t1l);
    cudaGetSymbolAddress((void**)&wh,  g_wh);
    cudaGetSymbolAddress((void**)&wl,  g_wl);

    cudaFuncSetAttribute(mgemm<false>, cudaFuncAttributeMaxDynamicSharedMemorySize, 75776);
    cudaFuncSetAttribute(mgemm<true>,  cudaFuncAttributeMaxDynamicSharedMemorySize, 75776);
    cudaFuncSetAttribute(fscores,      cudaFuncAttributeMaxDynamicSharedMemorySize, FS_SMEM);

    wconv_kernel<<<4608, 256>>>(Wq, Wk, Wv, Wo, W1, W2, wh, wl);
    embed_kernel<<<ROWS, DM>>>(x, ck, h, hh, hl);

    dim3 g1(32, 4, 1);
    dim3 g3(32, 4, 3);
    for (int i = 0; i < NL; i++) {
        size_t wbase = (size_t)i*6*262144;
        GemmJob jq = { wh + wbase + 0*262144, wl + wbase + 0*262144, bq + i*DM, nullptr, qh, ql };
        GemmJob jk = { wh + wbase + 1*262144, wl + wbase + 1*262144, bk + i*DM, nullptr, kh, kl };
        GemmJob jv = { wh + wbase + 2*262144, wl + wbase + 2*262144, bv + i*DM, nullptr, vh, vl };
        GemmJob jo = { wh + wbase + 3*262144, wl + wbase + 3*262144, bo + i*DM, t2, nullptr, nullptr };
        GemmJob jf1 = { wh + wbase + 4*262144, wl + wbase + 4*262144, b1 + i*DM, nullptr, t1h, t1l };
        GemmJob jf2 = { wh + wbase + 5*262144, wl + wbase + 5*262144, b2 + i*DM, t2, nullptr, nullptr };

        mgemm<false><<<g3, 256, 75776>>>(hh, hl, jq, jk, jv);
        sig3_kernel<<<ROWS/64, 512>>>(h, Ws + (size_t)i*DM*NH, bs + i*NH, sg);

        float* ser = out + SERIES_OFF + (size_t)i*LAYER_ELEMS;
        fscores<<<dim3(8, 64), 512, FS_SMEM>>>(qh, ql, kh, kl, vh, vl, ser, t1h, t1l);
        prior_kernel<<<BATCH*NH*WIN, 128>>>(sg,
                out + PRIOR_OFF + (size_t)i*LAYER_ELEMS,
                out + SIGMA_OFF + (size_t)i*LAYER_ELEMS);

        mgemm<false><<<g1, 256, 75776>>>(t1h, t1l, jo, jo, jo);
        ln_kernel<<<ROWS, 256>>>(h, t2, ln1g + i*DM, ln1b + i*DM, h, hh, hl);

        mgemm<true ><<<g1, 256, 75776>>>(hh, hl, jf1, jf1, jf1);
        mgemm<false><<<g1, 256, 75776>>>(t1h, t1l, jf2, jf2, jf2);
        ln_kernel<<<ROWS, 256>>>(h, t2, ln2g + i*DM, ln2b + i*DM, h, hh, hl);
    }

    ln_kernel<<<ROWS, 256>>>(h, nullptr, lnfg, lnfb, t1, nullptr, nullptr);
    proj_kernel<<<ROWS, 256>>>(t1, Wp, bp, out);
}

// round 7
// speedup vs baseline: 2.6325x; 1.0128x over previous
#include <cuda_runtime.h>
#include <cuda_bf16.h>
#include <math.h>
#include <stdint.h>

#define WIN   512
#define BATCH 8
#define CIN   38
#define COUT  38
#define DM    512
#define NH    8
#define EHD   64
#define NL    3
#define ROWS  (BATCH*WIN)   /* 4096 */

#define OUT_ELEMS    (BATCH*WIN*COUT)
#define LAYER_ELEMS  ((size_t)BATCH*NH*WIN*WIN)
#define SERIES_OFF   ((size_t)OUT_ELEMS)
#define PRIOR_OFF    (SERIES_OFF + 3*LAYER_ELEMS)
#define SIGMA_OFF    (PRIOR_OFF  + 3*LAYER_ELEMS)

// ---------------- scratch ---------------------------------------------------
__device__ float g_h [ROWS*DM];
__device__ float g_t1[ROWS*DM];
__device__ float g_t2[ROWS*DM];
__device__ float g_sig[ROWS*NH];
__device__ __nv_bfloat16 g_hh [ROWS*DM];
__device__ __nv_bfloat16 g_hl [ROWS*DM];
__device__ __nv_bfloat16 g_qh [ROWS*DM];
__device__ __nv_bfloat16 g_ql [ROWS*DM];
__device__ __nv_bfloat16 g_kh [ROWS*DM];
__device__ __nv_bfloat16 g_kl [ROWS*DM];
__device__ __nv_bfloat16 g_vh [ROWS*DM];
__device__ __nv_bfloat16 g_vl [ROWS*DM];
__device__ __nv_bfloat16 g_t1h[ROWS*DM];
__device__ __nv_bfloat16 g_t1l[ROWS*DM];
__device__ __nv_bfloat16 g_wh [18*262144];
__device__ __nv_bfloat16 g_wl [18*262144];

// ---------------- helpers ---------------------------------------------------
__device__ __forceinline__ uint32_t smaddr(const void* p) {
    return (uint32_t)__cvta_generic_to_shared(p);
}
__device__ __forceinline__ void ldsm4(uint32_t a, uint32_t& r0, uint32_t& r1,
                                      uint32_t& r2, uint32_t& r3) {
    asm volatile("ldmatrix.sync.aligned.m8n8.x4.shared.b16 {%0,%1,%2,%3}, [%4];\n"
                 : "=r"(r0), "=r"(r1), "=r"(r2), "=r"(r3) : "r"(a));
}
__device__ __forceinline__ void ldsm4t(uint32_t a, uint32_t& r0, uint32_t& r1,
                                       uint32_t& r2, uint32_t& r3) {
    asm volatile("ldmatrix.sync.aligned.m8n8.x4.trans.shared.b16 {%0,%1,%2,%3}, [%4];\n"
                 : "=r"(r0), "=r"(r1), "=r"(r2), "=r"(r3) : "r"(a));
}
__device__ __forceinline__ void ldsm2t(uint32_t a, uint32_t& r0, uint32_t& r1) {
    asm volatile("ldmatrix.sync.aligned.m8n8.x2.trans.shared.b16 {%0,%1}, [%2];\n"
                 : "=r"(r0), "=r"(r1) : "r"(a));
}
__device__ __forceinline__ void mmabf(float* d, const uint32_t* a, uint32_t b0, uint32_t b1) {
    asm volatile("mma.sync.aligned.m16n8k16.row.col.f32.bf16.bf16.f32 "
                 "{%0,%1,%2,%3}, {%4,%5,%6,%7}, {%8,%9}, {%0,%1,%2,%3};\n"
                 : "+f"(d[0]), "+f"(d[1]), "+f"(d[2]), "+f"(d[3])
                 : "r"(a[0]), "r"(a[1]), "r"(a[2]), "r"(a[3]), "r"(b0), "r"(b1));
}
__device__ __forceinline__ void cvst(float x, float y, __nv_bfloat16* ph, __nv_bfloat16* pl) {
    __nv_bfloat16 h0 = __float2bfloat16_rn(x);
    __nv_bfloat16 l0 = __float2bfloat16_rn(x - __bfloat162float(h0));
    __nv_bfloat16 h1 = __float2bfloat16_rn(y);
    __nv_bfloat16 l1 = __float2bfloat16_rn(y - __bfloat162float(h1));
    *(__nv_bfloat162*)ph = __halves2bfloat162(h0, h1);
    *(__nv_bfloat162*)pl = __halves2bfloat162(l0, l1);
}
__device__ __forceinline__ void cvst1(float x, __nv_bfloat16* ph, __nv_bfloat16* pl) {
    __nv_bfloat16 h0 = __float2bfloat16_rn(x);
    *ph = h0;
    *pl = __float2bfloat16_rn(x - __bfloat162float(h0));
}
__device__ __forceinline__ void cpa16(uint32_t s, const void* g) {
    asm volatile("cp.async.ca.shared.global [%0], [%1], 16;\n" :: "r"(s), "l"(g));
}

// ---------------- weight pre-conversion -------------------------------------
__global__ void wconv_kernel(const float* __restrict__ Wq, const float* __restrict__ Wk,
                             const float* __restrict__ Wv, const float* __restrict__ Wo,
                             const float* __restrict__ W1, const float* __restrict__ W2,
                             __nv_bfloat16* __restrict__ wh, __nv_bfloat16* __restrict__ wl) {
    size_t j4 = ((size_t)blockIdx.x*256 + threadIdx.x) * 4;
    if (j4 >= 18ull*262144) return;
    size_t uu = j4 >> 18;
    int u = (int)(uu % 6), i = (int)(uu / 6);
    size_t off = j4 & 262143;
    const float* src;
    switch (u) { case 0: src=Wq; break; case 1: src=Wk; break; case 2: src=Wv; break;
                 case 3: src=Wo; break; case 4: src=W1; break; default: src=W2; }
    float4 f = *(const float4*)(src + (size_t)i*262144 + off);
    cvst(f.x, f.y, wh+j4,   wl+j4);
    cvst(f.z, f.w, wh+j4+2, wl+j4+2);
}

// ---------------- embedding -------------------------------------------------
__global__ void embed_kernel(const float* __restrict__ x,
                             const float* __restrict__ ck,
                             float* __restrict__ h,
                             __nv_bfloat16* __restrict__ hh,
                             __nv_bfloat16* __restrict__ hl) {
    int bt = blockIdx.x;
    int b = bt >> 9, t = bt & (WIN-1);
    __shared__ float xs[3*CIN];
    int tid = threadIdx.x;
    if (tid < 3*CIN) {
        int w = tid / CIN, c = tid % CIN;
        int src = (t + w - 1 + WIN) & (WIN-1);
        xs[tid] = x[((size_t)b*WIN + src)*CIN + c];
    }
    __syncthreads();
    int d = tid;
    int i2 = (d >> 1) * 2;
    float ang = (float)t * __expf(-(float)i2 * (9.210340371976184f/512.0f));
    float acc = (d & 1) ? cosf(ang) : sinf(ang);
#pragma unroll 1
    for (int wc = 0; wc < 3*CIN; wc++)
        acc += xs[wc] * ck[(size_t)wc*DM + d];
    size_t idx = (size_t)bt*DM + d;
    h[idx] = acc;
    cvst1(acc, hh + idx, hl + idx);
}

// ---------------- dense GEMM: 64x128 tile, pure-bf16, cp.async --------------
struct GemmJob {
    const __nv_bfloat16* Wh; const __nv_bfloat16* Wl;
    const float* bias;
    float* Cf; __nv_bfloat16* Ch; __nv_bfloat16* Cl;
};

#define AH_OFF 0
#define AL_OFF 2560
#define BH_OFF 5120
#define BL_OFF 9472
#define BUF_SZ 13824   /* halves per buffer */

__device__ __forceinline__ void mg_issue(uint32_t smb, int buf, int tid,
        const __nv_bfloat16* Ah, const __nv_bfloat16* Al,
        const __nv_bfloat16* Wh, const __nv_bfloat16* Wl, int kt) {
    int ar = tid >> 2, ac = (tid & 3) * 8;
    int br = tid >> 3, bc = (tid & 7) * 16;
    uint32_t base = smb + (uint32_t)buf * (BUF_SZ*2);
    const __nv_bfloat16* ga  = Ah + (size_t)ar*512 + kt*32 + ac;
    const __nv_bfloat16* gal = Al + (size_t)ar*512 + kt*32 + ac;
    cpa16(base + (uint32_t)(AH_OFF + ar*40 + ac)*2, ga);
    cpa16(base + (uint32_t)(AL_OFF + ar*40 + ac)*2, gal);
    const __nv_bfloat16* gb  = Wh + (size_t)(kt*32 + br)*512 + bc;
    const __nv_bfloat16* gbl = Wl + (size_t)(kt*32 + br)*512 + bc;
    uint32_t sb  = base + (uint32_t)(BH_OFF + br*136 + bc)*2;
    uint32_t sbl = base + (uint32_t)(BL_OFF + br*136 + bc)*2;
    cpa16(sb, gb);        cpa16(sb+16, gb+8);
    cpa16(sbl, gbl);      cpa16(sbl+16, gbl+8);
    asm volatile("cp.async.commit_group;\n");
}

__device__ __forceinline__ void mg_compute(uint32_t smb, int buf, int tid,
                                           float (*acc)[4][4]) {
    int l = tid & 31, w = tid >> 5, wm = w & 1, wn = w >> 1;
    int lr = l & 15, lc8 = (l >> 4) << 3;
    uint32_t base = smb + (uint32_t)buf * (BUF_SZ*2);
#pragma unroll
    for (int ks = 0; ks < 32; ks += 16) {
        uint32_t ah[2][4], al[2][4];
#pragma unroll
        for (int fm = 0; fm < 2; fm++) {
            uint32_t aoff = (uint32_t)((wm*32 + fm*16 + lr)*40 + ks + lc8) * 2;
            ldsm4(base + AH_OFF*2 + aoff, ah[fm][0], ah[fm][1], ah[fm][2], ah[fm][3]);
            ldsm4(base + AL_OFF*2 + aoff, al[fm][0], al[fm][1], al[fm][2], al[fm][3]);
        }
#pragma unroll
        for (int fnp = 0; fnp < 2; fnp++) {
            uint32_t boff = (uint32_t)((ks + lr)*136 + wn*32 + fnp*16 + lc8) * 2;
            uint32_t bh[4], bl[4];
            ldsm4t(base + BH_OFF*2 + boff, bh[0], bh[1], bh[2], bh[3]);
            ldsm4t(base + BL_OFF*2 + boff, bl[0], bl[1], bl[2], bl[3]);
#pragma unroll
            for (int fm = 0; fm < 2; fm++) {
                mmabf(acc[fm][fnp*2],   ah[fm], bh[0], bh[1]);
                mmabf(acc[fm][fnp*2],   ah[fm], bl[0], bl[1]);
                mmabf(acc[fm][fnp*2],   al[fm], bh[0], bh[1]);
                mmabf(acc[fm][fnp*2+1], ah[fm], bh[2], bh[3]);
                mmabf(acc[fm][fnp*2+1], ah[fm], bl[2], bl[3]);
                mmabf(acc[fm][fnp*2+1], al[fm], bh[2], bh[3]);
            }
        }
    }
}

template<bool GELU>
__global__ __launch_bounds__(256, 2)
void mgemm(const __nv_bfloat16* __restrict__ Ah, const __nv_bfloat16* __restrict__ Al,
           GemmJob j0, GemmJob j1, GemmJob j2) {
    extern __shared__ __nv_bfloat16 sm[];
    GemmJob jb = (blockIdx.z == 0) ? j0 : ((blockIdx.z == 1) ? j1 : j2);
    int tid = threadIdx.x;
    const __nv_bfloat16* Abh = Ah + (size_t)blockIdx.x * 64 * 512;
    const __nv_bfloat16* Abl = Al + (size_t)blockIdx.x * 64 * 512;
    const __nv_bfloat16* Wbh = jb.Wh + blockIdx.y * 128;
    const __nv_bfloat16* Wbl = jb.Wl + blockIdx.y * 128;
    uint32_t smb = smaddr(sm);

    mg_issue(smb, 0, tid, Abh, Abl, Wbh, Wbl, 0);
    mg_issue(smb, 1, tid, Abh, Abl, Wbh, Wbl, 1);

    float acc[2][4][4] = {};
    for (int kt = 0; kt < 16; kt++) {
        int buf = kt & 1;
        if (kt < 15) asm volatile("cp.async.wait_group 1;\n");
        else         asm volatile("cp.async.wait_group 0;\n");
        __syncthreads();
        mg_compute(smb, buf, tid, acc);
        if (kt < 14) {
            __syncthreads();
            mg_issue(smb, buf, tid, Abh, Abl, Wbh, Wbl, kt+2);
        }
    }

    int l = tid & 31, w = tid >> 5, wm = w & 1, wn = w >> 1;
    int g = l >> 2, t2 = (l & 3) * 2;
    int rowb = blockIdx.x*64 + wm*32;
    int colb = blockIdx.y*128 + wn*32;
#pragma unroll
    for (int fm = 0; fm < 2; fm++) {
#pragma unroll
        for (int fn = 0; fn < 4; fn++) {
            int col = colb + fn*8 + t2;
            float bx0 = jb.bias[col], bx1 = jb.bias[col+1];
            float o0 = acc[fm][fn][0] + bx0, o1 = acc[fm][fn][1] + bx1;
            float o2 = acc[fm][fn][2] + bx0, o3 = acc[fm][fn][3] + bx1;
            if (GELU) {
                o0 = 0.5f*o0*(1.0f + erff(o0*0.70710678118654752f));
                o1 = 0.5f*o1*(1.0f + erff(o1*0.70710678118654752f));
                o2 = 0.5f*o2*(1.0f + erff(o2*0.70710678118654752f));
                o3 = 0.5f*o3*(1.0f + erff(o3*0.70710678118654752f));
            }
            int r0 = rowb + fm*16 + g;
            if (jb.Cf) {
                float2 p0 = {o0, o1}, p1 = {o2, o3};
                *(float2*)(jb.Cf + (size_t)r0*512 + col)     = p0;
                *(float2*)(jb.Cf + (size_t)(r0+8)*512 + col) = p1;
            }
            if (jb.Ch) {
                cvst(o0, o1, jb.Ch + (size_t)r0*512 + col,     jb.Cl + (size_t)r0*512 + col);
                cvst(o2, o3, jb.Ch + (size_t)(r0+8)*512 + col, jb.Cl + (size_t)(r0+8)*512 + col);
            }
        }
    }
}

// ---------------- fused scores + softmax + S@V ------------------------------
#define FQH 0
#define FQL 4608
#define FKH 9216
#define FKL 46080
#define FVH 0
#define FVL 4608
#define FSH 9216
#define FSL 42496
#define FS_SMEM 165888

__global__ __launch_bounds__(512)
void fscores(const __nv_bfloat16* __restrict__ qh, const __nv_bfloat16* __restrict__ ql,
             const __nv_bfloat16* __restrict__ kh, const __nv_bfloat16* __restrict__ kl,
             const __nv_bfloat16* __restrict__ vh, const __nv_bfloat16* __restrict__ vl,
             float* __restrict__ out,
             __nv_bfloat16* __restrict__ t1h, __nv_bfloat16* __restrict__ t1l) {
    extern __shared__ __nv_bfloat16 sm[];
    __shared__ float red[64][8];
    int tid = threadIdx.x;
    int bh = blockIdx.y, b = bh >> 3, hhd = bh & 7;
    int l0 = blockIdx.x * 64;

    {
        int r = tid >> 3, c = (tid & 7) * 8;
        size_t qoff = ((size_t)(b*512 + l0 + r))*512 + hhd*64 + c;
        int qi = r*72 + c;
        *(uint4*)&sm[FQH + qi] = *(const uint4*)(qh + qoff);
        *(uint4*)&sm[FQL + qi] = *(const uint4*)(ql + qoff);
#pragma unroll
        for (int i = 0; i < 8; i++) {
            int kr = r + i*64;
            size_t koff = ((size_t)(b*512 + kr))*512 + hhd*64 + c;
            int ki = kr*72 + c;
            *(uint4*)&sm[FKH + ki] = *(const uint4*)(kh + koff);
            *(uint4*)&sm[FKL + ki] = *(const uint4*)(kl + koff);
        }
    }
    __syncthreads();

    uint32_t smb = smaddr(sm);
    int l = tid & 31, w = tid >> 5;
    int wn = w & 7, wm = w >> 3;
    int lr = l & 15, lc8 = (l >> 4) << 3;
    float acc[2][8][4] = {};
#pragma unroll
    for (int ks = 0; ks < 64; ks += 16) {
        uint32_t ah[2][4], al[2][4];
#pragma unroll
        for (int fm = 0; fm < 2; fm++) {
            uint32_t aoff = (uint32_t)((wm*32 + fm*16 + lr)*72 + ks + lc8) * 2;
            ldsm4(smb + FQH*2 + aoff, ah[fm][0], ah[fm][1], ah[fm][2], ah[fm][3]);
            ldsm4(smb + FQL*2 + aoff, al[fm][0], al[fm][1], al[fm][2], al[fm][3]);
        }
#pragma unroll
        for (int fnp = 0; fnp < 4; fnp++) {
            uint32_t boff = (uint32_t)((wn*64 + fnp*16 + lr)*72 + ks + lc8) * 2;
            uint32_t khr[4], klr[4];
            ldsm4(smb + FKH*2 + boff, khr[0], khr[1], khr[2], khr[3]);
            ldsm4(smb + FKL*2 + boff, klr[0], klr[1], klr[2], klr[3]);
#pragma unroll
            for (int fm = 0; fm < 2; fm++) {
                mmabf(acc[fm][fnp*2],   ah[fm], khr[0], khr[2]);
                mmabf(acc[fm][fnp*2],   ah[fm], klr[0], klr[2]);
                mmabf(acc[fm][fnp*2],   al[fm], khr[0], khr[2]);
                mmabf(acc[fm][fnp*2+1], ah[fm], khr[1], khr[3]);
                mmabf(acc[fm][fnp*2+1], ah[fm], klr[1], klr[3]);
                mmabf(acc[fm][fnp*2+1], al[fm], khr[1], khr[3]);
            }
        }
    }

#pragma unroll
    for (int fm = 0; fm < 2; fm++)
#pragma unroll
        for (int fn = 0; fn < 8; fn++)
#pragma unroll
            for (int e = 0; e < 4; e++) acc[fm][fn][e] *= 0.125f;

    int g = l >> 2, t2 = (l & 3) * 2;
    float tmax[2][2] = {{-1e30f,-1e30f},{-1e30f,-1e30f}};
#pragma unroll
    for (int fm = 0; fm < 2; fm++)
#pragma unroll
        for (int fn = 0; fn < 8; fn++) {
            tmax[fm][0] = fmaxf(tmax[fm][0], fmaxf(acc[fm][fn][0], acc[fm][fn][1]));
            tmax[fm][1] = fmaxf(tmax[fm][1], fmaxf(acc[fm][fn][2], acc[fm][fn][3]));
        }
#pragma unroll
    for (int o = 1; o <= 2; o <<= 1) {
#pragma unroll
        for (int fm = 0; fm < 2; fm++) {
            tmax[fm][0] = fmaxf(tmax[fm][0], __shfl_xor_sync(0xffffffff, tmax[fm][0], o));
            tmax[fm][1] = fmaxf(tmax[fm][1], __shfl_xor_sync(0xffffffff, tmax[fm][1], o));
        }
    }
    if ((l & 3) == 0) {
#pragma unroll
        for (int fm = 0; fm < 2; fm++) {
            red[wm*32 + fm*16 + g][wn]     = tmax[fm][0];
            red[wm*32 + fm*16 + g + 8][wn] = tmax[fm][1];
        }
    }
    __syncthreads();
    float rmax[2][2];
#pragma unroll
    for (int fm = 0; fm < 2; fm++)
#pragma unroll
        for (int hf = 0; hf < 2; hf++) {
            int r = wm*32 + fm*16 + g + hf*8;
            float m = red[r][0];
#pragma unroll
            for (int ww = 1; ww < 8; ww++) m = fmaxf(m, red[r][ww]);
            rmax[fm][hf] = m;
        }
    __syncthreads();

    float tsum[2][2] = {};
#pragma unroll
    for (int fm = 0; fm < 2; fm++)
#pragma unroll
        for (int fn = 0; fn < 8; fn++) {
            acc[fm][fn][0] = __expf(acc[fm][fn][0] - rmax[fm][0]);
            acc[fm][fn][1] = __expf(acc[fm][fn][1] - rmax[fm][0]);
            acc[fm][fn][2] = __expf(acc[fm][fn][2] - rmax[fm][1]);
            acc[fm][fn][3] = __expf(acc[fm][fn][3] - rmax[fm][1]);
            tsum[fm][0] += acc[fm][fn][0] + acc[fm][fn][1];
            tsum[fm][1] += acc[fm][fn][2] + acc[fm][fn][3];
        }
#pragma unroll
    for (int o = 1; o <= 2; o <<= 1) {
#pragma unroll
        for (int fm = 0; fm < 2; fm++) {
            tsum[fm][0] += __shfl_xor_sync(0xffffffff, tsum[fm][0], o);
            tsum[fm][1] += __shfl_xor_sync(0xffffffff, tsum[fm][1], o);
        }
    }
    if ((l & 3) == 0) {
#pragma unroll
        for (int fm = 0; fm < 2; fm++) {
            red[wm*32 + fm*16 + g][wn]     = tsum[fm][0];
            red[wm*32 + fm*16 + g + 8][wn] = tsum[fm][1];
        }
    }
    __syncthreads();
    float rinv[2][2];
#pragma unroll
    for (int fm = 0; fm < 2; fm++)
#pragma unroll
        for (int hf = 0; hf < 2; hf++) {
            int r = wm*32 + fm*16 + g + hf*8;
            float s = red[r][0];
#pragma unroll
            for (int ww = 1; ww < 8; ww++) s += red[r][ww];
            rinv[fm][hf] = 1.0f / s;
        }

    float* ob = out + ((size_t)bh*512 + l0)*512;
#pragma unroll
    for (int fm = 0; fm < 2; fm++)
#pragma unroll
        for (int fn = 0; fn < 8; fn++) {
            int row0 = wm*32 + fm*16 + g;
            int col = wn*64 + fn*8 + t2;
            float s0 = acc[fm][fn][0]*rinv[fm][0], s1 = acc[fm][fn][1]*rinv[fm][0];
            float s2 = acc[fm][fn][2]*rinv[fm][1], s3 = acc[fm][fn][3]*rinv[fm][1];
            float2 p0 = {s0, s1}, p1 = {s2, s3};
            *(float2*)(ob + (size_t)row0*512 + col)     = p0;
            *(float2*)(ob + (size_t)(row0+8)*512 + col) = p1;
            cvst(s0, s1, &sm[FSH + row0*520 + col],     &sm[FSL + row0*520 + col]);
            cvst(s2, s3, &sm[FSH + (row0+8)*520 + col], &sm[FSL + (row0+8)*520 + col]);
        }
    __syncthreads();

    float acc2[2][4] = {};
    for (int kc = 0; kc < 8; kc++) {
        {
            int r = tid >> 3, c = (tid & 7) * 8;
            size_t voff = ((size_t)(b*512 + kc*64 + r))*512 + hhd*64 + c;
            *(uint4*)&sm[FVH + r*72 + c] = *(const uint4*)(vh + voff);
            *(uint4*)&sm[FVL + r*72 + c] = *(const uint4*)(vl + voff);
        }
        __syncthreads();
#pragma unroll
        for (int ks = 0; ks < 64; ks += 16) {
            uint32_t sa[2][4], sl2[2][4];
#pragma unroll
            for (int fm = 0; fm < 2; fm++) {
                uint32_t aoff = (uint32_t)((wm*32 + fm*16 + lr)*520 + kc*64 + ks + lc8) * 2;
                ldsm4(smb + FSH*2 + aoff, sa[fm][0], sa[fm][1], sa[fm][2], sa[fm][3]);
                ldsm4(smb + FSL*2 + aoff, sl2[fm][0], sl2[fm][1], sl2[fm][2], sl2[fm][3]);
            }
            uint32_t boff = (uint32_t)((ks + lr)*72 + wn*8) * 2;
            uint32_t bh2[2], bl2[2];
            ldsm2t(smb + FVH*2 + boff, bh2[0], bh2[1]);
            ldsm2t(smb + FVL*2 + boff, bl2[0], bl2[1]);
#pragma unroll
            for (int fm = 0; fm < 2; fm++) {
                mmabf(acc2[fm], sa[fm],  bh2[0], bh2[1]);
                mmabf(acc2[fm], sa[fm],  bl2[0], bl2[1]);
                mmabf(acc2[fm], sl2[fm], bh2[0], bh2[1]);
            }
        }
        if (kc < 7) __syncthreads();
    }

#pragma unroll
    for (int fm = 0; fm < 2; fm++) {
        int row0 = wm*32 + fm*16 + g;
        int col = wn*8 + t2;
        size_t p0 = ((size_t)(b*512 + l0 + row0))*512 + hhd*64 + col;
        size_t p1 = ((size_t)(b*512 + l0 + row0 + 8))*512 + hhd*64 + col;
        cvst(acc2[fm][0], acc2[fm][1], t1h + p0, t1l + p0);
        cvst(acc2[fm][2], acc2[fm][3], t1h + p1, t1l + p1);
    }
}

// ---------------- sigma projection v4: warp/row, L1-resident Ws -------------
__global__ __launch_bounds__(128)
void sig4_kernel(const float* __restrict__ h, const float* __restrict__ Ws,
                 const float* __restrict__ bs, float* __restrict__ sig) {
    int warp = threadIdx.x >> 5, lane = threadIdx.x & 31;
    int row = blockIdx.x*4 + warp;
    const float* hr = h + (size_t)row*512;
    float s[8] = {};
#pragma unroll
    for (int i = 0; i < 16; i++) {
        int k = i*32 + lane;
        float hv = hr[k];
        float4 wa = *(const float4*)(Ws + k*8);
        float4 wb = *(const float4*)(Ws + k*8 + 4);
        s[0] += hv*wa.x; s[1] += hv*wa.y; s[2] += hv*wa.z; s[3] += hv*wa.w;
        s[4] += hv*wb.x; s[5] += hv*wb.y; s[6] += hv*wb.z; s[7] += hv*wb.w;
    }
#pragma unroll
    for (int off = 16; off > 0; off >>= 1)
#pragma unroll
        for (int o = 0; o < 8; o++) s[o] += __shfl_xor_sync(0xffffffff, s[o], off);
    if (lane < 8) sig[row*8 + lane] = s[lane] + bs[lane];
}

// ---------------- prior + sigma (float4 writes) ------------------------------
__global__ __launch_bounds__(128)
void prior_kernel(const float* __restrict__ sig,
                  float* __restrict__ prior, float* __restrict__ sigma) {
    int idx = blockIdx.x;
    int l = idx & (WIN-1);
    int bh = idx >> 9;
    int b = bh >> 3, hh = bh & 7;
    float sv = sig[((size_t)b*WIN + l)*NH + hh];
    float sgm = 1.0f/(1.0f + __expf(-5.0f*sv)) + 1e-5f;
    float sg  = __expf(sgm * 1.0986122886681098f) - 1.0f;
    float inv = 0.3989422804014327f / sg;
    float cc  = -1.0f/(2.0f*sg*sg);
    size_t base = ((size_t)bh*WIN + l)*WIN;
    int s0 = threadIdx.x * 4;
    float d0 = (float)(l - s0), d1 = d0 - 1.0f, d2 = d0 - 2.0f, d3 = d0 - 3.0f;
    float4 pr;
    pr.x = inv*__expf(cc*d0*d0); pr.y = inv*__expf(cc*d1*d1);
    pr.z = inv*__expf(cc*d2*d2); pr.w = inv*__expf(cc*d3*d3);
    *(float4*)(prior + base + s0) = pr;
    float4 sgv = {sg, sg, sg, sg};
    *(float4*)(sigma + base + s0) = sgv;
}

// ---------------- LayerNorm -------------------------------------------------
__global__ void ln_kernel(const float* __restrict__ x, const float* __restrict__ res,
                          const float* __restrict__ g, const float* __restrict__ bb,
                          float* __restrict__ outf,
                          __nv_bfloat16* __restrict__ outh, __nv_bfloat16* __restrict__ outl) {
    size_t row = blockIdx.x;
    int tid = threadIdx.x;
    const float* xr = x + row*DM;
    float v0 = xr[tid], v1 = xr[tid+256];
    if (res) { const float* rr = res + row*DM; v0 += rr[tid]; v1 += rr[tid+256]; }
    __shared__ float red[256];
    red[tid] = v0 + v1;
    __syncthreads();
    for (int s = 128; s > 0; s >>= 1) { if (tid < s) red[tid] += red[tid+s]; __syncthreads(); }
    float mu = red[0] * (1.0f/DM);
    __syncthreads();
    float d0 = v0 - mu, d1 = v1 - mu;
    red[tid] = d0*d0 + d1*d1;
    __syncthreads();
    for (int s = 128; s > 0; s >>= 1) { if (tid < s) red[tid] += red[tid+s]; __syncthreads(); }
    float r = rsqrtf(red[0]*(1.0f/DM) + 1e-3f);
    float y0 = d0*r*g[tid]     + bb[tid];
    float y1 = d1*r*g[tid+256] + bb[tid+256];
    size_t i0 = row*DM + tid, i1 = i0 + 256;
    outf[i0] = y0;
    outf[i1] = y1;
    if (outh) {
        cvst1(y0, outh + i0, outl + i0);
        cvst1(y1, outh + i1, outl + i1);
    }
}

// ---------------- final projection ------------------------------------------
__global__ void proj_kernel(const float* __restrict__ hf, const float* __restrict__ Wp,
                            const float* __restrict__ bp, float* __restrict__ out) {
    int row = blockIdx.x;
    int warp = threadIdx.x >> 5, lane = threadIdx.x & 31;
    const float* hr = hf + (size_t)row*DM;
    for (int c = warp; c < COUT; c += 8) {
        float sum = 0.f;
        for (int k2 = lane; k2 < DM; k2 += 32) sum += hr[k2] * Wp[(size_t)k2*COUT + c];
#pragma unroll
        for (int o = 16; o > 0; o >>= 1) sum += __shfl_xor_sync(0xffffffff, sum, o);
        if (lane == 0) out[(size_t)row*COUT + c] = sum + bp[c];
    }
}

// ---------------- host orchestration ----------------------------------------
extern "C" void kernel_launch(void* const* d_in, const int* in_sizes, int n_in,
                              void* d_out, int out_size) {
    const float* x    = (const float*)d_in[0];
    const float* ck   = (const float*)d_in[1];
    const float* Wq   = (const float*)d_in[2];
    const float* bq   = (const float*)d_in[3];
    const float* Wk   = (const float*)d_in[4];
    const float* bk   = (const float*)d_in[5];
    const float* Wv   = (const float*)d_in[6];
    const float* bv   = (const float*)d_in[7];
    const float* Ws   = (const float*)d_in[8];
    const float* bs   = (const float*)d_in[9];
    const float* Wo   = (const float*)d_in[10];
    const float* bo   = (const float*)d_in[11];
    const float* W1   = (const float*)d_in[12];
    const float* b1   = (const float*)d_in[13];
    const float* W2   = (const float*)d_in[14];
    const float* b2   = (const float*)d_in[15];
    const float* ln1g = (const float*)d_in[16];
    const float* ln1b = (const float*)d_in[17];
    const float* ln2g = (const float*)d_in[18];
    const float* ln2b = (const float*)d_in[19];
    const float* lnfg = (const float*)d_in[20];
    const float* lnfb = (const float*)d_in[21];
    const float* Wp   = (const float*)d_in[22];
    const float* bp   = (const float*)d_in[23];
    float* out = (float*)d_out;

    float *h, *t1, *t2, *sg;
    __nv_bfloat16 *hh, *hl, *qh, *ql, *kh, *kl, *vh, *vl, *t1h, *t1l, *wh, *wl;
    cudaGetSymbolAddress((void**)&h,   g_h);
    cudaGetSymbolAddress((void**)&t1,  g_t1);
    cudaGetSymbolAddress((void**)&t2,  g_t2);
    cudaGetSymbolAddress((void**)&sg,  g_sig);
    cudaGetSymbolAddress((void**)&hh,  g_hh);
    cudaGetSymbolAddress((void**)&hl,  g_hl);
    cudaGetSymbolAddress((void**)&qh,  g_qh);
    cudaGetSymbolAddress((void**)&ql,  g_ql);
    cudaGetSymbolAddress((void**)&kh,  g_kh);
    cudaGetSymbolAddress((void**)&kl,  g_kl);
    cudaGetSymbolAddress((void**)&vh,  g_vh);
    cudaGetSymbolAddress((void**)&vl,  g_vl);
    cudaGetSymbolAddress((void**)&t1h, g_t1h);
    cudaGetSymbolAddress((void**)&t1l, g_t1l);
    cudaGetSymbolAddress((void**)&wh,  g_wh);
    cudaGetSymbolAddress((void**)&wl,  g_wl);

    cudaFuncSetAttribute(mgemm<false>, cudaFuncAttributeMaxDynamicSharedMemorySize, 55296);
    cudaFuncSetAttribute(mgemm<true>,  cudaFuncAttributeMaxDynamicSharedMemorySize, 55296);
    cudaFuncSetAttribute(fscores,      cudaFuncAttributeMaxDynamicSharedMemorySize, FS_SMEM);

    wconv_kernel<<<4608, 256>>>(Wq, Wk, Wv, Wo, W1, W2, wh, wl);
    embed_kernel<<<ROWS, DM>>>(x, ck, h, hh, hl);

    dim3 g1(64, 4, 1);
    dim3 g3(64, 4, 3);
    for (int i = 0; i < NL; i++) {
        size_t wbase = (size_t)i*6*262144;
        GemmJob jq = { wh + wbase + 0*262144, wl + wbase + 0*262144, bq + i*DM, nullptr, qh, ql };
        GemmJob jk = { wh + wbase + 1*262144, wl + wbase + 1*262144, bk + i*DM, nullptr, kh, kl };
        GemmJob jv = { wh + wbase + 2*262144, wl + wbase + 2*262144, bv + i*DM, nullptr, vh, vl };
        GemmJob jo = { wh + wbase + 3*262144, wl + wbase + 3*262144, bo + i*DM, t2, nullptr, nullptr };
        GemmJob jf1 = { wh + wbase + 4*262144, wl + wbase + 4*262144, b1 + i*DM, nullptr, t1h, t1l };
        GemmJob jf2 = { wh + wbase + 5*262144, wl + wbase + 5*262144, b2 + i*DM, t2, nullptr, nullptr };

        mgemm<false><<<g3, 256, 55296>>>(hh, hl, jq, jk, jv);
        sig4_kernel<<<ROWS/4, 128>>>(h, Ws + (size_t)i*DM*NH, bs + i*NH, sg);

        float* ser = out + SERIES_OFF + (size_t)i*LAYER_ELEMS;
        fscores<<<dim3(8, 64), 512, FS_SMEM>>>(qh, ql, kh, kl, vh, vl, ser, t1h, t1l);
        prior_kernel<<<BATCH*NH*WIN, 128>>>(sg,
                out + PRIOR_OFF + (size_t)i*LAYER_ELEMS,
                out + SIGMA_OFF + (size_t)i*LAYER_ELEMS);

        mgemm<false><<<g1, 256, 55296>>>(t1h, t1l, jo, jo, jo);
        ln_kernel<<<ROWS, 256>>>(h, t2, ln1g + i*DM, ln1b + i*DM, h, hh, hl);

        mgemm<true ><<<g1, 256, 55296>>>(hh, hl, jf1, jf1, jf1);
        mgemm<false><<<g1, 256, 55296>>>(t1h, t1l, jf2, jf2, jf2);
        ln_kernel<<<ROWS, 256>>>(h, t2, ln2g + i*DM, ln2b + i*DM, h, hh, hl);
    }

    ln_kernel<<<ROWS, 256>>>(h, nullptr, lnfg, lnfb, t1, nullptr, nullptr);
    proj_kernel<<<ROWS, 256>>>(t1, Wp, bp, out);
}

// round 8
// speedup vs baseline: 2.6331x; 1.0002x over previous
#include <cuda_runtime.h>
#include <cuda_bf16.h>
#include <math.h>
#include <stdint.h>

#define WIN   512
#define BATCH 8
#define CIN   38
#define COUT  38
#define DM    512
#define NH    8
#define EHD   64
#define NL    3
#define ROWS  (BATCH*WIN)   /* 4096 */

#define OUT_ELEMS    (BATCH*WIN*COUT)
#define LAYER_ELEMS  ((size_t)BATCH*NH*WIN*WIN)
#define SERIES_OFF   ((size_t)OUT_ELEMS)
#define PRIOR_OFF    (SERIES_OFF + 3*LAYER_ELEMS)
#define SIGMA_OFF    (PRIOR_OFF  + 3*LAYER_ELEMS)

// ---------------- scratch ---------------------------------------------------
__device__ float g_h [ROWS*DM];
__device__ float g_t1[ROWS*DM];
__device__ float g_t2[ROWS*DM];
__device__ float g_sig[ROWS*NH];
__device__ __nv_bfloat16 g_hh [ROWS*DM];
__device__ __nv_bfloat16 g_hl [ROWS*DM];
__device__ __nv_bfloat16 g_qh [ROWS*DM];
__device__ __nv_bfloat16 g_ql [ROWS*DM];
__device__ __nv_bfloat16 g_kh [ROWS*DM];
__device__ __nv_bfloat16 g_kl [ROWS*DM];
__device__ __nv_bfloat16 g_vh [ROWS*DM];
__device__ __nv_bfloat16 g_vl [ROWS*DM];
__device__ __nv_bfloat16 g_t1h[ROWS*DM];
__device__ __nv_bfloat16 g_t1l[ROWS*DM];
__device__ __nv_bfloat16 g_wh [18*262144];
__device__ __nv_bfloat16 g_wl [18*262144];

// ---------------- helpers ---------------------------------------------------
__device__ __forceinline__ uint32_t smaddr(const void* p) {
    return (uint32_t)__cvta_generic_to_shared(p);
}
__device__ __forceinline__ void ldsm4(uint32_t a, uint32_t& r0, uint32_t& r1,
                                      uint32_t& r2, uint32_t& r3) {
    asm volatile("ldmatrix.sync.aligned.m8n8.x4.shared.b16 {%0,%1,%2,%3}, [%4];\n"
                 : "=r"(r0), "=r"(r1), "=r"(r2), "=r"(r3) : "r"(a));
}
__device__ __forceinline__ void ldsm4t(uint32_t a, uint32_t& r0, uint32_t& r1,
                                       uint32_t& r2, uint32_t& r3) {
    asm volatile("ldmatrix.sync.aligned.m8n8.x4.trans.shared.b16 {%0,%1,%2,%3}, [%4];\n"
                 : "=r"(r0), "=r"(r1), "=r"(r2), "=r"(r3) : "r"(a));
}
__device__ __forceinline__ void ldsm2t(uint32_t a, uint32_t& r0, uint32_t& r1) {
    asm volatile("ldmatrix.sync.aligned.m8n8.x2.trans.shared.b16 {%0,%1}, [%2];\n"
                 : "=r"(r0), "=r"(r1) : "r"(a));
}
__device__ __forceinline__ void mmabf(float* d, const uint32_t* a, uint32_t b0, uint32_t b1) {
    asm volatile("mma.sync.aligned.m16n8k16.row.col.f32.bf16.bf16.f32 "
                 "{%0,%1,%2,%3}, {%4,%5,%6,%7}, {%8,%9}, {%0,%1,%2,%3};\n"
                 : "+f"(d[0]), "+f"(d[1]), "+f"(d[2]), "+f"(d[3])
                 : "r"(a[0]), "r"(a[1]), "r"(a[2]), "r"(a[3]), "r"(b0), "r"(b1));
}
__device__ __forceinline__ void cvst(float x, float y, __nv_bfloat16* ph, __nv_bfloat16* pl) {
    __nv_bfloat16 h0 = __float2bfloat16_rn(x);
    __nv_bfloat16 l0 = __float2bfloat16_rn(x - __bfloat162float(h0));
    __nv_bfloat16 h1 = __float2bfloat16_rn(y);
    __nv_bfloat16 l1 = __float2bfloat16_rn(y - __bfloat162float(h1));
    *(__nv_bfloat162*)ph = __halves2bfloat162(h0, h1);
    *(__nv_bfloat162*)pl = __halves2bfloat162(l0, l1);
}
__device__ __forceinline__ void cvst1(float x, __nv_bfloat16* ph, __nv_bfloat16* pl) {
    __nv_bfloat16 h0 = __float2bfloat16_rn(x);
    *ph = h0;
    *pl = __float2bfloat16_rn(x - __bfloat162float(h0));
}
__device__ __forceinline__ void cpa16(uint32_t s, const void* g) {
    asm volatile("cp.async.ca.shared.global [%0], [%1], 16;\n" :: "r"(s), "l"(g));
}

// ---------------- weight pre-conversion -------------------------------------
__global__ void wconv_kernel(const float* __restrict__ Wq, const float* __restrict__ Wk,
                             const float* __restrict__ Wv, const float* __restrict__ Wo,
                             const float* __restrict__ W1, const float* __restrict__ W2,
                             __nv_bfloat16* __restrict__ wh, __nv_bfloat16* __restrict__ wl) {
    size_t j4 = ((size_t)blockIdx.x*256 + threadIdx.x) * 4;
    if (j4 >= 18ull*262144) return;
    size_t uu = j4 >> 18;
    int u = (int)(uu % 6), i = (int)(uu / 6);
    size_t off = j4 & 262143;
    const float* src;
    switch (u) { case 0: src=Wq; break; case 1: src=Wk; break; case 2: src=Wv; break;
                 case 3: src=Wo; break; case 4: src=W1; break; default: src=W2; }
    float4 f = *(const float4*)(src + (size_t)i*262144 + off);
    cvst(f.x, f.y, wh+j4,   wl+j4);
    cvst(f.z, f.w, wh+j4+2, wl+j4+2);
}

// ---------------- embedding -------------------------------------------------
__global__ void embed_kernel(const float* __restrict__ x,
                             const float* __restrict__ ck,
                             float* __restrict__ h,
                             __nv_bfloat16* __restrict__ hh,
                             __nv_bfloat16* __restrict__ hl) {
    int bt = blockIdx.x;
    int b = bt >> 9, t = bt & (WIN-1);
    __shared__ float xs[3*CIN];
    int tid = threadIdx.x;
    if (tid < 3*CIN) {
        int w = tid / CIN, c = tid % CIN;
        int src = (t + w - 1 + WIN) & (WIN-1);
        xs[tid] = x[((size_t)b*WIN + src)*CIN + c];
    }
    __syncthreads();
    int d = tid;
    int i2 = (d >> 1) * 2;
    float ang = (float)t * __expf(-(float)i2 * (9.210340371976184f/512.0f));
    float acc = (d & 1) ? cosf(ang) : sinf(ang);
#pragma unroll 1
    for (int wc = 0; wc < 3*CIN; wc++)
        acc += xs[wc] * ck[(size_t)wc*DM + d];
    size_t idx = (size_t)bt*DM + d;
    h[idx] = acc;
    cvst1(acc, hh + idx, hl + idx);
}

// ---------------- dense GEMM: 64x128 tile, pure-bf16, cp.async --------------
struct GemmJob {
    const __nv_bfloat16* Wh; const __nv_bfloat16* Wl;
    const float* bias;
    float* Cf; __nv_bfloat16* Ch; __nv_bfloat16* Cl;
};

#define AH_OFF 0
#define AL_OFF 2560
#define BH_OFF 5120
#define BL_OFF 9472
#define BUF_SZ 13824   /* halves per buffer */

__device__ __forceinline__ void mg_issue(uint32_t smb, int buf, int tid,
        const __nv_bfloat16* Ah, const __nv_bfloat16* Al,
        const __nv_bfloat16* Wh, const __nv_bfloat16* Wl, int kt) {
    int ar = tid >> 2, ac = (tid & 3) * 8;
    int br = tid >> 3, bc = (tid & 7) * 16;
    uint32_t base = smb + (uint32_t)buf * (BUF_SZ*2);
    const __nv_bfloat16* ga  = Ah + (size_t)ar*512 + kt*32 + ac;
    const __nv_bfloat16* gal = Al + (size_t)ar*512 + kt*32 + ac;
    cpa16(base + (uint32_t)(AH_OFF + ar*40 + ac)*2, ga);
    cpa16(base + (uint32_t)(AL_OFF + ar*40 + ac)*2, gal);
    const __nv_bfloat16* gb  = Wh + (size_t)(kt*32 + br)*512 + bc;
    const __nv_bfloat16* gbl = Wl + (size_t)(kt*32 + br)*512 + bc;
    uint32_t sb  = base + (uint32_t)(BH_OFF + br*136 + bc)*2;
    uint32_t sbl = base + (uint32_t)(BL_OFF + br*136 + bc)*2;
    cpa16(sb, gb);        cpa16(sb+16, gb+8);
    cpa16(sbl, gbl);      cpa16(sbl+16, gbl+8);
    asm volatile("cp.async.commit_group;\n");
}

__device__ __forceinline__ void mg_compute(uint32_t smb, int buf, int tid,
                                           float (*acc)[4][4]) {
    int l = tid & 31, w = tid >> 5, wm = w & 1, wn = w >> 1;
    int lr = l & 15, lc8 = (l >> 4) << 3;
    uint32_t base = smb + (uint32_t)buf * (BUF_SZ*2);
#pragma unroll
    for (int ks = 0; ks < 32; ks += 16) {
        uint32_t ah[2][4], al[2][4];
#pragma unroll
        for (int fm = 0; fm < 2; fm++) {
            uint32_t aoff = (uint32_t)((wm*32 + fm*16 + lr)*40 + ks + lc8) * 2;
            ldsm4(base + AH_OFF*2 + aoff, ah[fm][0], ah[fm][1], ah[fm][2], ah[fm][3]);
            ldsm4(base + AL_OFF*2 + aoff, al[fm][0], al[fm][1], al[fm][2], al[fm][3]);
        }
#pragma unroll
        for (int fnp = 0; fnp < 2; fnp++) {
            uint32_t boff = (uint32_t)((ks + lr)*136 + wn*32 + fnp*16 + lc8) * 2;
            uint32_t bh[4], bl[4];
            ldsm4t(base + BH_OFF*2 + boff, bh[0], bh[1], bh[2], bh[3]);
            ldsm4t(base + BL_OFF*2 + boff, bl[0], bl[1], bl[2], bl[3]);
#pragma unroll
            for (int fm = 0; fm < 2; fm++) {
                mmabf(acc[fm][fnp*2],   ah[fm], bh[0], bh[1]);
                mmabf(acc[fm][fnp*2],   ah[fm], bl[0], bl[1]);
                mmabf(acc[fm][fnp*2],   al[fm], bh[0], bh[1]);
                mmabf(acc[fm][fnp*2+1], ah[fm], bh[2], bh[3]);
                mmabf(acc[fm][fnp*2+1], ah[fm], bl[2], bl[3]);
                mmabf(acc[fm][fnp*2+1], al[fm], bh[2], bh[3]);
            }
        }
    }
}

template<bool GELU>
__global__ __launch_bounds__(256, 2)
void mgemm(const __nv_bfloat16* __restrict__ Ah, const __nv_bfloat16* __restrict__ Al,
           GemmJob j0, GemmJob j1, GemmJob j2) {
    extern __shared__ __nv_bfloat16 sm[];
    GemmJob jb = (blockIdx.z == 0) ? j0 : ((blockIdx.z == 1) ? j1 : j2);
    int tid = threadIdx.x;
    const __nv_bfloat16* Abh = Ah + (size_t)blockIdx.x * 64 * 512;
    const __nv_bfloat16* Abl = Al + (size_t)blockIdx.x * 64 * 512;
    const __nv_bfloat16* Wbh = jb.Wh + blockIdx.y * 128;
    const __nv_bfloat16* Wbl = jb.Wl + blockIdx.y * 128;
    uint32_t smb = smaddr(sm);

    mg_issue(smb, 0, tid, Abh, Abl, Wbh, Wbl, 0);
    mg_issue(smb, 1, tid, Abh, Abl, Wbh, Wbl, 1);

    float acc[2][4][4] = {};
    for (int kt = 0; kt < 16; kt++) {
        int buf = kt & 1;
        if (kt < 15) asm volatile("cp.async.wait_group 1;\n");
        else         asm volatile("cp.async.wait_group 0;\n");
        __syncthreads();
        mg_compute(smb, buf, tid, acc);
        if (kt < 14) {
            __syncthreads();
            mg_issue(smb, buf, tid, Abh, Abl, Wbh, Wbl, kt+2);
        }
    }

    int l = tid & 31, w = tid >> 5, wm = w & 1, wn = w >> 1;
    int g = l >> 2, t2 = (l & 3) * 2;
    int rowb = blockIdx.x*64 + wm*32;
    int colb = blockIdx.y*128 + wn*32;
#pragma unroll
    for (int fm = 0; fm < 2; fm++) {
#pragma unroll
        for (int fn = 0; fn < 4; fn++) {
            int col = colb + fn*8 + t2;
            float bx0 = jb.bias[col], bx1 = jb.bias[col+1];
            float o0 = acc[fm][fn][0] + bx0, o1 = acc[fm][fn][1] + bx1;
            float o2 = acc[fm][fn][2] + bx0, o3 = acc[fm][fn][3] + bx1;
            if (GELU) {
                o0 = 0.5f*o0*(1.0f + erff(o0*0.70710678118654752f));
                o1 = 0.5f*o1*(1.0f + erff(o1*0.70710678118654752f));
                o2 = 0.5f*o2*(1.0f + erff(o2*0.70710678118654752f));
                o3 = 0.5f*o3*(1.0f + erff(o3*0.70710678118654752f));
            }
            int r0 = rowb + fm*16 + g;
            if (jb.Cf) {
                float2 p0 = {o0, o1}, p1 = {o2, o3};
                *(float2*)(jb.Cf + (size_t)r0*512 + col)     = p0;
                *(float2*)(jb.Cf + (size_t)(r0+8)*512 + col) = p1;
            }
            if (jb.Ch) {
                cvst(o0, o1, jb.Ch + (size_t)r0*512 + col,     jb.Cl + (size_t)r0*512 + col);
                cvst(o2, o3, jb.Ch + (size_t)(r0+8)*512 + col, jb.Cl + (size_t)(r0+8)*512 + col);
            }
        }
    }
}

// ---------------- fused scores + softmax + S@V ------------------------------
#define FQH 0
#define FQL 4608
#define FKH 9216
#define FKL 46080
#define FVH 0
#define FVL 4608
#define FSH 9216
#define FSL 42496
#define FS_SMEM 165888

__global__ __launch_bounds__(512)
void fscores(const __nv_bfloat16* __restrict__ qh, const __nv_bfloat16* __restrict__ ql,
             const __nv_bfloat16* __restrict__ kh, const __nv_bfloat16* __restrict__ kl,
             const __nv_bfloat16* __restrict__ vh, const __nv_bfloat16* __restrict__ vl,
             float* __restrict__ out,
             __nv_bfloat16* __restrict__ t1h, __nv_bfloat16* __restrict__ t1l) {
    extern __shared__ __nv_bfloat16 sm[];
    __shared__ float red[64][8];
    int tid = threadIdx.x;
    int bh = blockIdx.y, b = bh >> 3, hhd = bh & 7;
    int l0 = blockIdx.x * 64;

    {
        int r = tid >> 3, c = (tid & 7) * 8;
        size_t qoff = ((size_t)(b*512 + l0 + r))*512 + hhd*64 + c;
        int qi = r*72 + c;
        *(uint4*)&sm[FQH + qi] = *(const uint4*)(qh + qoff);
        *(uint4*)&sm[FQL + qi] = *(const uint4*)(ql + qoff);
#pragma unroll
        for (int i = 0; i < 8; i++) {
            int kr = r + i*64;
            size_t koff = ((size_t)(b*512 + kr))*512 + hhd*64 + c;
            int ki = kr*72 + c;
            *(uint4*)&sm[FKH + ki] = *(const uint4*)(kh + koff);
            *(uint4*)&sm[FKL + ki] = *(const uint4*)(kl + koff);
        }
    }
    __syncthreads();

    uint32_t smb = smaddr(sm);
    int l = tid & 31, w = tid >> 5;
    int wn = w & 7, wm = w >> 3;
    int lr = l & 15, lc8 = (l >> 4) << 3;
    float acc[2][8][4] = {};
#pragma unroll
    for (int ks = 0; ks < 64; ks += 16) {
        uint32_t ah[2][4], al[2][4];
#pragma unroll
        for (int fm = 0; fm < 2; fm++) {
            uint32_t aoff = (uint32_t)((wm*32 + fm*16 + lr)*72 + ks + lc8) * 2;
            ldsm4(smb + FQH*2 + aoff, ah[fm][0], ah[fm][1], ah[fm][2], ah[fm][3]);
            ldsm4(smb + FQL*2 + aoff, al[fm][0], al[fm][1], al[fm][2], al[fm][3]);
        }
#pragma unroll
        for (int fnp = 0; fnp < 4; fnp++) {
            uint32_t boff = (uint32_t)((wn*64 + fnp*16 + lr)*72 + ks + lc8) * 2;
            uint32_t khr[4], klr[4];
            ldsm4(smb + FKH*2 + boff, khr[0], khr[1], khr[2], khr[3]);
            ldsm4(smb + FKL*2 + boff, klr[0], klr[1], klr[2], klr[3]);
#pragma unroll
            for (int fm = 0; fm < 2; fm++) {
                mmabf(acc[fm][fnp*2],   ah[fm], khr[0], khr[2]);
                mmabf(acc[fm][fnp*2],   ah[fm], klr[0], klr[2]);
                mmabf(acc[fm][fnp*2],   al[fm], khr[0], khr[2]);
                mmabf(acc[fm][fnp*2+1], ah[fm], khr[1], khr[3]);
                mmabf(acc[fm][fnp*2+1], ah[fm], klr[1], klr[3]);
                mmabf(acc[fm][fnp*2+1], al[fm], khr[1], khr[3]);
            }
        }
    }

#pragma unroll
    for (int fm = 0; fm < 2; fm++)
#pragma unroll
        for (int fn = 0; fn < 8; fn++)
#pragma unroll
            for (int e = 0; e < 4; e++) acc[fm][fn][e] *= 0.125f;

    int g = l >> 2, t2 = (l & 3) * 2;
    float tmax[2][2] = {{-1e30f,-1e30f},{-1e30f,-1e30f}};
#pragma unroll
    for (int fm = 0; fm < 2; fm++)
#pragma unroll
        for (int fn = 0; fn < 8; fn++) {
            tmax[fm][0] = fmaxf(tmax[fm][0], fmaxf(acc[fm][fn][0], acc[fm][fn][1]));
            tmax[fm][1] = fmaxf(tmax[fm][1], fmaxf(acc[fm][fn][2], acc[fm][fn][3]));
        }
#pragma unroll
    for (int o = 1; o <= 2; o <<= 1) {
#pragma unroll
        for (int fm = 0; fm < 2; fm++) {
            tmax[fm][0] = fmaxf(tmax[fm][0], __shfl_xor_sync(0xffffffff, tmax[fm][0], o));
            tmax[fm][1] = fmaxf(tmax[fm][1], __shfl_xor_sync(0xffffffff, tmax[fm][1], o));
        }
    }
    if ((l & 3) == 0) {
#pragma unroll
        for (int fm = 0; fm < 2; fm++) {
            red[wm*32 + fm*16 + g][wn]     = tmax[fm][0];
            red[wm*32 + fm*16 + g + 8][wn] = tmax[fm][1];
        }
    }
    __syncthreads();
    float rmax[2][2];
#pragma unroll
    for (int fm = 0; fm < 2; fm++)
#pragma unroll
        for (int hf = 0; hf < 2; hf++) {
            int r = wm*32 + fm*16 + g + hf*8;
            float m = red[r][0];
#pragma unroll
            for (int ww = 1; ww < 8; ww++) m = fmaxf(m, red[r][ww]);
            rmax[fm][hf] = m;
        }
    __syncthreads();

    float tsum[2][2] = {};
#pragma unroll
    for (int fm = 0; fm < 2; fm++)
#pragma unroll
        for (int fn = 0; fn < 8; fn++) {
            acc[fm][fn][0] = __expf(acc[fm][fn][0] - rmax[fm][0]);
            acc[fm][fn][1] = __expf(acc[fm][fn][1] - rmax[fm][0]);
            acc[fm][fn][2] = __expf(acc[fm][fn][2] - rmax[fm][1]);
            acc[fm][fn][3] = __expf(acc[fm][fn][3] - rmax[fm][1]);
            tsum[fm][0] += acc[fm][fn][0] + acc[fm][fn][1];
            tsum[fm][1] += acc[fm][fn][2] + acc[fm][fn][3];
        }
#pragma unroll
    for (int o = 1; o <= 2; o <<= 1) {
#pragma unroll
        for (int fm = 0; fm < 2; fm++) {
            tsum[fm][0] += __shfl_xor_sync(0xffffffff, tsum[fm][0], o);
            tsum[fm][1] += __shfl_xor_sync(0xffffffff, tsum[fm][1], o);
        }
    }
    if ((l & 3) == 0) {
#pragma unroll
        for (int fm = 0; fm < 2; fm++) {
            red[wm*32 + fm*16 + g][wn]     = tsum[fm][0];
            red[wm*32 + fm*16 + g + 8][wn] = tsum[fm][1];
        }
    }
    __syncthreads();
    float rinv[2][2];
#pragma unroll
    for (int fm = 0; fm < 2; fm++)
#pragma unroll
        for (int hf = 0; hf < 2; hf++) {
            int r = wm*32 + fm*16 + g + hf*8;
            float s = red[r][0];
#pragma unroll
            for (int ww = 1; ww < 8; ww++) s += red[r][ww];
            rinv[fm][hf] = 1.0f / s;
        }

    float* ob = out + ((size_t)bh*512 + l0)*512;
#pragma unroll
    for (int fm = 0; fm < 2; fm++)
#pragma unroll
        for (int fn = 0; fn < 8; fn++) {
            int row0 = wm*32 + fm*16 + g;
            int col = wn*64 + fn*8 + t2;
            float s0 = acc[fm][fn][0]*rinv[fm][0], s1 = acc[fm][fn][1]*rinv[fm][0];
            float s2 = acc[fm][fn][2]*rinv[fm][1], s3 = acc[fm][fn][3]*rinv[fm][1];
            float2 p0 = {s0, s1}, p1 = {s2, s3};
            *(float2*)(ob + (size_t)row0*512 + col)     = p0;
            *(float2*)(ob + (size_t)(row0+8)*512 + col) = p1;
            cvst(s0, s1, &sm[FSH + row0*520 + col],     &sm[FSL + row0*520 + col]);
            cvst(s2, s3, &sm[FSH + (row0+8)*520 + col], &sm[FSL + (row0+8)*520 + col]);
        }
    __syncthreads();

    float acc2[2][4] = {};
    for (int kc = 0; kc < 8; kc++) {
        {
            int r = tid >> 3, c = (tid & 7) * 8;
            size_t voff = ((size_t)(b*512 + kc*64 + r))*512 + hhd*64 + c;
            *(uint4*)&sm[FVH + r*72 + c] = *(const uint4*)(vh + voff);
            *(uint4*)&sm[FVL + r*72 + c] = *(const uint4*)(vl + voff);
        }
        __syncthreads();
#pragma unroll
        for (int ks = 0; ks < 64; ks += 16) {
            uint32_t sa[2][4], sl2[2][4];
#pragma unroll
            for (int fm = 0; fm < 2; fm++) {
                uint32_t aoff = (uint32_t)((wm*32 + fm*16 + lr)*520 + kc*64 + ks + lc8) * 2;
                ldsm4(smb + FSH*2 + aoff, sa[fm][0], sa[fm][1], sa[fm][2], sa[fm][3]);
                ldsm4(smb + FSL*2 + aoff, sl2[fm][0], sl2[fm][1], sl2[fm][2], sl2[fm][3]);
            }
            uint32_t boff = (uint32_t)((ks + lr)*72 + wn*8) * 2;
            uint32_t bh2[2], bl2[2];
            ldsm2t(smb + FVH*2 + boff, bh2[0], bh2[1]);
            ldsm2t(smb + FVL*2 + boff, bl2[0], bl2[1]);
#pragma unroll
            for (int fm = 0; fm < 2; fm++) {
                mmabf(acc2[fm], sa[fm],  bh2[0], bh2[1]);
                mmabf(acc2[fm], sa[fm],  bl2[0], bl2[1]);
                mmabf(acc2[fm], sl2[fm], bh2[0], bh2[1]);
            }
        }
        if (kc < 7) __syncthreads();
    }

#pragma unroll
    for (int fm = 0; fm < 2; fm++) {
        int row0 = wm*32 + fm*16 + g;
        int col = wn*8 + t2;
        size_t p0 = ((size_t)(b*512 + l0 + row0))*512 + hhd*64 + col;
        size_t p1 = ((size_t)(b*512 + l0 + row0 + 8))*512 + hhd*64 + col;
        cvst(acc2[fm][0], acc2[fm][1], t1h + p0, t1l + p0);
        cvst(acc2[fm][2], acc2[fm][3], t1h + p1, t1l + p1);
    }
}

// ---------------- sigma projection v4: warp/row, L1-resident Ws -------------
__global__ __launch_bounds__(128)
void sig4_kernel(const float* __restrict__ h, const float* __restrict__ Ws,
                 const float* __restrict__ bs, float* __restrict__ sig) {
    int warp = threadIdx.x >> 5, lane = threadIdx.x & 31;
    int row = blockIdx.x*4 + warp;
    const float* hr = h + (size_t)row*512;
    float s[8] = {};
#pragma unroll
    for (int i = 0; i < 16; i++) {
        int k = i*32 + lane;
        float hv = hr[k];
        float4 wa = *(const float4*)(Ws + k*8);
        float4 wb = *(const float4*)(Ws + k*8 + 4);
        s[0] += hv*wa.x; s[1] += hv*wa.y; s[2] += hv*wa.z; s[3] += hv*wa.w;
        s[4] += hv*wb.x; s[5] += hv*wb.y; s[6] += hv*wb.z; s[7] += hv*wb.w;
    }
#pragma unroll
    for (int off = 16; off > 0; off >>= 1)
#pragma unroll
        for (int o = 0; o < 8; o++) s[o] += __shfl_xor_sync(0xffffffff, s[o], off);
    if (lane < 8) sig[row*8 + lane] = s[lane] + bs[lane];
}

// ---------------- prior + sigma (float4 writes) ------------------------------
__global__ __launch_bounds__(128)
void prior_kernel(const float* __restrict__ sig,
                  float* __restrict__ prior, float* __restrict__ sigma) {
    int idx = blockIdx.x;
    int l = idx & (WIN-1);
    int bh = idx >> 9;
    int b = bh >> 3, hh = bh & 7;
    float sv = sig[((size_t)b*WIN + l)*NH + hh];
    float sgm = 1.0f/(1.0f + __expf(-5.0f*sv)) + 1e-5f;
    float sg  = __expf(sgm * 1.0986122886681098f) - 1.0f;
    float inv = 0.3989422804014327f / sg;
    float cc  = -1.0f/(2.0f*sg*sg);
    size_t base = ((size_t)bh*WIN + l)*WIN;
    int s0 = threadIdx.x * 4;
    float d0 = (float)(l - s0), d1 = d0 - 1.0f, d2 = d0 - 2.0f, d3 = d0 - 3.0f;
    float4 pr;
    pr.x = inv*__expf(cc*d0*d0); pr.y = inv*__expf(cc*d1*d1);
    pr.z = inv*__expf(cc*d2*d2); pr.w = inv*__expf(cc*d3*d3);
    *(float4*)(prior + base + s0) = pr;
    float4 sgv = {sg, sg, sg, sg};
    *(float4*)(sigma + base + s0) = sgv;
}

// ---------------- LayerNorm -------------------------------------------------
__global__ void ln_kernel(const float* __restrict__ x, const float* __restrict__ res,
                          const float* __restrict__ g, const float* __restrict__ bb,
                          float* __restrict__ outf,
                          __nv_bfloat16* __restrict__ outh, __nv_bfloat16* __restrict__ outl) {
    size_t row = blockIdx.x;
    int tid = threadIdx.x;
    const float* xr = x + row*DM;
    float v0 = xr[tid], v1 = xr[tid+256];
    if (res) { const float* rr = res + row*DM; v0 += rr[tid]; v1 += rr[tid+256]; }
    __shared__ float red[256];
    red[tid] = v0 + v1;
    __syncthreads();
    for (int s = 128; s > 0; s >>= 1) { if (tid < s) red[tid] += red[tid+s]; __syncthreads(); }
    float mu = red[0] * (1.0f/DM);
    __syncthreads();
    float d0 = v0 - mu, d1 = v1 - mu;
    red[tid] = d0*d0 + d1*d1;
    __syncthreads();
    for (int s = 128; s > 0; s >>= 1) { if (tid < s) red[tid] += red[tid+s]; __syncthreads(); }
    float r = rsqrtf(red[0]*(1.0f/DM) + 1e-3f);
    float y0 = d0*r*g[tid]     + bb[tid];
    float y1 = d1*r*g[tid+256] + bb[tid+256];
    size_t i0 = row*DM + tid, i1 = i0 + 256;
    outf[i0] = y0;
    outf[i1] = y1;
    if (outh) {
        cvst1(y0, outh + i0, outl + i0);
        cvst1(y1, outh + i1, outl + i1);
    }
}

// ---------------- final projection ------------------------------------------
__global__ void proj_kernel(const float* __restrict__ hf, const float* __restrict__ Wp,
                            const float* __restrict__ bp, float* __restrict__ out) {
    int row = blockIdx.x;
    int warp = threadIdx.x >> 5, lane = threadIdx.x & 31;
    const float* hr = hf + (size_t)row*DM;
    for (int c = warp; c < COUT; c += 8) {
        float sum = 0.f;
        for (int k2 = lane; k2 < DM; k2 += 32) sum += hr[k2] * Wp[(size_t)k2*COUT + c];
#pragma unroll
        for (int o = 16; o > 0; o >>= 1) sum += __shfl_xor_sync(0xffffffff, sum, o);
        if (lane == 0) out[(size_t)row*COUT + c] = sum + bp[c];
    }
}

// ---------------- host orchestration ----------------------------------------
extern "C" void kernel_launch(void* const* d_in, const int* in_sizes, int n_in,
                              void* d_out, int out_size) {
    const float* x    = (const float*)d_in[0];
    const float* ck   = (const float*)d_in[1];
    const float* Wq   = (const float*)d_in[2];
    const float* bq   = (const float*)d_in[3];
    const float* Wk   = (const float*)d_in[4];
    const float* bk   = (const float*)d_in[5];
    const float* Wv   = (const float*)d_in[6];
    const float* bv   = (const float*)d_in[7];
    const float* Ws   = (const float*)d_in[8];
    const float* bs   = (const float*)d_in[9];
    const float* Wo   = (const float*)d_in[10];
    const float* bo   = (const float*)d_in[11];
    const float* W1   = (const float*)d_in[12];
    const float* b1   = (const float*)d_in[13];
    const float* W2   = (const float*)d_in[14];
    const float* b2   = (const float*)d_in[15];
    const float* ln1g = (const float*)d_in[16];
    const float* ln1b = (const float*)d_in[17];
    const float* ln2g = (const float*)d_in[18];
    const float* ln2b = (const float*)d_in[19];
    const float* lnfg = (const float*)d_in[20];
    const float* lnfb = (const float*)d_in[21];
    const float* Wp   = (const float*)d_in[22];
    const float* bp   = (const float*)d_in[23];
    float* out = (float*)d_out;

    float *h, *t1, *t2, *sg;
    __nv_bfloat16 *hh, *hl, *qh, *ql, *kh, *kl, *vh, *vl, *t1h, *t1l, *wh, *wl;
    cudaGetSymbolAddress((void**)&h,   g_h);
    cudaGetSymbolAddress((void**)&t1,  g_t1);
    cudaGetSymbolAddress((void**)&t2,  g_t2);
    cudaGetSymbolAddress((void**)&sg,  g_sig);
    cudaGetSymbolAddress((void**)&hh,  g_hh);
    cudaGetSymbolAddress((void**)&hl,  g_hl);
    cudaGetSymbolAddress((void**)&qh,  g_qh);
    cudaGetSymbolAddress((void**)&ql,  g_ql);
    cudaGetSymbolAddress((void**)&kh,  g_kh);
    cudaGetSymbolAddress((void**)&kl,  g_kl);
    cudaGetSymbolAddress((void**)&vh,  g_vh);
    cudaGetSymbolAddress((void**)&vl,  g_vl);
    cudaGetSymbolAddress((void**)&t1h, g_t1h);
    cudaGetSymbolAddress((void**)&t1l, g_t1l);
    cudaGetSymbolAddress((void**)&wh,  g_wh);
    cudaGetSymbolAddress((void**)&wl,  g_wl);

    cudaFuncSetAttribute(mgemm<false>, cudaFuncAttributeMaxDynamicSharedMemorySize, 55296);
    cudaFuncSetAttribute(mgemm<true>,  cudaFuncAttributeMaxDynamicSharedMemorySize, 55296);
    cudaFuncSetAttribute(fscores,      cudaFuncAttributeMaxDynamicSharedMemorySize, FS_SMEM);

    wconv_kernel<<<4608, 256>>>(Wq, Wk, Wv, Wo, W1, W2, wh, wl);
    embed_kernel<<<ROWS, DM>>>(x, ck, h, hh, hl);

    dim3 g1(64, 4, 1);
    dim3 g3(64, 4, 3);
    for (int i = 0; i < NL; i++) {
        size_t wbase = (size_t)i*6*262144;
        GemmJob jq = { wh + wbase + 0*262144, wl + wbase + 0*262144, bq + i*DM, nullptr, qh, ql };
        GemmJob jk = { wh + wbase + 1*262144, wl + wbase + 1*262144, bk + i*DM, nullptr, kh, kl };
        GemmJob jv = { wh + wbase + 2*262144, wl + wbase + 2*262144, bv + i*DM, nullptr, vh, vl };
        GemmJob jo = { wh + wbase + 3*262144, wl + wbase + 3*262144, bo + i*DM, t2, nullptr, nullptr };
        GemmJob jf1 = { wh + wbase + 4*262144, wl + wbase + 4*262144, b1 + i*DM, nullptr, t1h, t1l };
        GemmJob jf2 = { wh + wbase + 5*262144, wl + wbase + 5*262144, b2 + i*DM, t2, nullptr, nullptr };

        mgemm<false><<<g3, 256, 55296>>>(hh, hl, jq, jk, jv);
        sig4_kernel<<<ROWS/4, 128>>>(h, Ws + (size_t)i*DM*NH, bs + i*NH, sg);

        float* ser = out + SERIES_OFF + (size_t)i*LAYER_ELEMS;
        fscores<<<dim3(8, 64), 512, FS_SMEM>>>(qh, ql, kh, kl, vh, vl, ser, t1h, t1l);
        prior_kernel<<<BATCH*NH*WIN, 128>>>(sg,
                out + PRIOR_OFF + (size_t)i*LAYER_ELEMS,
                out + SIGMA_OFF + (size_t)i*LAYER_ELEMS);

        mgemm<false><<<g1, 256, 55296>>>(t1h, t1l, jo, jo, jo);
        ln_kernel<<<ROWS, 256>>>(h, t2, ln1g + i*DM, ln1b + i*DM, h, hh, hl);

        mgemm<true ><<<g1, 256, 55296>>>(hh, hl, jf1, jf1, jf1);
        mgemm<false><<<g1, 256, 55296>>>(t1h, t1l, jf2, jf2, jf2);
        ln_kernel<<<ROWS, 256>>>(h, t2, ln2g + i*DM, ln2b + i*DM, h, hh, hl);
    }

    ln_kernel<<<ROWS, 256>>>(h, nullptr, lnfg, lnfb, t1, nullptr, nullptr);
    proj_kernel<<<ROWS, 256>>>(t1, Wp, bp, out);
}